// round 11
// baseline (speedup 1.0000x reference)
#include <cuda_runtime.h>
#include <cuda_bf16.h>
#include <cstdint>

#define NNODES 100000
#define NEDGES 1600000
#define FIN 128
#define FHID 128
#define FOUT 64

// ---------------- scratch (static device globals; no allocation) ----------------
__device__ uint32_t g_XSh[(size_t)3 * NNODES * 64];    // XS bf16-hi plane (k-pairs packed)
__device__ uint32_t g_XSl[(size_t)3 * NNODES * 64];    // XS bf16-lo plane
__device__ float    g_H2 [(size_t)3 * NNODES * FOUT];  // layer-2 transformed features
__device__ int      g_cnt     [3 * NNODES];            // cursor (holds rowstart after scan)
__device__ int      g_outcnt  [3 * NNODES];
__device__ int      g_rowstart[3 * (NNODES + 1)];
__device__ int      g_esrc    [3 * NEDGES];
__device__ float    g_nsrc    [3 * NNODES];
__device__ float    g_ndst    [3 * NNODES];
__device__ uint32_t g_W1h[64 * 128], g_W1l[64 * 128];  // W1 packed bf16 hi/lo (k-pairs)
__device__ uint32_t g_W2h[64 * 64],  g_W2l[64 * 64];   // W2 packed bf16 hi/lo

struct F3 { const float* p[3]; };
struct I3 { const int*   p[3]; };

// ---------------- bf16 split helpers ----------------
__device__ __forceinline__ void split2(float f0, float f1, uint32_t& uh, uint32_t& ul) {
    __nv_bfloat16 h0 = __float2bfloat16_rn(f0), h1 = __float2bfloat16_rn(f1);
    float r0 = f0 - __bfloat162float(h0);
    float r1 = f1 - __bfloat162float(h1);
    __nv_bfloat16 l0 = __float2bfloat16_rn(r0), l1 = __float2bfloat16_rn(r1);
    uh = ((uint32_t)(*(uint16_t*)&h1) << 16) | (uint32_t)(*(uint16_t*)&h0);
    ul = ((uint32_t)(*(uint16_t*)&l1) << 16) | (uint32_t)(*(uint16_t*)&l0);
}

__device__ __forceinline__ void mma_bf16(float* d, const uint32_t* a, const uint32_t* b) {
    asm volatile(
        "mma.sync.aligned.m16n8k16.row.col.f32.bf16.bf16.f32 "
        "{%0,%1,%2,%3},{%4,%5,%6,%7},{%8,%9},{%0,%1,%2,%3};"
        : "+f"(d[0]), "+f"(d[1]), "+f"(d[2]), "+f"(d[3])
        : "r"(a[0]), "r"(a[1]), "r"(a[2]), "r"(a[3]), "r"(b[0]), "r"(b[1]));
}

// ---------------- launch 0: zero histograms + pack weights ----------------
__global__ void zero_pack(int* cnt, int* outcnt,
                          const float* __restrict__ W1, const float* __restrict__ W2,
                          uint32_t* w1h, uint32_t* w1l, uint32_t* w2h, uint32_t* w2l) {
    int i = blockIdx.x * blockDim.x + threadIdx.x;
    if (i < 3 * NNODES) { cnt[i] = 0; outcnt[i] = 0; }
    if (i < 64 * 128) {
        int kp = i >> 7, c = i & 127;
        split2(W1[(2 * kp) * FHID + c], W1[(2 * kp + 1) * FHID + c], w1h[i], w1l[i]);
    }
    if (i < 64 * 64) {
        int kp = i >> 6, c = i & 63;
        split2(W2[(2 * kp) * FOUT + c], W2[(2 * kp + 1) * FOUT + c], w2h[i], w2l[i]);
    }
}

// ---------------- launch 1: degree histograms (4 edges/thread, int4 loads) ----------------
__global__ __launch_bounds__(256)
void hist_all(I3 srcs, I3 dsts, int* cnt, int* outcnt) {
    int g = blockIdx.y;
    int i = blockIdx.x * blockDim.x + threadIdx.x;
    if (i < NEDGES / 4) {
        int4 d4 = __ldg((const int4*)dsts.p[g] + i);
        int4 s4 = __ldg((const int4*)srcs.p[g] + i);
        int* c = cnt + g * NNODES;
        int* o = outcnt + g * NNODES;
        atomicAdd(c + d4.x, 1);
        atomicAdd(c + d4.y, 1);
        atomicAdd(c + d4.z, 1);
        atomicAdd(c + d4.w, 1);
        atomicAdd(o + s4.x, 1);
        atomicAdd(o + s4.y, 1);
        atomicAdd(o + s4.z, 1);
        atomicAdd(o + s4.w, 1);
    }
}

// ---------------- launch 2: scan + norms (one block per graph) ----------------
__global__ void scan_norms(int* __restrict__ cntAll,
                           const int* __restrict__ outcntAll,
                           int* __restrict__ rowstartAll,
                           float* __restrict__ nsrcAll,
                           float* __restrict__ ndstAll) {
    __shared__ int part[1024];
    const int gb = blockIdx.x;
    int* cnt          = cntAll      + gb * NNODES;
    const int* outcnt = outcntAll   + gb * NNODES;
    int* rowstart     = rowstartAll + gb * (NNODES + 1);
    float* nsrc       = nsrcAll + gb * NNODES;
    float* ndst       = ndstAll + gb * NNODES;
    const int t = threadIdx.x;
    const int chunk = (NNODES + 1023) / 1024;
    const int lo = t * chunk;
    const int hi = min(lo + chunk, NNODES);
    int s = 0;
    for (int i = lo; i < hi; i++) {
        int c = cnt[i];
        s += c;
        ndst[i] = rsqrtf(fmaxf((float)c, 1.f));
        nsrc[i] = rsqrtf(fmaxf((float)outcnt[i], 1.f));
    }
    part[t] = s;
    __syncthreads();
    for (int off = 1; off < 1024; off <<= 1) {
        int v = (t >= off) ? part[t - off] : 0;
        __syncthreads();
        part[t] += v;
        __syncthreads();
    }
    int run = part[t] - s;
    for (int i = lo; i < hi; i++) {
        int c = cnt[i];
        rowstart[i] = run;
        cnt[i] = run;          // cursor = row start (absolute)
        run += c;
    }
    if (t == 1023) rowstart[NNODES] = part[1023];
}

// ---------------- launch 3: CSR fill (4 edges/thread) ----------------
__global__ __launch_bounds__(256)
void fill_all(I3 srcs, I3 dsts, int* cnt, int* __restrict__ esrcAll) {
    int g = blockIdx.y;
    int i = blockIdx.x * blockDim.x + threadIdx.x;
    if (i < NEDGES / 4) {
        int4 d4 = __ldg((const int4*)dsts.p[g] + i);
        int4 s4 = __ldg((const int4*)srcs.p[g] + i);
        int* c = cnt + g * NNODES;
        int* esrc = esrcAll + (size_t)g * NEDGES;
        int p0 = atomicAdd(c + d4.x, 1);
        int p1 = atomicAdd(c + d4.y, 1);
        int p2 = atomicAdd(c + d4.z, 1);
        int p3 = atomicAdd(c + d4.w, 1);
        esrc[p0] = s4.x;
        esrc[p1] = s4.y;
        esrc[p2] = s4.z;
        esrc[p3] = s4.w;
    }
}

// ---------------- launches 4-6: scaled gather SpMM, ONE GRAPH per launch ----------------
// XS[i,:] = sum_{e in row i} nsrc[s]*feat[s,:]  -> packed bf16 hi/lo planes
__global__ __launch_bounds__(256)
void spmm_scaled(const float* __restrict__ X,
                 const int* __restrict__ rowstart,
                 const int* __restrict__ esrc,
                 uint32_t* __restrict__ XSh,
                 uint32_t* __restrict__ XSl,
                 const float* __restrict__ nsrc)
{
    int gt = blockIdx.x * blockDim.x + threadIdx.x;
    int row = gt >> 5;        // warp id == row
    int lc  = gt & 31;        // float4 lane (32 x 4 = 128 cols)
    if (row >= NNODES) return;

    int beg = rowstart[row];
    int end = rowstart[row + 1];
    float4 acc = make_float4(0.f, 0.f, 0.f, 0.f);
    int e = beg;
    for (; e + 4 <= end; e += 4) {
        int s0 = __ldg(esrc + e + 0);
        int s1 = __ldg(esrc + e + 1);
        int s2 = __ldg(esrc + e + 2);
        int s3 = __ldg(esrc + e + 3);
        float w0 = __ldg(nsrc + s0), w1 = __ldg(nsrc + s1);
        float w2 = __ldg(nsrc + s2), w3 = __ldg(nsrc + s3);
        float4 v0 = __ldg((const float4*)(X + (size_t)s0 * FIN) + lc);
        float4 v1 = __ldg((const float4*)(X + (size_t)s1 * FIN) + lc);
        float4 v2 = __ldg((const float4*)(X + (size_t)s2 * FIN) + lc);
        float4 v3 = __ldg((const float4*)(X + (size_t)s3 * FIN) + lc);
        acc.x = fmaf(w0, v0.x, fmaf(w1, v1.x, fmaf(w2, v2.x, fmaf(w3, v3.x, acc.x))));
        acc.y = fmaf(w0, v0.y, fmaf(w1, v1.y, fmaf(w2, v2.y, fmaf(w3, v3.y, acc.y))));
        acc.z = fmaf(w0, v0.z, fmaf(w1, v1.z, fmaf(w2, v2.z, fmaf(w3, v3.z, acc.z))));
        acc.w = fmaf(w0, v0.w, fmaf(w1, v1.w, fmaf(w2, v2.w, fmaf(w3, v3.w, acc.w))));
    }
    for (; e < end; e++) {
        int s = __ldg(esrc + e);
        float ws = __ldg(nsrc + s);
        float4 v = __ldg((const float4*)(X + (size_t)s * FIN) + lc);
        acc.x = fmaf(ws, v.x, acc.x);
        acc.y = fmaf(ws, v.y, acc.y);
        acc.z = fmaf(ws, v.z, acc.z);
        acc.w = fmaf(ws, v.w, acc.w);
    }
    uint32_t h0, l0, h1, l1;
    split2(acc.x, acc.y, h0, l0);
    split2(acc.z, acc.w, h1, l1);
    *((uint2*)(XSh + (size_t)row * 64) + lc) = make_uint2(h0, h1);
    *((uint2*)(XSl + (size_t)row * 64) + lc) = make_uint2(l0, l1);
}

// ---------------- fused dense chain (per graph) ----------------
// H2 = relu( (XS @ W1) * ndst + b1 ) @ W2 * nsrc
#define LDAp 12
#define LDB1 136
#define LDT  68
#define LDB2 72
#define OFF_AH 0
#define OFF_AL (OFF_AH + 128 * LDAp)
#define OFF_B1H (OFF_AL + 128 * LDAp)
#define OFF_B1L (OFF_B1H + 8 * LDB1)
#define OFF_TH (OFF_B1L + 8 * LDB1)
#define OFF_TL (OFF_TH + 128 * LDT)
#define OFF_B2H (OFF_TL + 128 * LDT)
#define OFF_B2L (OFF_B2H + 8 * LDB2)
#define OFF_BSH (OFF_B2L + 8 * LDB2)
#define SMEM_WORDS (OFF_BSH + 128)

__global__ __launch_bounds__(256)
void fused_gemm(const uint32_t* __restrict__ XSh,
                const uint32_t* __restrict__ XSl,
                const uint32_t* __restrict__ W1h, const uint32_t* __restrict__ W1l,
                const uint32_t* __restrict__ W2h, const uint32_t* __restrict__ W2l,
                const float* __restrict__ b1,
                float* __restrict__ H2,
                const float* __restrict__ nsrc,
                const float* __restrict__ ndst)
{
    extern __shared__ uint32_t sm[];
    uint32_t* Ahp = sm + OFF_AH;    // [128][LDAp]
    uint32_t* Alp = sm + OFF_AL;
    uint32_t* B1h = sm + OFF_B1H;   // [8][LDB1]
    uint32_t* B1l = sm + OFF_B1L;
    uint32_t* Th  = sm + OFF_TH;    // [128][LDT]
    uint32_t* Tl  = sm + OFF_TL;
    uint32_t* B2h = sm + OFF_B2H;   // [8][LDB2]
    uint32_t* B2l = sm + OFF_B2L;
    float*    bsh = (float*)(sm + OFF_BSH);

    const int tid  = threadIdx.x;
    const int warp = tid >> 5;
    const int lane = tid & 31;
    const int warp_m = warp & 3;
    const int warp_n = warp >> 2;
    const int m0w = warp_m * 32;
    const int g  = lane >> 2;
    const int tg = lane & 3;
    const int blockRow = blockIdx.x * 128;
    const int M = NNODES;

    if (tid < FHID) bsh[tid] = b1[tid];

    // ================= stage 1: T = XS @ W1 (3-term bf16) =================
    float acc1[2][8][4];
#pragma unroll
    for (int mi = 0; mi < 2; mi++)
#pragma unroll
        for (int ni = 0; ni < 8; ni++)
#pragma unroll
            for (int j = 0; j < 4; j++) acc1[mi][ni][j] = 0.f;

    const int n0w1 = warp_n * 64;
    const int arow = tid >> 1;          // 0..127
    const int aq   = (tid & 1) * 4;     // uint4 column within 8-wide chunk

    for (int kc = 0; kc < FIN; kc += 16) {
        __syncthreads();
        // A chunk: pre-packed planes, direct copy
        {
            int grow = blockRow + arow;
            uint4 vh = make_uint4(0u, 0u, 0u, 0u);
            uint4 vl = make_uint4(0u, 0u, 0u, 0u);
            if (grow < M) {
                vh = *(const uint4*)(XSh + (size_t)grow * 64 + kc / 2 + aq);
                vl = *(const uint4*)(XSl + (size_t)grow * 64 + kc / 2 + aq);
            }
            *(uint4*)&Ahp[arow * LDAp + aq] = vh;
            *(uint4*)&Alp[arow * LDAp + aq] = vl;
        }
        // B1 chunk (pre-packed)
        {
            int jp = tid >> 5;
            int c4 = (tid & 31) * 4;
            *(uint4*)&B1h[jp * LDB1 + c4] =
                *(const uint4*)(W1h + (size_t)(kc / 2 + jp) * FHID + c4);
            *(uint4*)&B1l[jp * LDB1 + c4] =
                *(const uint4*)(W1l + (size_t)(kc / 2 + jp) * FHID + c4);
        }
        __syncthreads();

        uint32_t ah[2][4], al[2][4];
#pragma unroll
        for (int mi = 0; mi < 2; mi++) {
            int r = m0w + mi * 16 + g;
            ah[mi][0] = Ahp[r * LDAp + tg];            al[mi][0] = Alp[r * LDAp + tg];
            ah[mi][1] = Ahp[(r + 8) * LDAp + tg];      al[mi][1] = Alp[(r + 8) * LDAp + tg];
            ah[mi][2] = Ahp[r * LDAp + tg + 4];        al[mi][2] = Alp[r * LDAp + tg + 4];
            ah[mi][3] = Ahp[(r + 8) * LDAp + tg + 4];  al[mi][3] = Alp[(r + 8) * LDAp + tg + 4];
        }
#pragma unroll
        for (int ni = 0; ni < 8; ni++) {
            int c = n0w1 + ni * 8 + g;
            uint32_t bh[2], bl[2];
            bh[0] = B1h[tg * LDB1 + c];        bl[0] = B1l[tg * LDB1 + c];
            bh[1] = B1h[(tg + 4) * LDB1 + c];  bl[1] = B1l[(tg + 4) * LDB1 + c];
#pragma unroll
            for (int mi = 0; mi < 2; mi++) {
                mma_bf16(acc1[mi][ni], al[mi], bh);
                mma_bf16(acc1[mi][ni], ah[mi], bl);
                mma_bf16(acc1[mi][ni], ah[mi], bh);
            }
        }
    }

    // ---- t = relu(T*ndst + b1), packed bf16 hi/lo into smem ----
    __syncthreads();
#pragma unroll
    for (int mi = 0; mi < 2; mi++) {
        int r0 = m0w + mi * 16 + g;
        int r1 = r0 + 8;
        int gr0 = blockRow + r0, gr1 = blockRow + r1;
        float nd0 = (gr0 < M) ? ndst[gr0] : 0.f;
        float nd1 = (gr1 < M) ? ndst[gr1] : 0.f;
#pragma unroll
        for (int ni = 0; ni < 8; ni++) {
            int col = n0w1 + ni * 8 + 2 * tg;
            int cp  = col >> 1;
            float t00 = fmaxf(fmaf(acc1[mi][ni][0], nd0, bsh[col]), 0.f);
            float t01 = fmaxf(fmaf(acc1[mi][ni][1], nd0, bsh[col + 1]), 0.f);
            float t10 = fmaxf(fmaf(acc1[mi][ni][2], nd1, bsh[col]), 0.f);
            float t11 = fmaxf(fmaf(acc1[mi][ni][3], nd1, bsh[col + 1]), 0.f);
            uint32_t h, l;
            split2(t00, t01, h, l);
            Th[r0 * LDT + cp] = h;  Tl[r0 * LDT + cp] = l;
            split2(t10, t11, h, l);
            Th[r1 * LDT + cp] = h;  Tl[r1 * LDT + cp] = l;
        }
    }

    // ================= stage 2: H2 = t @ W2 * nsrc =================
    float acc2[2][4][4];
#pragma unroll
    for (int mi = 0; mi < 2; mi++)
#pragma unroll
        for (int ni = 0; ni < 4; ni++)
#pragma unroll
            for (int j = 0; j < 4; j++) acc2[mi][ni][j] = 0.f;

    const int n0w2 = warp_n * 32;

    for (int ch = 0; ch < 8; ch++) {
        __syncthreads();
        if (tid < 128) {
            int jp = tid >> 4;
            int c4 = (tid & 15) * 4;
            *(uint4*)&B2h[jp * LDB2 + c4] =
                *(const uint4*)(W2h + (size_t)(ch * 8 + jp) * FOUT + c4);
        } else {
            int t2 = tid - 128;
            int jp = t2 >> 4;
            int c4 = (t2 & 15) * 4;
            *(uint4*)&B2l[jp * LDB2 + c4] =
                *(const uint4*)(W2l + (size_t)(ch * 8 + jp) * FOUT + c4);
        }
        __syncthreads();

        int cb = ch * 8;
        uint32_t ah[2][4], al[2][4];
#pragma unroll
        for (int mi = 0; mi < 2; mi++) {
            int r = m0w + mi * 16 + g;
            ah[mi][0] = Th[r * LDT + cb + tg];            al[mi][0] = Tl[r * LDT + cb + tg];
            ah[mi][1] = Th[(r + 8) * LDT + cb + tg];      al[mi][1] = Tl[(r + 8) * LDT + cb + tg];
            ah[mi][2] = Th[r * LDT + cb + tg + 4];        al[mi][2] = Tl[r * LDT + cb + tg + 4];
            ah[mi][3] = Th[(r + 8) * LDT + cb + tg + 4];  al[mi][3] = Tl[(r + 8) * LDT + cb + tg + 4];
        }
#pragma unroll
        for (int ni = 0; ni < 4; ni++) {
            int c = n0w2 + ni * 8 + g;
            uint32_t bh[2], bl[2];
            bh[0] = B2h[tg * LDB2 + c];        bl[0] = B2l[tg * LDB2 + c];
            bh[1] = B2h[(tg + 4) * LDB2 + c];  bl[1] = B2l[(tg + 4) * LDB2 + c];
#pragma unroll
            for (int mi = 0; mi < 2; mi++) {
                mma_bf16(acc2[mi][ni], al[mi], bh);
                mma_bf16(acc2[mi][ni], ah[mi], bl);
                mma_bf16(acc2[mi][ni], ah[mi], bh);
            }
        }
    }

    // ---- epilogue: H2 = acc2 * nsrc ----
#pragma unroll
    for (int mi = 0; mi < 2; mi++) {
        int gr0 = blockRow + m0w + mi * 16 + g;
        int gr1 = gr0 + 8;
        float s0 = (gr0 < M) ? nsrc[gr0] : 0.f;
        float s1 = (gr1 < M) ? nsrc[gr1] : 0.f;
#pragma unroll
        for (int ni = 0; ni < 4; ni++) {
            int col = n0w2 + ni * 8 + 2 * tg;
            if (gr0 < M)
                *(float2*)(H2 + (size_t)gr0 * FOUT + col) =
                    make_float2(acc2[mi][ni][0] * s0, acc2[mi][ni][1] * s0);
            if (gr1 < M)
                *(float2*)(H2 + (size_t)gr1 * FOUT + col) =
                    make_float2(acc2[mi][ni][2] * s1, acc2[mi][ni][3] * s1);
        }
    }
}

// ---------------- final gather SpMM (per graph; H2 is L2-hot from fused_gemm) ----------------
__global__ __launch_bounds__(256)
void spmm_out(const float* __restrict__ H,
              const int* __restrict__ rowstart,
              const int* __restrict__ esrc,
              float* __restrict__ out,
              const float* __restrict__ ndst,
              const float* __restrict__ bias)
{
    constexpr int C = FOUT, C4 = C / 4, RPW = 32 / C4;   // 16 lanes/row, 2 rows/warp
    int gt = blockIdx.x * blockDim.x + threadIdx.x;
    int w = gt >> 5;
    int lane = gt & 31;
    int sub = lane / C4;
    int lc  = lane % C4;
    int row = w * RPW + sub;
    if (row >= NNODES) return;

    int beg = rowstart[row];
    int end = rowstart[row + 1];
    float4 acc = make_float4(0.f, 0.f, 0.f, 0.f);
    int e = beg;
    for (; e + 4 <= end; e += 4) {
        int s0 = __ldg(esrc + e + 0);
        int s1 = __ldg(esrc + e + 1);
        int s2 = __ldg(esrc + e + 2);
        int s3 = __ldg(esrc + e + 3);
        float4 v0 = __ldg((const float4*)(H + (size_t)s0 * C) + lc);
        float4 v1 = __ldg((const float4*)(H + (size_t)s1 * C) + lc);
        float4 v2 = __ldg((const float4*)(H + (size_t)s2 * C) + lc);
        float4 v3 = __ldg((const float4*)(H + (size_t)s3 * C) + lc);
        acc.x += (v0.x + v1.x) + (v2.x + v3.x);
        acc.y += (v0.y + v1.y) + (v2.y + v3.y);
        acc.z += (v0.z + v1.z) + (v2.z + v3.z);
        acc.w += (v0.w + v1.w) + (v2.w + v3.w);
    }
    for (; e < end; e++) {
        int s = __ldg(esrc + e);
        float4 v = __ldg((const float4*)(H + (size_t)s * C) + lc);
        acc.x += v.x; acc.y += v.y; acc.z += v.z; acc.w += v.w;
    }
    float nd = ndst[row];
    float4 b = ((const float4*)bias)[lc];
    acc.x = fmaf(acc.x, nd, b.x);
    acc.y = fmaf(acc.y, nd, b.y);
    acc.z = fmaf(acc.z, nd, b.z);
    acc.w = fmaf(acc.w, nd, b.w);
    *((float4*)(out + (size_t)row * C) + lc) = acc;
}

// ---------------- launch ----------------
extern "C" void kernel_launch(void* const* d_in, const int* in_sizes, int n_in,
                              void* d_out, int out_size)
{
    float *H2, *nsrc, *ndst;
    int *cnt, *outcnt, *rowstart, *esrc;
    uint32_t *xsh, *xsl, *w1h, *w1l, *w2h, *w2l;
    cudaGetSymbolAddress((void**)&xsh,      g_XSh);
    cudaGetSymbolAddress((void**)&xsl,      g_XSl);
    cudaGetSymbolAddress((void**)&H2,       g_H2);
    cudaGetSymbolAddress((void**)&cnt,      g_cnt);
    cudaGetSymbolAddress((void**)&outcnt,   g_outcnt);
    cudaGetSymbolAddress((void**)&rowstart, g_rowstart);
    cudaGetSymbolAddress((void**)&esrc,     g_esrc);
    cudaGetSymbolAddress((void**)&nsrc,     g_nsrc);
    cudaGetSymbolAddress((void**)&ndst,     g_ndst);
    cudaGetSymbolAddress((void**)&w1h,      g_W1h);
    cudaGetSymbolAddress((void**)&w1l,      g_W1l);
    cudaGetSymbolAddress((void**)&w2h,      g_W2h);
    cudaGetSymbolAddress((void**)&w2l,      g_W2l);

    F3 feats = {{ (const float*)d_in[0], (const float*)d_in[3], (const float*)d_in[6] }};
    I3 srcs  = {{ (const int*)d_in[1],   (const int*)d_in[4],   (const int*)d_in[7] }};
    I3 dsts  = {{ (const int*)d_in[2],   (const int*)d_in[5],   (const int*)d_in[8] }};
    const float* W1 = (const float*)d_in[9];
    const float* b1 = (const float*)d_in[10];
    const float* W2 = (const float*)d_in[11];
    const float* b2 = (const float*)d_in[12];

    static const size_t SMEM_BYTES = SMEM_WORDS * sizeof(uint32_t);
    cudaFuncSetAttribute(fused_gemm, cudaFuncAttributeMaxDynamicSharedMemorySize,
                         (int)SMEM_BYTES);

    dim3 gE((NEDGES / 4 + 255) / 256, 3);        // 4 edges per thread
    const int gG  = (NNODES + 127) / 128;
    const int gS1 = (NNODES * 32 + 255) / 256;
    const int gS2 = (NNODES * 16 + 255) / 256;

    zero_pack <<<(3 * NNODES + 255) / 256, 256>>>(cnt, outcnt, W1, W2, w1h, w1l, w2h, w2l);
    hist_all  <<<gE, 256>>>(srcs, dsts, cnt, outcnt);
    scan_norms<<<3, 1024>>>(cnt, outcnt, rowstart, nsrc, ndst);
    fill_all  <<<gE, 256>>>(srcs, dsts, cnt, esrc);

    // XS = gather(nsrc * feat), one graph per launch (L2-resident features)
    for (int g = 0; g < 3; g++)
        spmm_scaled<<<gS1, 256>>>(feats.p[g],
                                  rowstart + g * (NNODES + 1),
                                  esrc + (size_t)g * NEDGES,
                                  xsh + (size_t)g * NNODES * 64,
                                  xsl + (size_t)g * NNODES * 64,
                                  nsrc + g * NNODES);

    // per-graph: dense chain then immediately its output gather (H2 stays L2-hot)
    for (int g = 0; g < 3; g++) {
        fused_gemm<<<gG, 256, SMEM_BYTES>>>(xsh + (size_t)g * NNODES * 64,
                                            xsl + (size_t)g * NNODES * 64,
                                            w1h, w1l, w2h, w2l, b1,
                                            H2 + (size_t)g * NNODES * FOUT,
                                            nsrc + g * NNODES,
                                            ndst + g * NNODES);
        spmm_out<<<gS2, 256>>>(H2 + (size_t)g * NNODES * FOUT,
                               rowstart + g * (NNODES + 1),
                               esrc + (size_t)g * NEDGES,
                               (float*)d_out + (size_t)g * NNODES * FOUT,
                               ndst + g * NNODES,
                               b2);
    }
}

// round 12
// speedup vs baseline: 1.0402x; 1.0402x over previous
#include <cuda_runtime.h>
#include <cuda_bf16.h>
#include <cuda_fp16.h>
#include <cstdint>

#define NNODES 100000
#define NEDGES 1600000
#define FIN 128
#define FHID 128
#define FOUT 64

// ---------------- scratch (static device globals; no allocation) ----------------
__device__ uint32_t g_XSh[(size_t)3 * NNODES * 64];    // XS bf16-hi plane (k-pairs packed)
__device__ uint32_t g_XSl[(size_t)3 * NNODES * 64];    // XS bf16-lo plane
__device__ __half   g_H2 [(size_t)3 * NNODES * FOUT];  // layer-2 transformed features (fp16)
__device__ int      g_cnt     [3 * NNODES];            // cursor (holds rowstart after scan)
__device__ int      g_outcnt  [3 * NNODES];
__device__ int      g_rowstart[3 * (NNODES + 1)];
__device__ int      g_esrc    [3 * NEDGES];
__device__ float    g_nsrc    [3 * NNODES];
__device__ float    g_ndst    [3 * NNODES];
__device__ uint32_t g_W1h[64 * 128], g_W1l[64 * 128];  // W1 packed bf16 hi/lo (k-pairs)
__device__ uint32_t g_W2h[64 * 64],  g_W2l[64 * 64];   // W2 packed bf16 hi/lo

struct F3 { const float* p[3]; };
struct I3 { const int*   p[3]; };

// ---------------- bf16 split helpers ----------------
__device__ __forceinline__ void split2(float f0, float f1, uint32_t& uh, uint32_t& ul) {
    __nv_bfloat16 h0 = __float2bfloat16_rn(f0), h1 = __float2bfloat16_rn(f1);
    float r0 = f0 - __bfloat162float(h0);
    float r1 = f1 - __bfloat162float(h1);
    __nv_bfloat16 l0 = __float2bfloat16_rn(r0), l1 = __float2bfloat16_rn(r1);
    uh = ((uint32_t)(*(uint16_t*)&h1) << 16) | (uint32_t)(*(uint16_t*)&h0);
    ul = ((uint32_t)(*(uint16_t*)&l1) << 16) | (uint32_t)(*(uint16_t*)&l0);
}

__device__ __forceinline__ void mma_bf16(float* d, const uint32_t* a, const uint32_t* b) {
    asm volatile(
        "mma.sync.aligned.m16n8k16.row.col.f32.bf16.bf16.f32 "
        "{%0,%1,%2,%3},{%4,%5,%6,%7},{%8,%9},{%0,%1,%2,%3};"
        : "+f"(d[0]), "+f"(d[1]), "+f"(d[2]), "+f"(d[3])
        : "r"(a[0]), "r"(a[1]), "r"(a[2]), "r"(a[3]), "r"(b[0]), "r"(b[1]));
}

// ---------------- launch 0: zero histograms + pack weights ----------------
__global__ void zero_pack(int* cnt, int* outcnt,
                          const float* __restrict__ W1, const float* __restrict__ W2,
                          uint32_t* w1h, uint32_t* w1l, uint32_t* w2h, uint32_t* w2l) {
    int i = blockIdx.x * blockDim.x + threadIdx.x;
    if (i < 3 * NNODES) { cnt[i] = 0; outcnt[i] = 0; }
    if (i < 64 * 128) {
        int kp = i >> 7, c = i & 127;
        split2(W1[(2 * kp) * FHID + c], W1[(2 * kp + 1) * FHID + c], w1h[i], w1l[i]);
    }
    if (i < 64 * 64) {
        int kp = i >> 6, c = i & 63;
        split2(W2[(2 * kp) * FOUT + c], W2[(2 * kp + 1) * FOUT + c], w2h[i], w2l[i]);
    }
}

// ---------------- launch 1: degree histograms (4 edges/thread, int4 loads) ----------------
__global__ __launch_bounds__(256)
void hist_all(I3 srcs, I3 dsts, int* cnt, int* outcnt) {
    int g = blockIdx.y;
    int i = blockIdx.x * blockDim.x + threadIdx.x;
    if (i < NEDGES / 4) {
        int4 d4 = __ldg((const int4*)dsts.p[g] + i);
        int4 s4 = __ldg((const int4*)srcs.p[g] + i);
        int* c = cnt + g * NNODES;
        int* o = outcnt + g * NNODES;
        atomicAdd(c + d4.x, 1);
        atomicAdd(c + d4.y, 1);
        atomicAdd(c + d4.z, 1);
        atomicAdd(c + d4.w, 1);
        atomicAdd(o + s4.x, 1);
        atomicAdd(o + s4.y, 1);
        atomicAdd(o + s4.z, 1);
        atomicAdd(o + s4.w, 1);
    }
}

// ---------------- launch 2: scan + norms (one block per graph) ----------------
__global__ void scan_norms(int* __restrict__ cntAll,
                           const int* __restrict__ outcntAll,
                           int* __restrict__ rowstartAll,
                           float* __restrict__ nsrcAll,
                           float* __restrict__ ndstAll) {
    __shared__ int part[1024];
    const int gb = blockIdx.x;
    int* cnt          = cntAll      + gb * NNODES;
    const int* outcnt = outcntAll   + gb * NNODES;
    int* rowstart     = rowstartAll + gb * (NNODES + 1);
    float* nsrc       = nsrcAll + gb * NNODES;
    float* ndst       = ndstAll + gb * NNODES;
    const int t = threadIdx.x;
    const int chunk = (NNODES + 1023) / 1024;
    const int lo = t * chunk;
    const int hi = min(lo + chunk, NNODES);
    int s = 0;
    for (int i = lo; i < hi; i++) {
        int c = cnt[i];
        s += c;
        ndst[i] = rsqrtf(fmaxf((float)c, 1.f));
        nsrc[i] = rsqrtf(fmaxf((float)outcnt[i], 1.f));
    }
    part[t] = s;
    __syncthreads();
    for (int off = 1; off < 1024; off <<= 1) {
        int v = (t >= off) ? part[t - off] : 0;
        __syncthreads();
        part[t] += v;
        __syncthreads();
    }
    int run = part[t] - s;
    for (int i = lo; i < hi; i++) {
        int c = cnt[i];
        rowstart[i] = run;
        cnt[i] = run;          // cursor = row start (absolute)
        run += c;
    }
    if (t == 1023) rowstart[NNODES] = part[1023];
}

// ---------------- launch 3: CSR fill (4 edges/thread) ----------------
__global__ __launch_bounds__(256)
void fill_all(I3 srcs, I3 dsts, int* cnt, int* __restrict__ esrcAll) {
    int g = blockIdx.y;
    int i = blockIdx.x * blockDim.x + threadIdx.x;
    if (i < NEDGES / 4) {
        int4 d4 = __ldg((const int4*)dsts.p[g] + i);
        int4 s4 = __ldg((const int4*)srcs.p[g] + i);
        int* c = cnt + g * NNODES;
        int* esrc = esrcAll + (size_t)g * NEDGES;
        int p0 = atomicAdd(c + d4.x, 1);
        int p1 = atomicAdd(c + d4.y, 1);
        int p2 = atomicAdd(c + d4.z, 1);
        int p3 = atomicAdd(c + d4.w, 1);
        esrc[p0] = s4.x;
        esrc[p1] = s4.y;
        esrc[p2] = s4.z;
        esrc[p3] = s4.w;
    }
}

// ---------------- launches 4-6: scaled gather SpMM, ONE GRAPH per launch ----------------
// XS[i,:] = sum_{e in row i} nsrc[s]*feat[s,:]  -> packed bf16 hi/lo planes
__global__ __launch_bounds__(256)
void spmm_scaled(const float* __restrict__ X,
                 const int* __restrict__ rowstart,
                 const int* __restrict__ esrc,
                 uint32_t* __restrict__ XSh,
                 uint32_t* __restrict__ XSl,
                 const float* __restrict__ nsrc)
{
    int gt = blockIdx.x * blockDim.x + threadIdx.x;
    int row = gt >> 5;        // warp id == row
    int lc  = gt & 31;        // float4 lane (32 x 4 = 128 cols)
    if (row >= NNODES) return;

    int beg = rowstart[row];
    int end = rowstart[row + 1];
    float4 acc = make_float4(0.f, 0.f, 0.f, 0.f);
    int e = beg;
    for (; e + 4 <= end; e += 4) {
        int s0 = __ldg(esrc + e + 0);
        int s1 = __ldg(esrc + e + 1);
        int s2 = __ldg(esrc + e + 2);
        int s3 = __ldg(esrc + e + 3);
        float w0 = __ldg(nsrc + s0), w1 = __ldg(nsrc + s1);
        float w2 = __ldg(nsrc + s2), w3 = __ldg(nsrc + s3);
        float4 v0 = __ldg((const float4*)(X + (size_t)s0 * FIN) + lc);
        float4 v1 = __ldg((const float4*)(X + (size_t)s1 * FIN) + lc);
        float4 v2 = __ldg((const float4*)(X + (size_t)s2 * FIN) + lc);
        float4 v3 = __ldg((const float4*)(X + (size_t)s3 * FIN) + lc);
        acc.x = fmaf(w0, v0.x, fmaf(w1, v1.x, fmaf(w2, v2.x, fmaf(w3, v3.x, acc.x))));
        acc.y = fmaf(w0, v0.y, fmaf(w1, v1.y, fmaf(w2, v2.y, fmaf(w3, v3.y, acc.y))));
        acc.z = fmaf(w0, v0.z, fmaf(w1, v1.z, fmaf(w2, v2.z, fmaf(w3, v3.z, acc.z))));
        acc.w = fmaf(w0, v0.w, fmaf(w1, v1.w, fmaf(w2, v2.w, fmaf(w3, v3.w, acc.w))));
    }
    for (; e < end; e++) {
        int s = __ldg(esrc + e);
        float ws = __ldg(nsrc + s);
        float4 v = __ldg((const float4*)(X + (size_t)s * FIN) + lc);
        acc.x = fmaf(ws, v.x, acc.x);
        acc.y = fmaf(ws, v.y, acc.y);
        acc.z = fmaf(ws, v.z, acc.z);
        acc.w = fmaf(ws, v.w, acc.w);
    }
    uint32_t h0, l0, h1, l1;
    split2(acc.x, acc.y, h0, l0);
    split2(acc.z, acc.w, h1, l1);
    *((uint2*)(XSh + (size_t)row * 64) + lc) = make_uint2(h0, h1);
    *((uint2*)(XSl + (size_t)row * 64) + lc) = make_uint2(l0, l1);
}

// ---------------- launch 7: fused dense chain ----------------
// H2 = fp16( relu( (XS @ W1) * ndst + b1 ) @ W2 * nsrc )
#define LDAp 12
#define LDB1 136
#define LDT  68
#define LDB2 72
#define OFF_AH 0
#define OFF_AL (OFF_AH + 128 * LDAp)
#define OFF_B1H (OFF_AL + 128 * LDAp)
#define OFF_B1L (OFF_B1H + 8 * LDB1)
#define OFF_TH (OFF_B1L + 8 * LDB1)
#define OFF_TL (OFF_TH + 128 * LDT)
#define OFF_B2H (OFF_TL + 128 * LDT)
#define OFF_B2L (OFF_B2H + 8 * LDB2)
#define OFF_BSH (OFF_B2L + 8 * LDB2)
#define SMEM_WORDS (OFF_BSH + 128)

__global__ __launch_bounds__(256)
void fused_gemm(const uint32_t* __restrict__ XShBase,
                const uint32_t* __restrict__ XSlBase,
                const uint32_t* __restrict__ W1h, const uint32_t* __restrict__ W1l,
                const uint32_t* __restrict__ W2h, const uint32_t* __restrict__ W2l,
                const float* __restrict__ b1,
                __half* __restrict__ H2base,
                const float* __restrict__ nsrcAll,
                const float* __restrict__ ndstAll)
{
    extern __shared__ uint32_t sm[];
    uint32_t* Ahp = sm + OFF_AH;    // [128][LDAp]
    uint32_t* Alp = sm + OFF_AL;
    uint32_t* B1h = sm + OFF_B1H;   // [8][LDB1]
    uint32_t* B1l = sm + OFF_B1L;
    uint32_t* Th  = sm + OFF_TH;    // [128][LDT]
    uint32_t* Tl  = sm + OFF_TL;
    uint32_t* B2h = sm + OFF_B2H;   // [8][LDB2]
    uint32_t* B2l = sm + OFF_B2L;
    float*    bsh = (float*)(sm + OFF_BSH);

    const int gidx = blockIdx.y;
    const uint32_t* XSh = XShBase + (size_t)gidx * NNODES * 64;
    const uint32_t* XSl = XSlBase + (size_t)gidx * NNODES * 64;
    __half*      H2   = H2base + (size_t)gidx * NNODES * FOUT;
    const float* nsrc = nsrcAll + gidx * NNODES;
    const float* ndst = ndstAll + gidx * NNODES;

    const int tid  = threadIdx.x;
    const int warp = tid >> 5;
    const int lane = tid & 31;
    const int warp_m = warp & 3;
    const int warp_n = warp >> 2;
    const int m0w = warp_m * 32;
    const int g  = lane >> 2;
    const int tg = lane & 3;
    const int blockRow = blockIdx.x * 128;
    const int M = NNODES;

    if (tid < FHID) bsh[tid] = b1[tid];

    // ================= stage 1: T = XS @ W1 (3-term bf16) =================
    float acc1[2][8][4];
#pragma unroll
    for (int mi = 0; mi < 2; mi++)
#pragma unroll
        for (int ni = 0; ni < 8; ni++)
#pragma unroll
            for (int j = 0; j < 4; j++) acc1[mi][ni][j] = 0.f;

    const int n0w1 = warp_n * 64;
    const int arow = tid >> 1;          // 0..127
    const int aq   = (tid & 1) * 4;     // uint4 column within 8-wide chunk

    for (int kc = 0; kc < FIN; kc += 16) {
        __syncthreads();
        // A chunk: pre-packed planes, direct copy
        {
            int grow = blockRow + arow;
            uint4 vh = make_uint4(0u, 0u, 0u, 0u);
            uint4 vl = make_uint4(0u, 0u, 0u, 0u);
            if (grow < M) {
                vh = *(const uint4*)(XSh + (size_t)grow * 64 + kc / 2 + aq);
                vl = *(const uint4*)(XSl + (size_t)grow * 64 + kc / 2 + aq);
            }
            *(uint4*)&Ahp[arow * LDAp + aq] = vh;
            *(uint4*)&Alp[arow * LDAp + aq] = vl;
        }
        // B1 chunk (pre-packed)
        {
            int jp = tid >> 5;
            int c4 = (tid & 31) * 4;
            *(uint4*)&B1h[jp * LDB1 + c4] =
                *(const uint4*)(W1h + (size_t)(kc / 2 + jp) * FHID + c4);
            *(uint4*)&B1l[jp * LDB1 + c4] =
                *(const uint4*)(W1l + (size_t)(kc / 2 + jp) * FHID + c4);
        }
        __syncthreads();

        uint32_t ah[2][4], al[2][4];
#pragma unroll
        for (int mi = 0; mi < 2; mi++) {
            int r = m0w + mi * 16 + g;
            ah[mi][0] = Ahp[r * LDAp + tg];            al[mi][0] = Alp[r * LDAp + tg];
            ah[mi][1] = Ahp[(r + 8) * LDAp + tg];      al[mi][1] = Alp[(r + 8) * LDAp + tg];
            ah[mi][2] = Ahp[r * LDAp + tg + 4];        al[mi][2] = Alp[r * LDAp + tg + 4];
            ah[mi][3] = Ahp[(r + 8) * LDAp + tg + 4];  al[mi][3] = Alp[(r + 8) * LDAp + tg + 4];
        }
#pragma unroll
        for (int ni = 0; ni < 8; ni++) {
            int c = n0w1 + ni * 8 + g;
            uint32_t bh[2], bl[2];
            bh[0] = B1h[tg * LDB1 + c];        bl[0] = B1l[tg * LDB1 + c];
            bh[1] = B1h[(tg + 4) * LDB1 + c];  bl[1] = B1l[(tg + 4) * LDB1 + c];
#pragma unroll
            for (int mi = 0; mi < 2; mi++) {
                mma_bf16(acc1[mi][ni], al[mi], bh);
                mma_bf16(acc1[mi][ni], ah[mi], bl);
                mma_bf16(acc1[mi][ni], ah[mi], bh);
            }
        }
    }

    // ---- t = relu(T*ndst + b1), packed bf16 hi/lo into smem ----
    __syncthreads();
#pragma unroll
    for (int mi = 0; mi < 2; mi++) {
        int r0 = m0w + mi * 16 + g;
        int r1 = r0 + 8;
        int gr0 = blockRow + r0, gr1 = blockRow + r1;
        float nd0 = (gr0 < M) ? ndst[gr0] : 0.f;
        float nd1 = (gr1 < M) ? ndst[gr1] : 0.f;
#pragma unroll
        for (int ni = 0; ni < 8; ni++) {
            int col = n0w1 + ni * 8 + 2 * tg;
            int cp  = col >> 1;
            float t00 = fmaxf(fmaf(acc1[mi][ni][0], nd0, bsh[col]), 0.f);
            float t01 = fmaxf(fmaf(acc1[mi][ni][1], nd0, bsh[col + 1]), 0.f);
            float t10 = fmaxf(fmaf(acc1[mi][ni][2], nd1, bsh[col]), 0.f);
            float t11 = fmaxf(fmaf(acc1[mi][ni][3], nd1, bsh[col + 1]), 0.f);
            uint32_t h, l;
            split2(t00, t01, h, l);
            Th[r0 * LDT + cp] = h;  Tl[r0 * LDT + cp] = l;
            split2(t10, t11, h, l);
            Th[r1 * LDT + cp] = h;  Tl[r1 * LDT + cp] = l;
        }
    }

    // ================= stage 2: H2 = t @ W2 * nsrc =================
    float acc2[2][4][4];
#pragma unroll
    for (int mi = 0; mi < 2; mi++)
#pragma unroll
        for (int ni = 0; ni < 4; ni++)
#pragma unroll
            for (int j = 0; j < 4; j++) acc2[mi][ni][j] = 0.f;

    const int n0w2 = warp_n * 32;

    for (int ch = 0; ch < 8; ch++) {
        __syncthreads();
        if (tid < 128) {
            int jp = tid >> 4;
            int c4 = (tid & 15) * 4;
            *(uint4*)&B2h[jp * LDB2 + c4] =
                *(const uint4*)(W2h + (size_t)(ch * 8 + jp) * FOUT + c4);
        } else {
            int t2 = tid - 128;
            int jp = t2 >> 4;
            int c4 = (t2 & 15) * 4;
            *(uint4*)&B2l[jp * LDB2 + c4] =
                *(const uint4*)(W2l + (size_t)(ch * 8 + jp) * FOUT + c4);
        }
        __syncthreads();

        int cb = ch * 8;
        uint32_t ah[2][4], al[2][4];
#pragma unroll
        for (int mi = 0; mi < 2; mi++) {
            int r = m0w + mi * 16 + g;
            ah[mi][0] = Th[r * LDT + cb + tg];            al[mi][0] = Tl[r * LDT + cb + tg];
            ah[mi][1] = Th[(r + 8) * LDT + cb + tg];      al[mi][1] = Tl[(r + 8) * LDT + cb + tg];
            ah[mi][2] = Th[r * LDT + cb + tg + 4];        al[mi][2] = Tl[r * LDT + cb + tg + 4];
            ah[mi][3] = Th[(r + 8) * LDT + cb + tg + 4];  al[mi][3] = Tl[(r + 8) * LDT + cb + tg + 4];
        }
#pragma unroll
        for (int ni = 0; ni < 4; ni++) {
            int c = n0w2 + ni * 8 + g;
            uint32_t bh[2], bl[2];
            bh[0] = B2h[tg * LDB2 + c];        bl[0] = B2l[tg * LDB2 + c];
            bh[1] = B2h[(tg + 4) * LDB2 + c];  bl[1] = B2l[(tg + 4) * LDB2 + c];
#pragma unroll
            for (int mi = 0; mi < 2; mi++) {
                mma_bf16(acc2[mi][ni], al[mi], bh);
                mma_bf16(acc2[mi][ni], ah[mi], bl);
                mma_bf16(acc2[mi][ni], ah[mi], bh);
            }
        }
    }

    // ---- epilogue: H2 = fp16(acc2 * nsrc) ----
#pragma unroll
    for (int mi = 0; mi < 2; mi++) {
        int gr0 = blockRow + m0w + mi * 16 + g;
        int gr1 = gr0 + 8;
        float s0 = (gr0 < M) ? nsrc[gr0] : 0.f;
        float s1 = (gr1 < M) ? nsrc[gr1] : 0.f;
#pragma unroll
        for (int ni = 0; ni < 4; ni++) {
            int col = n0w2 + ni * 8 + 2 * tg;
            if (gr0 < M)
                *(half2*)(H2 + (size_t)gr0 * FOUT + col) =
                    __floats2half2_rn(acc2[mi][ni][0] * s0, acc2[mi][ni][1] * s0);
            if (gr1 < M)
                *(half2*)(H2 + (size_t)gr1 * FOUT + col) =
                    __floats2half2_rn(acc2[mi][ni][2] * s1, acc2[mi][ni][3] * s1);
        }
    }
}

// ---------------- launch 8: final gather SpMM (fp16 H2 rows, fp32 accumulate) ----------------
__global__ __launch_bounds__(256)
void spmm_out(const __half* __restrict__ H2base,
              const int* __restrict__ rowstartAll,
              const int* __restrict__ esrcAll,
              float* __restrict__ outBase,
              const float* __restrict__ ndstAll,
              const float* __restrict__ bias)
{
    constexpr int C = FOUT;          // 64 halves per row (128 bytes)
    const int gidx = blockIdx.y;
    const __half* H = H2base + (size_t)gidx * NNODES * C;
    const int* rowstart = rowstartAll + gidx * (NNODES + 1);
    const int* esrc = esrcAll + (size_t)gidx * NEDGES;
    float* out = outBase + (size_t)gidx * NNODES * C;

    int gt = blockIdx.x * blockDim.x + threadIdx.x;
    int w = gt >> 5;
    int lane = gt & 31;
    int sub = lane >> 4;             // 2 rows per warp
    int lc  = lane & 15;             // uint2 lane: 4 halves
    int row = w * 2 + sub;
    if (row >= NNODES) return;

    int beg = rowstart[row];
    int end = rowstart[row + 1];
    float4 acc = make_float4(0.f, 0.f, 0.f, 0.f);
    int e = beg;
    for (; e + 4 <= end; e += 4) {
        int s0 = __ldg(esrc + e + 0);
        int s1 = __ldg(esrc + e + 1);
        int s2 = __ldg(esrc + e + 2);
        int s3 = __ldg(esrc + e + 3);
        uint2 u0 = __ldg((const uint2*)(H + (size_t)s0 * C) + lc);
        uint2 u1 = __ldg((const uint2*)(H + (size_t)s1 * C) + lc);
        uint2 u2 = __ldg((const uint2*)(H + (size_t)s2 * C) + lc);
        uint2 u3 = __ldg((const uint2*)(H + (size_t)s3 * C) + lc);
#pragma unroll
        for (int j = 0; j < 4; j++) {
            uint2 u = (j == 0) ? u0 : (j == 1) ? u1 : (j == 2) ? u2 : u3;
            float2 fa = __half22float2(*(half2*)&u.x);
            float2 fb = __half22float2(*(half2*)&u.y);
            acc.x += fa.x; acc.y += fa.y; acc.z += fb.x; acc.w += fb.y;
        }
    }
    for (; e < end; e++) {
        int s = __ldg(esrc + e);
        uint2 u = __ldg((const uint2*)(H + (size_t)s * C) + lc);
        float2 fa = __half22float2(*(half2*)&u.x);
        float2 fb = __half22float2(*(half2*)&u.y);
        acc.x += fa.x; acc.y += fa.y; acc.z += fb.x; acc.w += fb.y;
    }
    float nd = ndstAll[gidx * NNODES + row];
    float4 b = ((const float4*)bias)[lc];
    acc.x = fmaf(acc.x, nd, b.x);
    acc.y = fmaf(acc.y, nd, b.y);
    acc.z = fmaf(acc.z, nd, b.z);
    acc.w = fmaf(acc.w, nd, b.w);
    *((float4*)(out + (size_t)row * C) + lc) = acc;
}

// ---------------- launch ----------------
extern "C" void kernel_launch(void* const* d_in, const int* in_sizes, int n_in,
                              void* d_out, int out_size)
{
    float *nsrc, *ndst;
    int *cnt, *outcnt, *rowstart, *esrc;
    uint32_t *xsh, *xsl, *w1h, *w1l, *w2h, *w2l;
    __half *h2;
    cudaGetSymbolAddress((void**)&xsh,      g_XSh);
    cudaGetSymbolAddress((void**)&xsl,      g_XSl);
    cudaGetSymbolAddress((void**)&h2,       g_H2);
    cudaGetSymbolAddress((void**)&cnt,      g_cnt);
    cudaGetSymbolAddress((void**)&outcnt,   g_outcnt);
    cudaGetSymbolAddress((void**)&rowstart, g_rowstart);
    cudaGetSymbolAddress((void**)&esrc,     g_esrc);
    cudaGetSymbolAddress((void**)&nsrc,     g_nsrc);
    cudaGetSymbolAddress((void**)&ndst,     g_ndst);
    cudaGetSymbolAddress((void**)&w1h,      g_W1h);
    cudaGetSymbolAddress((void**)&w1l,      g_W1l);
    cudaGetSymbolAddress((void**)&w2h,      g_W2h);
    cudaGetSymbolAddress((void**)&w2l,      g_W2l);

    F3 feats = {{ (const float*)d_in[0], (const float*)d_in[3], (const float*)d_in[6] }};
    I3 srcs  = {{ (const int*)d_in[1],   (const int*)d_in[4],   (const int*)d_in[7] }};
    I3 dsts  = {{ (const int*)d_in[2],   (const int*)d_in[5],   (const int*)d_in[8] }};
    const float* W1 = (const float*)d_in[9];
    const float* b1 = (const float*)d_in[10];
    const float* W2 = (const float*)d_in[11];
    const float* b2 = (const float*)d_in[12];

    static const size_t SMEM_BYTES = SMEM_WORDS * sizeof(uint32_t);
    cudaFuncSetAttribute(fused_gemm, cudaFuncAttributeMaxDynamicSharedMemorySize,
                         (int)SMEM_BYTES);

    dim3 gE((NEDGES / 4 + 255) / 256, 3);        // 4 edges per thread
    dim3 gG((NNODES + 127) / 128, 3);
    const int gS1 = (NNODES * 32 + 255) / 256;
    dim3 gS2((NNODES * 16 + 255) / 256, 3);

    zero_pack <<<(3 * NNODES + 255) / 256, 256>>>(cnt, outcnt, W1, W2, w1h, w1l, w2h, w2l);
    hist_all  <<<gE, 256>>>(srcs, dsts, cnt, outcnt);
    scan_norms<<<3, 1024>>>(cnt, outcnt, rowstart, nsrc, ndst);
    fill_all  <<<gE, 256>>>(srcs, dsts, cnt, esrc);

    // XS = gather(nsrc * feat), one graph per launch (L2-resident features)
    for (int g = 0; g < 3; g++)
        spmm_scaled<<<gS1, 256>>>(feats.p[g],
                                  rowstart + g * (NNODES + 1),
                                  esrc + (size_t)g * NEDGES,
                                  xsh + (size_t)g * NNODES * 64,
                                  xsl + (size_t)g * NNODES * 64,
                                  nsrc + g * NNODES);

    // H2 = fp16( relu((XS@W1)*ndst + b1) @ W2 * nsrc )
    fused_gemm<<<gG, 256, SMEM_BYTES>>>(xsh, xsl, w1h, w1l, w2h, w2l, b1, h2, nsrc, ndst);
    // out = gather(H2)*ndst + b2
    spmm_out<<<gS2, 256>>>(h2, rowstart, esrc, (float*)d_out, ndst, b2);
}

// round 13
// speedup vs baseline: 1.5767x; 1.5158x over previous
#include <cuda_runtime.h>
#include <cuda_bf16.h>
#include <cuda_fp16.h>
#include <cstdint>

#define NNODES 100000
#define NEDGES 1600000
#define FIN 128
#define FHID 128
#define FOUT 64
#define SCAN_NB 98   // ceil(NNODES / 1024)

// ---------------- scratch (static device globals; no allocation) ----------------
__device__ uint32_t g_XSh[(size_t)3 * NNODES * 64];    // XS bf16-hi plane (k-pairs packed)
__device__ uint32_t g_XSl[(size_t)3 * NNODES * 64];    // XS bf16-lo plane
__device__ __half   g_H2 [(size_t)3 * NNODES * FOUT];  // layer-2 transformed features (fp16)
__device__ int      g_cnt     [3 * NNODES];            // hist -> cursor
__device__ int      g_outcnt  [3 * NNODES];
__device__ int      g_rowstart[3 * (NNODES + 1)];
__device__ int      g_partial [3 * SCAN_NB];           // per-block scan totals
__device__ int      g_esrc    [3 * NEDGES];
__device__ float    g_nsrc    [3 * NNODES];
__device__ float    g_ndst    [3 * NNODES];
__device__ uint32_t g_W1h[64 * 128], g_W1l[64 * 128];  // W1 packed bf16 hi/lo (k-pairs)
__device__ uint32_t g_W2h[64 * 64],  g_W2l[64 * 64];   // W2 packed bf16 hi/lo

struct F3 { const float* p[3]; };
struct I3 { const int*   p[3]; };

// ---------------- bf16 split helpers ----------------
__device__ __forceinline__ void split2(float f0, float f1, uint32_t& uh, uint32_t& ul) {
    __nv_bfloat16 h0 = __float2bfloat16_rn(f0), h1 = __float2bfloat16_rn(f1);
    float r0 = f0 - __bfloat162float(h0);
    float r1 = f1 - __bfloat162float(h1);
    __nv_bfloat16 l0 = __float2bfloat16_rn(r0), l1 = __float2bfloat16_rn(r1);
    uh = ((uint32_t)(*(uint16_t*)&h1) << 16) | (uint32_t)(*(uint16_t*)&h0);
    ul = ((uint32_t)(*(uint16_t*)&l1) << 16) | (uint32_t)(*(uint16_t*)&l0);
}

__device__ __forceinline__ void mma_bf16(float* d, const uint32_t* a, const uint32_t* b) {
    asm volatile(
        "mma.sync.aligned.m16n8k16.row.col.f32.bf16.bf16.f32 "
        "{%0,%1,%2,%3},{%4,%5,%6,%7},{%8,%9},{%0,%1,%2,%3};"
        : "+f"(d[0]), "+f"(d[1]), "+f"(d[2]), "+f"(d[3])
        : "r"(a[0]), "r"(a[1]), "r"(a[2]), "r"(a[3]), "r"(b[0]), "r"(b[1]));
}

// ---------------- launch 0: zero histograms + pack weights ----------------
__global__ void zero_pack(int* cnt, int* outcnt,
                          const float* __restrict__ W1, const float* __restrict__ W2,
                          uint32_t* w1h, uint32_t* w1l, uint32_t* w2h, uint32_t* w2l) {
    int i = blockIdx.x * blockDim.x + threadIdx.x;
    if (i < 3 * NNODES) { cnt[i] = 0; outcnt[i] = 0; }
    if (i < 64 * 128) {
        int kp = i >> 7, c = i & 127;
        split2(W1[(2 * kp) * FHID + c], W1[(2 * kp + 1) * FHID + c], w1h[i], w1l[i]);
    }
    if (i < 64 * 64) {
        int kp = i >> 6, c = i & 63;
        split2(W2[(2 * kp) * FOUT + c], W2[(2 * kp + 1) * FOUT + c], w2h[i], w2l[i]);
    }
}

// ---------------- launch 1: degree histograms (4 edges/thread, int4 loads) ----------------
__global__ __launch_bounds__(256)
void hist_all(I3 srcs, I3 dsts, int* cnt, int* outcnt) {
    int g = blockIdx.y;
    int i = blockIdx.x * blockDim.x + threadIdx.x;
    if (i < NEDGES / 4) {
        int4 d4 = __ldg((const int4*)dsts.p[g] + i);
        int4 s4 = __ldg((const int4*)srcs.p[g] + i);
        int* c = cnt + g * NNODES;
        int* o = outcnt + g * NNODES;
        atomicAdd(c + d4.x, 1);
        atomicAdd(c + d4.y, 1);
        atomicAdd(c + d4.z, 1);
        atomicAdd(c + d4.w, 1);
        atomicAdd(o + s4.x, 1);
        atomicAdd(o + s4.y, 1);
        atomicAdd(o + s4.z, 1);
        atomicAdd(o + s4.w, 1);
    }
}

// ---------------- launch 2: scanA — block-local exclusive scan + norms ----------------
// grid (SCAN_NB, 3) x 1024. rowstart gets LOCAL prefix; partial[g][b] = block total.
__global__ __launch_bounds__(1024)
void scanA(const int* __restrict__ cntAll, const int* __restrict__ outcntAll,
           int* __restrict__ rowstartAll, int* __restrict__ partial,
           float* __restrict__ nsrcAll, float* __restrict__ ndstAll) {
    __shared__ int sc[1024];
    const int g = blockIdx.y;
    const int b = blockIdx.x;
    const int t = threadIdx.x;
    const int i = b * 1024 + t;

    int c = 0;
    if (i < NNODES) {
        c = cntAll[g * NNODES + i];
        ndstAll[g * NNODES + i] = rsqrtf(fmaxf((float)c, 1.f));
        nsrcAll[g * NNODES + i] = rsqrtf(fmaxf((float)outcntAll[g * NNODES + i], 1.f));
    }
    sc[t] = c;
    __syncthreads();
    // Hillis-Steele inclusive scan
#pragma unroll
    for (int off = 1; off < 1024; off <<= 1) {
        int v = (t >= off) ? sc[t - off] : 0;
        __syncthreads();
        sc[t] += v;
        __syncthreads();
    }
    if (i < NNODES)
        rowstartAll[g * (NNODES + 1) + i] = sc[t] - c;   // local exclusive prefix
    if (t == 1023)
        partial[g * SCAN_NB + b] = sc[1023];             // block total
}

// ---------------- launch 3: scanB — scan the block totals (tiny) ----------------
__global__ void scanB(int* __restrict__ partial) {
    int g = threadIdx.x;          // 3 threads, one graph each (98 serial adds: trivial)
    if (g < 3) {
        int run = 0;
        for (int b = 0; b < SCAN_NB; b++) {
            int v = partial[g * SCAN_NB + b];
            partial[g * SCAN_NB + b] = run;
            run += v;
        }
    }
}

// ---------------- launch 4: scanC — apply offsets, set cursor ----------------
__global__ __launch_bounds__(1024)
void scanC(int* __restrict__ cntAll, int* __restrict__ rowstartAll,
           const int* __restrict__ partial) {
    const int g = blockIdx.y;
    const int b = blockIdx.x;
    const int t = threadIdx.x;
    const int i = b * 1024 + t;
    if (i < NNODES) {
        int off = partial[g * SCAN_NB + b];
        int r = rowstartAll[g * (NNODES + 1) + i] + off;
        rowstartAll[g * (NNODES + 1) + i] = r;
        cntAll[g * NNODES + i] = r;            // cursor = row start (absolute)
    }
    if (b == 0 && t == 0)
        rowstartAll[g * (NNODES + 1) + NNODES] = NEDGES;   // total in-degree is constant
}

// ---------------- launch 5: CSR fill (4 edges/thread) ----------------
__global__ __launch_bounds__(256)
void fill_all(I3 srcs, I3 dsts, int* cnt, int* __restrict__ esrcAll) {
    int g = blockIdx.y;
    int i = blockIdx.x * blockDim.x + threadIdx.x;
    if (i < NEDGES / 4) {
        int4 d4 = __ldg((const int4*)dsts.p[g] + i);
        int4 s4 = __ldg((const int4*)srcs.p[g] + i);
        int* c = cnt + g * NNODES;
        int* esrc = esrcAll + (size_t)g * NEDGES;
        int p0 = atomicAdd(c + d4.x, 1);
        int p1 = atomicAdd(c + d4.y, 1);
        int p2 = atomicAdd(c + d4.z, 1);
        int p3 = atomicAdd(c + d4.w, 1);
        esrc[p0] = s4.x;
        esrc[p1] = s4.y;
        esrc[p2] = s4.z;
        esrc[p3] = s4.w;
    }
}

// ---------------- launches 6-8: scaled gather SpMM, ONE GRAPH per launch ----------------
// XS[i,:] = sum_{e in row i} nsrc[s]*feat[s,:]  -> packed bf16 hi/lo planes
__global__ __launch_bounds__(256)
void spmm_scaled(const float* __restrict__ X,
                 const int* __restrict__ rowstart,
                 const int* __restrict__ esrc,
                 uint32_t* __restrict__ XSh,
                 uint32_t* __restrict__ XSl,
                 const float* __restrict__ nsrc)
{
    int gt = blockIdx.x * blockDim.x + threadIdx.x;
    int row = gt >> 5;        // warp id == row
    int lc  = gt & 31;        // float4 lane (32 x 4 = 128 cols)
    if (row >= NNODES) return;

    int beg = rowstart[row];
    int end = rowstart[row + 1];
    float4 acc = make_float4(0.f, 0.f, 0.f, 0.f);
    int e = beg;
    for (; e + 4 <= end; e += 4) {
        int s0 = __ldg(esrc + e + 0);
        int s1 = __ldg(esrc + e + 1);
        int s2 = __ldg(esrc + e + 2);
        int s3 = __ldg(esrc + e + 3);
        float w0 = __ldg(nsrc + s0), w1 = __ldg(nsrc + s1);
        float w2 = __ldg(nsrc + s2), w3 = __ldg(nsrc + s3);
        float4 v0 = __ldg((const float4*)(X + (size_t)s0 * FIN) + lc);
        float4 v1 = __ldg((const float4*)(X + (size_t)s1 * FIN) + lc);
        float4 v2 = __ldg((const float4*)(X + (size_t)s2 * FIN) + lc);
        float4 v3 = __ldg((const float4*)(X + (size_t)s3 * FIN) + lc);
        acc.x = fmaf(w0, v0.x, fmaf(w1, v1.x, fmaf(w2, v2.x, fmaf(w3, v3.x, acc.x))));
        acc.y = fmaf(w0, v0.y, fmaf(w1, v1.y, fmaf(w2, v2.y, fmaf(w3, v3.y, acc.y))));
        acc.z = fmaf(w0, v0.z, fmaf(w1, v1.z, fmaf(w2, v2.z, fmaf(w3, v3.z, acc.z))));
        acc.w = fmaf(w0, v0.w, fmaf(w1, v1.w, fmaf(w2, v2.w, fmaf(w3, v3.w, acc.w))));
    }
    for (; e < end; e++) {
        int s = __ldg(esrc + e);
        float ws = __ldg(nsrc + s);
        float4 v = __ldg((const float4*)(X + (size_t)s * FIN) + lc);
        acc.x = fmaf(ws, v.x, acc.x);
        acc.y = fmaf(ws, v.y, acc.y);
        acc.z = fmaf(ws, v.z, acc.z);
        acc.w = fmaf(ws, v.w, acc.w);
    }
    uint32_t h0, l0, h1, l1;
    split2(acc.x, acc.y, h0, l0);
    split2(acc.z, acc.w, h1, l1);
    *((uint2*)(XSh + (size_t)row * 64) + lc) = make_uint2(h0, h1);
    *((uint2*)(XSl + (size_t)row * 64) + lc) = make_uint2(l0, l1);
}

// ---------------- launch 9: fused dense chain ----------------
// H2 = fp16( relu( (XS @ W1) * ndst + b1 ) @ W2 * nsrc )
#define LDAp 12
#define LDB1 136
#define LDT  68
#define LDB2 72
#define OFF_AH 0
#define OFF_AL (OFF_AH + 128 * LDAp)
#define OFF_B1H (OFF_AL + 128 * LDAp)
#define OFF_B1L (OFF_B1H + 8 * LDB1)
#define OFF_TH (OFF_B1L + 8 * LDB1)
#define OFF_TL (OFF_TH + 128 * LDT)
#define OFF_B2H (OFF_TL + 128 * LDT)
#define OFF_B2L (OFF_B2H + 8 * LDB2)
#define OFF_BSH (OFF_B2L + 8 * LDB2)
#define SMEM_WORDS (OFF_BSH + 128)

__global__ __launch_bounds__(256)
void fused_gemm(const uint32_t* __restrict__ XShBase,
                const uint32_t* __restrict__ XSlBase,
                const uint32_t* __restrict__ W1h, const uint32_t* __restrict__ W1l,
                const uint32_t* __restrict__ W2h, const uint32_t* __restrict__ W2l,
                const float* __restrict__ b1,
                __half* __restrict__ H2base,
                const float* __restrict__ nsrcAll,
                const float* __restrict__ ndstAll)
{
    extern __shared__ uint32_t sm[];
    uint32_t* Ahp = sm + OFF_AH;    // [128][LDAp]
    uint32_t* Alp = sm + OFF_AL;
    uint32_t* B1h = sm + OFF_B1H;   // [8][LDB1]
    uint32_t* B1l = sm + OFF_B1L;
    uint32_t* Th  = sm + OFF_TH;    // [128][LDT]
    uint32_t* Tl  = sm + OFF_TL;
    uint32_t* B2h = sm + OFF_B2H;   // [8][LDB2]
    uint32_t* B2l = sm + OFF_B2L;
    float*    bsh = (float*)(sm + OFF_BSH);

    const int gidx = blockIdx.y;
    const uint32_t* XSh = XShBase + (size_t)gidx * NNODES * 64;
    const uint32_t* XSl = XSlBase + (size_t)gidx * NNODES * 64;
    __half*      H2   = H2base + (size_t)gidx * NNODES * FOUT;
    const float* nsrc = nsrcAll + gidx * NNODES;
    const float* ndst = ndstAll + gidx * NNODES;

    const int tid  = threadIdx.x;
    const int warp = tid >> 5;
    const int lane = tid & 31;
    const int warp_m = warp & 3;
    const int warp_n = warp >> 2;
    const int m0w = warp_m * 32;
    const int g  = lane >> 2;
    const int tg = lane & 3;
    const int blockRow = blockIdx.x * 128;
    const int M = NNODES;

    if (tid < FHID) bsh[tid] = b1[tid];

    // ================= stage 1: T = XS @ W1 (3-term bf16) =================
    float acc1[2][8][4];
#pragma unroll
    for (int mi = 0; mi < 2; mi++)
#pragma unroll
        for (int ni = 0; ni < 8; ni++)
#pragma unroll
            for (int j = 0; j < 4; j++) acc1[mi][ni][j] = 0.f;

    const int n0w1 = warp_n * 64;
    const int arow = tid >> 1;          // 0..127
    const int aq   = (tid & 1) * 4;     // uint4 column within 8-wide chunk

    for (int kc = 0; kc < FIN; kc += 16) {
        __syncthreads();
        // A chunk: pre-packed planes, direct copy
        {
            int grow = blockRow + arow;
            uint4 vh = make_uint4(0u, 0u, 0u, 0u);
            uint4 vl = make_uint4(0u, 0u, 0u, 0u);
            if (grow < M) {
                vh = *(const uint4*)(XSh + (size_t)grow * 64 + kc / 2 + aq);
                vl = *(const uint4*)(XSl + (size_t)grow * 64 + kc / 2 + aq);
            }
            *(uint4*)&Ahp[arow * LDAp + aq] = vh;
            *(uint4*)&Alp[arow * LDAp + aq] = vl;
        }
        // B1 chunk (pre-packed)
        {
            int jp = tid >> 5;
            int c4 = (tid & 31) * 4;
            *(uint4*)&B1h[jp * LDB1 + c4] =
                *(const uint4*)(W1h + (size_t)(kc / 2 + jp) * FHID + c4);
            *(uint4*)&B1l[jp * LDB1 + c4] =
                *(const uint4*)(W1l + (size_t)(kc / 2 + jp) * FHID + c4);
        }
        __syncthreads();

        uint32_t ah[2][4], al[2][4];
#pragma unroll
        for (int mi = 0; mi < 2; mi++) {
            int r = m0w + mi * 16 + g;
            ah[mi][0] = Ahp[r * LDAp + tg];            al[mi][0] = Alp[r * LDAp + tg];
            ah[mi][1] = Ahp[(r + 8) * LDAp + tg];      al[mi][1] = Alp[(r + 8) * LDAp + tg];
            ah[mi][2] = Ahp[r * LDAp + tg + 4];        al[mi][2] = Alp[r * LDAp + tg + 4];
            ah[mi][3] = Ahp[(r + 8) * LDAp + tg + 4];  al[mi][3] = Alp[(r + 8) * LDAp + tg + 4];
        }
#pragma unroll
        for (int ni = 0; ni < 8; ni++) {
            int c = n0w1 + ni * 8 + g;
            uint32_t bh[2], bl[2];
            bh[0] = B1h[tg * LDB1 + c];        bl[0] = B1l[tg * LDB1 + c];
            bh[1] = B1h[(tg + 4) * LDB1 + c];  bl[1] = B1l[(tg + 4) * LDB1 + c];
#pragma unroll
            for (int mi = 0; mi < 2; mi++) {
                mma_bf16(acc1[mi][ni], al[mi], bh);
                mma_bf16(acc1[mi][ni], ah[mi], bl);
                mma_bf16(acc1[mi][ni], ah[mi], bh);
            }
        }
    }

    // ---- t = relu(T*ndst + b1), packed bf16 hi/lo into smem ----
    __syncthreads();
#pragma unroll
    for (int mi = 0; mi < 2; mi++) {
        int r0 = m0w + mi * 16 + g;
        int r1 = r0 + 8;
        int gr0 = blockRow + r0, gr1 = blockRow + r1;
        float nd0 = (gr0 < M) ? ndst[gr0] : 0.f;
        float nd1 = (gr1 < M) ? ndst[gr1] : 0.f;
#pragma unroll
        for (int ni = 0; ni < 8; ni++) {
            int col = n0w1 + ni * 8 + 2 * tg;
            int cp  = col >> 1;
            float t00 = fmaxf(fmaf(acc1[mi][ni][0], nd0, bsh[col]), 0.f);
            float t01 = fmaxf(fmaf(acc1[mi][ni][1], nd0, bsh[col + 1]), 0.f);
            float t10 = fmaxf(fmaf(acc1[mi][ni][2], nd1, bsh[col]), 0.f);
            float t11 = fmaxf(fmaf(acc1[mi][ni][3], nd1, bsh[col + 1]), 0.f);
            uint32_t h, l;
            split2(t00, t01, h, l);
            Th[r0 * LDT + cp] = h;  Tl[r0 * LDT + cp] = l;
            split2(t10, t11, h, l);
            Th[r1 * LDT + cp] = h;  Tl[r1 * LDT + cp] = l;
        }
    }

    // ================= stage 2: H2 = t @ W2 * nsrc =================
    float acc2[2][4][4];
#pragma unroll
    for (int mi = 0; mi < 2; mi++)
#pragma unroll
        for (int ni = 0; ni < 4; ni++)
#pragma unroll
            for (int j = 0; j < 4; j++) acc2[mi][ni][j] = 0.f;

    const int n0w2 = warp_n * 32;

    for (int ch = 0; ch < 8; ch++) {
        __syncthreads();
        if (tid < 128) {
            int jp = tid >> 4;
            int c4 = (tid & 15) * 4;
            *(uint4*)&B2h[jp * LDB2 + c4] =
                *(const uint4*)(W2h + (size_t)(ch * 8 + jp) * FOUT + c4);
        } else {
            int t2 = tid - 128;
            int jp = t2 >> 4;
            int c4 = (t2 & 15) * 4;
            *(uint4*)&B2l[jp * LDB2 + c4] =
                *(const uint4*)(W2l + (size_t)(ch * 8 + jp) * FOUT + c4);
        }
        __syncthreads();

        int cb = ch * 8;
        uint32_t ah[2][4], al[2][4];
#pragma unroll
        for (int mi = 0; mi < 2; mi++) {
            int r = m0w + mi * 16 + g;
            ah[mi][0] = Th[r * LDT + cb + tg];            al[mi][0] = Tl[r * LDT + cb + tg];
            ah[mi][1] = Th[(r + 8) * LDT + cb + tg];      al[mi][1] = Tl[(r + 8) * LDT + cb + tg];
            ah[mi][2] = Th[r * LDT + cb + tg + 4];        al[mi][2] = Tl[r * LDT + cb + tg + 4];
            ah[mi][3] = Th[(r + 8) * LDT + cb + tg + 4];  al[mi][3] = Tl[(r + 8) * LDT + cb + tg + 4];
        }
#pragma unroll
        for (int ni = 0; ni < 4; ni++) {
            int c = n0w2 + ni * 8 + g;
            uint32_t bh[2], bl[2];
            bh[0] = B2h[tg * LDB2 + c];        bl[0] = B2l[tg * LDB2 + c];
            bh[1] = B2h[(tg + 4) * LDB2 + c];  bl[1] = B2l[(tg + 4) * LDB2 + c];
#pragma unroll
            for (int mi = 0; mi < 2; mi++) {
                mma_bf16(acc2[mi][ni], al[mi], bh);
                mma_bf16(acc2[mi][ni], ah[mi], bl);
                mma_bf16(acc2[mi][ni], ah[mi], bh);
            }
        }
    }

    // ---- epilogue: H2 = fp16(acc2 * nsrc) ----
#pragma unroll
    for (int mi = 0; mi < 2; mi++) {
        int gr0 = blockRow + m0w + mi * 16 + g;
        int gr1 = gr0 + 8;
        float s0 = (gr0 < M) ? nsrc[gr0] : 0.f;
        float s1 = (gr1 < M) ? nsrc[gr1] : 0.f;
#pragma unroll
        for (int ni = 0; ni < 4; ni++) {
            int col = n0w2 + ni * 8 + 2 * tg;
            if (gr0 < M)
                *(half2*)(H2 + (size_t)gr0 * FOUT + col) =
                    __floats2half2_rn(acc2[mi][ni][0] * s0, acc2[mi][ni][1] * s0);
            if (gr1 < M)
                *(half2*)(H2 + (size_t)gr1 * FOUT + col) =
                    __floats2half2_rn(acc2[mi][ni][2] * s1, acc2[mi][ni][3] * s1);
        }
    }
}

// ---------------- launch 10: final gather SpMM (fp16 H2 rows, fp32 accumulate) ----------------
__global__ __launch_bounds__(256)
void spmm_out(const __half* __restrict__ H2base,
              const int* __restrict__ rowstartAll,
              const int* __restrict__ esrcAll,
              float* __restrict__ outBase,
              const float* __restrict__ ndstAll,
              const float* __restrict__ bias)
{
    constexpr int C = FOUT;          // 64 halves per row (128 bytes)
    const int gidx = blockIdx.y;
    const __half* H = H2base + (size_t)gidx * NNODES * C;
    const int* rowstart = rowstartAll + gidx * (NNODES + 1);
    const int* esrc = esrcAll + (size_t)gidx * NEDGES;
    float* out = outBase + (size_t)gidx * NNODES * C;

    int gt = blockIdx.x * blockDim.x + threadIdx.x;
    int w = gt >> 5;
    int lane = gt & 31;
    int sub = lane >> 4;             // 2 rows per warp
    int lc  = lane & 15;             // uint2 lane: 4 halves
    int row = w * 2 + sub;
    if (row >= NNODES) return;

    int beg = rowstart[row];
    int end = rowstart[row + 1];
    float4 acc = make_float4(0.f, 0.f, 0.f, 0.f);
    int e = beg;
    for (; e + 4 <= end; e += 4) {
        int s0 = __ldg(esrc + e + 0);
        int s1 = __ldg(esrc + e + 1);
        int s2 = __ldg(esrc + e + 2);
        int s3 = __ldg(esrc + e + 3);
        uint2 u0 = __ldg((const uint2*)(H + (size_t)s0 * C) + lc);
        uint2 u1 = __ldg((const uint2*)(H + (size_t)s1 * C) + lc);
        uint2 u2 = __ldg((const uint2*)(H + (size_t)s2 * C) + lc);
        uint2 u3 = __ldg((const uint2*)(H + (size_t)s3 * C) + lc);
#pragma unroll
        for (int j = 0; j < 4; j++) {
            uint2 u = (j == 0) ? u0 : (j == 1) ? u1 : (j == 2) ? u2 : u3;
            float2 fa = __half22float2(*(half2*)&u.x);
            float2 fb = __half22float2(*(half2*)&u.y);
            acc.x += fa.x; acc.y += fa.y; acc.z += fb.x; acc.w += fb.y;
        }
    }
    for (; e < end; e++) {
        int s = __ldg(esrc + e);
        uint2 u = __ldg((const uint2*)(H + (size_t)s * C) + lc);
        float2 fa = __half22float2(*(half2*)&u.x);
        float2 fb = __half22float2(*(half2*)&u.y);
        acc.x += fa.x; acc.y += fa.y; acc.z += fb.x; acc.w += fb.y;
    }
    float nd = ndstAll[gidx * NNODES + row];
    float4 b = ((const float4*)bias)[lc];
    acc.x = fmaf(acc.x, nd, b.x);
    acc.y = fmaf(acc.y, nd, b.y);
    acc.z = fmaf(acc.z, nd, b.z);
    acc.w = fmaf(acc.w, nd, b.w);
    *((float4*)(out + (size_t)row * C) + lc) = acc;
}

// ---------------- launch ----------------
extern "C" void kernel_launch(void* const* d_in, const int* in_sizes, int n_in,
                              void* d_out, int out_size)
{
    float *nsrc, *ndst;
    int *cnt, *outcnt, *rowstart, *esrc, *partial;
    uint32_t *xsh, *xsl, *w1h, *w1l, *w2h, *w2l;
    __half *h2;
    cudaGetSymbolAddress((void**)&xsh,      g_XSh);
    cudaGetSymbolAddress((void**)&xsl,      g_XSl);
    cudaGetSymbolAddress((void**)&h2,       g_H2);
    cudaGetSymbolAddress((void**)&cnt,      g_cnt);
    cudaGetSymbolAddress((void**)&outcnt,   g_outcnt);
    cudaGetSymbolAddress((void**)&rowstart, g_rowstart);
    cudaGetSymbolAddress((void**)&partial,  g_partial);
    cudaGetSymbolAddress((void**)&esrc,     g_esrc);
    cudaGetSymbolAddress((void**)&nsrc,     g_nsrc);
    cudaGetSymbolAddress((void**)&ndst,     g_ndst);
    cudaGetSymbolAddress((void**)&w1h,      g_W1h);
    cudaGetSymbolAddress((void**)&w1l,      g_W1l);
    cudaGetSymbolAddress((void**)&w2h,      g_W2h);
    cudaGetSymbolAddress((void**)&w2l,      g_W2l);

    F3 feats = {{ (const float*)d_in[0], (const float*)d_in[3], (const float*)d_in[6] }};
    I3 srcs  = {{ (const int*)d_in[1],   (const int*)d_in[4],   (const int*)d_in[7] }};
    I3 dsts  = {{ (const int*)d_in[2],   (const int*)d_in[5],   (const int*)d_in[8] }};
    const float* W1 = (const float*)d_in[9];
    const float* b1 = (const float*)d_in[10];
    const float* W2 = (const float*)d_in[11];
    const float* b2 = (const float*)d_in[12];

    static const size_t SMEM_BYTES = SMEM_WORDS * sizeof(uint32_t);
    cudaFuncSetAttribute(fused_gemm, cudaFuncAttributeMaxDynamicSharedMemorySize,
                         (int)SMEM_BYTES);

    dim3 gE((NEDGES / 4 + 255) / 256, 3);        // 4 edges per thread
    dim3 gSc(SCAN_NB, 3);
    dim3 gG((NNODES + 127) / 128, 3);
    const int gS1 = (NNODES * 32 + 255) / 256;
    dim3 gS2((NNODES * 16 + 255) / 256, 3);

    zero_pack<<<(3 * NNODES + 255) / 256, 256>>>(cnt, outcnt, W1, W2, w1h, w1l, w2h, w2l);
    hist_all <<<gE, 256>>>(srcs, dsts, cnt, outcnt);
    scanA    <<<gSc, 1024>>>(cnt, outcnt, rowstart, partial, nsrc, ndst);
    scanB    <<<1, 32>>>(partial);
    scanC    <<<gSc, 1024>>>(cnt, rowstart, partial);
    fill_all <<<gE, 256>>>(srcs, dsts, cnt, esrc);

    // XS = gather(nsrc * feat), one graph per launch (L2-resident features)
    for (int g = 0; g < 3; g++)
        spmm_scaled<<<gS1, 256>>>(feats.p[g],
                                  rowstart + g * (NNODES + 1),
                                  esrc + (size_t)g * NEDGES,
                                  xsh + (size_t)g * NNODES * 64,
                                  xsl + (size_t)g * NNODES * 64,
                                  nsrc + g * NNODES);

    // H2 = fp16( relu((XS@W1)*ndst + b1) @ W2 * nsrc )
    fused_gemm<<<gG, 256, SMEM_BYTES>>>(xsh, xsl, w1h, w1l, w2h, w2l, b1, h2, nsrc, ndst);
    // out = gather(H2)*ndst + b2
    spmm_out<<<gS2, 256>>>(h2, rowstart, esrc, (float*)d_out, ndst, b2);
}

// round 14
// speedup vs baseline: 1.6032x; 1.0168x over previous
#include <cuda_runtime.h>
#include <cuda_bf16.h>
#include <cuda_fp16.h>
#include <cstdint>

#define NNODES 100000
#define NEDGES 1600000
#define FIN 128
#define FHID 128
#define FOUT 64
#define SCAN_NB 98   // ceil(NNODES / 1024)

// ---------------- scratch (static device globals; no allocation) ----------------
__device__ uint32_t g_XSh[(size_t)3 * NNODES * 64];    // XS bf16-hi plane (k-pairs packed)
__device__ uint32_t g_XSl[(size_t)3 * NNODES * 64];    // XS bf16-lo plane
__device__ __half   g_H2 [(size_t)3 * NNODES * FOUT];  // layer-2 transformed features (fp16)
__device__ int      g_cnt     [3 * NNODES];            // hist -> cursor
__device__ int      g_outcnt  [3 * NNODES];
__device__ int      g_rowstart[3 * (NNODES + 1)];
__device__ int      g_partial [3 * SCAN_NB];           // per-block scan totals
__device__ int      g_esrc    [3 * NEDGES];
__device__ float    g_nsrc    [3 * NNODES];
__device__ float    g_ndst    [3 * NNODES];
__device__ uint32_t g_W1h[64 * 128], g_W1l[64 * 128];  // W1 packed bf16 hi/lo (k-pairs)
__device__ uint32_t g_W2h[64 * 64],  g_W2l[64 * 64];   // W2 packed bf16 hi/lo

struct F3 { const float* p[3]; };
struct I3 { const int*   p[3]; };

// ---------------- bf16 split helpers ----------------
__device__ __forceinline__ void split2(float f0, float f1, uint32_t& uh, uint32_t& ul) {
    __nv_bfloat16 h0 = __float2bfloat16_rn(f0), h1 = __float2bfloat16_rn(f1);
    float r0 = f0 - __bfloat162float(h0);
    float r1 = f1 - __bfloat162float(h1);
    __nv_bfloat16 l0 = __float2bfloat16_rn(r0), l1 = __float2bfloat16_rn(r1);
    uh = ((uint32_t)(*(uint16_t*)&h1) << 16) | (uint32_t)(*(uint16_t*)&h0);
    ul = ((uint32_t)(*(uint16_t*)&l1) << 16) | (uint32_t)(*(uint16_t*)&l0);
}

__device__ __forceinline__ void mma_bf16(float* d, const uint32_t* a, const uint32_t* b) {
    asm volatile(
        "mma.sync.aligned.m16n8k16.row.col.f32.bf16.bf16.f32 "
        "{%0,%1,%2,%3},{%4,%5,%6,%7},{%8,%9},{%0,%1,%2,%3};"
        : "+f"(d[0]), "+f"(d[1]), "+f"(d[2]), "+f"(d[3])
        : "r"(a[0]), "r"(a[1]), "r"(a[2]), "r"(a[3]), "r"(b[0]), "r"(b[1]));
}

// ---------------- launch 0: zero histograms + pack weights ----------------
__global__ void zero_pack(int* cnt, int* outcnt,
                          const float* __restrict__ W1, const float* __restrict__ W2,
                          uint32_t* w1h, uint32_t* w1l, uint32_t* w2h, uint32_t* w2l) {
    int i = blockIdx.x * blockDim.x + threadIdx.x;
    if (i < 3 * NNODES) { cnt[i] = 0; outcnt[i] = 0; }
    if (i < 64 * 128) {
        int kp = i >> 7, c = i & 127;
        split2(W1[(2 * kp) * FHID + c], W1[(2 * kp + 1) * FHID + c], w1h[i], w1l[i]);
    }
    if (i < 64 * 64) {
        int kp = i >> 6, c = i & 63;
        split2(W2[(2 * kp) * FOUT + c], W2[(2 * kp + 1) * FOUT + c], w2h[i], w2l[i]);
    }
}

// ---------------- launch 1: degree histograms (4 edges/thread, int4 loads) ----------------
__global__ __launch_bounds__(256)
void hist_all(I3 srcs, I3 dsts, int* cnt, int* outcnt) {
    int g = blockIdx.y;
    int i = blockIdx.x * blockDim.x + threadIdx.x;
    if (i < NEDGES / 4) {
        int4 d4 = __ldg((const int4*)dsts.p[g] + i);
        int4 s4 = __ldg((const int4*)srcs.p[g] + i);
        int* c = cnt + g * NNODES;
        int* o = outcnt + g * NNODES;
        atomicAdd(c + d4.x, 1);
        atomicAdd(c + d4.y, 1);
        atomicAdd(c + d4.z, 1);
        atomicAdd(c + d4.w, 1);
        atomicAdd(o + s4.x, 1);
        atomicAdd(o + s4.y, 1);
        atomicAdd(o + s4.z, 1);
        atomicAdd(o + s4.w, 1);
    }
}

// ---------------- launch 2: scanA — block-local exclusive scan + norms ----------------
// grid (SCAN_NB, 3) x 1024. rowstart gets LOCAL prefix; partial[g][b] = block total.
__global__ __launch_bounds__(1024)
void scanA(const int* __restrict__ cntAll, const int* __restrict__ outcntAll,
           int* __restrict__ rowstartAll, int* __restrict__ partial,
           float* __restrict__ nsrcAll, float* __restrict__ ndstAll) {
    __shared__ int sc[1024];
    const int g = blockIdx.y;
    const int b = blockIdx.x;
    const int t = threadIdx.x;
    const int i = b * 1024 + t;

    int c = 0;
    if (i < NNODES) {
        c = cntAll[g * NNODES + i];
        ndstAll[g * NNODES + i] = rsqrtf(fmaxf((float)c, 1.f));
        nsrcAll[g * NNODES + i] = rsqrtf(fmaxf((float)outcntAll[g * NNODES + i], 1.f));
    }
    sc[t] = c;
    __syncthreads();
    // Hillis-Steele inclusive scan
#pragma unroll
    for (int off = 1; off < 1024; off <<= 1) {
        int v = (t >= off) ? sc[t - off] : 0;
        __syncthreads();
        sc[t] += v;
        __syncthreads();
    }
    if (i < NNODES)
        rowstartAll[g * (NNODES + 1) + i] = sc[t] - c;   // local exclusive prefix
    if (t == 1023)
        partial[g * SCAN_NB + b] = sc[1023];             // block total
}

// ---------------- launch 3: scanC — compute block offset (reduce partials) + apply ----------------
__global__ __launch_bounds__(1024)
void scanC(int* __restrict__ cntAll, int* __restrict__ rowstartAll,
           const int* __restrict__ partial) {
    __shared__ int red[128];
    const int g = blockIdx.y;
    const int b = blockIdx.x;
    const int t = threadIdx.x;
    const int i = b * 1024 + t;

    // offset = sum of partial[g][0..b-1], computed by 128-thread tree reduce
    if (t < 128)
        red[t] = (t < b) ? partial[g * SCAN_NB + t] : 0;
    __syncthreads();
#pragma unroll
    for (int off = 64; off > 0; off >>= 1) {
        if (t < off) red[t] += red[t + off];
        __syncthreads();
    }
    int offset = red[0];

    if (i < NNODES) {
        int r = rowstartAll[g * (NNODES + 1) + i] + offset;
        rowstartAll[g * (NNODES + 1) + i] = r;
        cntAll[g * NNODES + i] = r;            // cursor = row start (absolute)
    }
    if (b == 0 && t == 0)
        rowstartAll[g * (NNODES + 1) + NNODES] = NEDGES;   // total in-degree is constant
}

// ---------------- launch 4: CSR fill (8 edges/thread; MLP=8 over ATOMG latency) ----------------
__global__ __launch_bounds__(256)
void fill_all(I3 srcs, I3 dsts, int* cnt, int* __restrict__ esrcAll) {
    int g = blockIdx.y;
    int i = blockIdx.x * blockDim.x + threadIdx.x;
    if (i < NEDGES / 8) {
        int4 d4a = __ldg((const int4*)dsts.p[g] + 2 * i + 0);
        int4 d4b = __ldg((const int4*)dsts.p[g] + 2 * i + 1);
        int4 s4a = __ldg((const int4*)srcs.p[g] + 2 * i + 0);
        int4 s4b = __ldg((const int4*)srcs.p[g] + 2 * i + 1);
        int* c = cnt + g * NNODES;
        int* esrc = esrcAll + (size_t)g * NEDGES;
        int p0 = atomicAdd(c + d4a.x, 1);
        int p1 = atomicAdd(c + d4a.y, 1);
        int p2 = atomicAdd(c + d4a.z, 1);
        int p3 = atomicAdd(c + d4a.w, 1);
        int p4 = atomicAdd(c + d4b.x, 1);
        int p5 = atomicAdd(c + d4b.y, 1);
        int p6 = atomicAdd(c + d4b.z, 1);
        int p7 = atomicAdd(c + d4b.w, 1);
        esrc[p0] = s4a.x;
        esrc[p1] = s4a.y;
        esrc[p2] = s4a.z;
        esrc[p3] = s4a.w;
        esrc[p4] = s4b.x;
        esrc[p5] = s4b.y;
        esrc[p6] = s4b.z;
        esrc[p7] = s4b.w;
    }
}

// ---------------- launches 5-7: scaled gather SpMM, ONE GRAPH per launch ----------------
// XS[i,:] = sum_{e in row i} nsrc[s]*feat[s,:]  -> packed bf16 hi/lo planes
__global__ __launch_bounds__(256)
void spmm_scaled(const float* __restrict__ X,
                 const int* __restrict__ rowstart,
                 const int* __restrict__ esrc,
                 uint32_t* __restrict__ XSh,
                 uint32_t* __restrict__ XSl,
                 const float* __restrict__ nsrc)
{
    int gt = blockIdx.x * blockDim.x + threadIdx.x;
    int row = gt >> 5;        // warp id == row
    int lc  = gt & 31;        // float4 lane (32 x 4 = 128 cols)
    if (row >= NNODES) return;

    int beg = rowstart[row];
    int end = rowstart[row + 1];
    float4 acc = make_float4(0.f, 0.f, 0.f, 0.f);
    int e = beg;
    for (; e + 4 <= end; e += 4) {
        int s0 = __ldg(esrc + e + 0);
        int s1 = __ldg(esrc + e + 1);
        int s2 = __ldg(esrc + e + 2);
        int s3 = __ldg(esrc + e + 3);
        float w0 = __ldg(nsrc + s0), w1 = __ldg(nsrc + s1);
        float w2 = __ldg(nsrc + s2), w3 = __ldg(nsrc + s3);
        float4 v0 = __ldg((const float4*)(X + (size_t)s0 * FIN) + lc);
        float4 v1 = __ldg((const float4*)(X + (size_t)s1 * FIN) + lc);
        float4 v2 = __ldg((const float4*)(X + (size_t)s2 * FIN) + lc);
        float4 v3 = __ldg((const float4*)(X + (size_t)s3 * FIN) + lc);
        acc.x = fmaf(w0, v0.x, fmaf(w1, v1.x, fmaf(w2, v2.x, fmaf(w3, v3.x, acc.x))));
        acc.y = fmaf(w0, v0.y, fmaf(w1, v1.y, fmaf(w2, v2.y, fmaf(w3, v3.y, acc.y))));
        acc.z = fmaf(w0, v0.z, fmaf(w1, v1.z, fmaf(w2, v2.z, fmaf(w3, v3.z, acc.z))));
        acc.w = fmaf(w0, v0.w, fmaf(w1, v1.w, fmaf(w2, v2.w, fmaf(w3, v3.w, acc.w))));
    }
    for (; e < end; e++) {
        int s = __ldg(esrc + e);
        float ws = __ldg(nsrc + s);
        float4 v = __ldg((const float4*)(X + (size_t)s * FIN) + lc);
        acc.x = fmaf(ws, v.x, acc.x);
        acc.y = fmaf(ws, v.y, acc.y);
        acc.z = fmaf(ws, v.z, acc.z);
        acc.w = fmaf(ws, v.w, acc.w);
    }
    uint32_t h0, l0, h1, l1;
    split2(acc.x, acc.y, h0, l0);
    split2(acc.z, acc.w, h1, l1);
    *((uint2*)(XSh + (size_t)row * 64) + lc) = make_uint2(h0, h1);
    *((uint2*)(XSl + (size_t)row * 64) + lc) = make_uint2(l0, l1);
}

// ---------------- launch 8: fused dense chain ----------------
// H2 = fp16( relu( (XS @ W1) * ndst + b1 ) @ W2 * nsrc )
#define LDAp 12
#define LDB1 136
#define LDT  68
#define LDB2 72
#define OFF_AH 0
#define OFF_AL (OFF_AH + 128 * LDAp)
#define OFF_B1H (OFF_AL + 128 * LDAp)
#define OFF_B1L (OFF_B1H + 8 * LDB1)
#define OFF_TH (OFF_B1L + 8 * LDB1)
#define OFF_TL (OFF_TH + 128 * LDT)
#define OFF_B2H (OFF_TL + 128 * LDT)
#define OFF_B2L (OFF_B2H + 8 * LDB2)
#define OFF_BSH (OFF_B2L + 8 * LDB2)
#define SMEM_WORDS (OFF_BSH + 128)

__global__ __launch_bounds__(256)
void fused_gemm(const uint32_t* __restrict__ XShBase,
                const uint32_t* __restrict__ XSlBase,
                const uint32_t* __restrict__ W1h, const uint32_t* __restrict__ W1l,
                const uint32_t* __restrict__ W2h, const uint32_t* __restrict__ W2l,
                const float* __restrict__ b1,
                __half* __restrict__ H2base,
                const float* __restrict__ nsrcAll,
                const float* __restrict__ ndstAll)
{
    extern __shared__ uint32_t sm[];
    uint32_t* Ahp = sm + OFF_AH;    // [128][LDAp]
    uint32_t* Alp = sm + OFF_AL;
    uint32_t* B1h = sm + OFF_B1H;   // [8][LDB1]
    uint32_t* B1l = sm + OFF_B1L;
    uint32_t* Th  = sm + OFF_TH;    // [128][LDT]
    uint32_t* Tl  = sm + OFF_TL;
    uint32_t* B2h = sm + OFF_B2H;   // [8][LDB2]
    uint32_t* B2l = sm + OFF_B2L;
    float*    bsh = (float*)(sm + OFF_BSH);

    const int gidx = blockIdx.y;
    const uint32_t* XSh = XShBase + (size_t)gidx * NNODES * 64;
    const uint32_t* XSl = XSlBase + (size_t)gidx * NNODES * 64;
    __half*      H2   = H2base + (size_t)gidx * NNODES * FOUT;
    const float* nsrc = nsrcAll + gidx * NNODES;
    const float* ndst = ndstAll + gidx * NNODES;

    const int tid  = threadIdx.x;
    const int warp = tid >> 5;
    const int lane = tid & 31;
    const int warp_m = warp & 3;
    const int warp_n = warp >> 2;
    const int m0w = warp_m * 32;
    const int g  = lane >> 2;
    const int tg = lane & 3;
    const int blockRow = blockIdx.x * 128;
    const int M = NNODES;

    if (tid < FHID) bsh[tid] = b1[tid];

    // ================= stage 1: T = XS @ W1 (3-term bf16) =================
    float acc1[2][8][4];
#pragma unroll
    for (int mi = 0; mi < 2; mi++)
#pragma unroll
        for (int ni = 0; ni < 8; ni++)
#pragma unroll
            for (int j = 0; j < 4; j++) acc1[mi][ni][j] = 0.f;

    const int n0w1 = warp_n * 64;
    const int arow = tid >> 1;          // 0..127
    const int aq   = (tid & 1) * 4;     // uint4 column within 8-wide chunk

    for (int kc = 0; kc < FIN; kc += 16) {
        __syncthreads();
        // A chunk: pre-packed planes, direct copy
        {
            int grow = blockRow + arow;
            uint4 vh = make_uint4(0u, 0u, 0u, 0u);
            uint4 vl = make_uint4(0u, 0u, 0u, 0u);
            if (grow < M) {
                vh = *(const uint4*)(XSh + (size_t)grow * 64 + kc / 2 + aq);
                vl = *(const uint4*)(XSl + (size_t)grow * 64 + kc / 2 + aq);
            }
            *(uint4*)&Ahp[arow * LDAp + aq] = vh;
            *(uint4*)&Alp[arow * LDAp + aq] = vl;
        }
        // B1 chunk (pre-packed)
        {
            int jp = tid >> 5;
            int c4 = (tid & 31) * 4;
            *(uint4*)&B1h[jp * LDB1 + c4] =
                *(const uint4*)(W1h + (size_t)(kc / 2 + jp) * FHID + c4);
            *(uint4*)&B1l[jp * LDB1 + c4] =
                *(const uint4*)(W1l + (size_t)(kc / 2 + jp) * FHID + c4);
        }
        __syncthreads();

        uint32_t ah[2][4], al[2][4];
#pragma unroll
        for (int mi = 0; mi < 2; mi++) {
            int r = m0w + mi * 16 + g;
            ah[mi][0] = Ahp[r * LDAp + tg];            al[mi][0] = Alp[r * LDAp + tg];
            ah[mi][1] = Ahp[(r + 8) * LDAp + tg];      al[mi][1] = Alp[(r + 8) * LDAp + tg];
            ah[mi][2] = Ahp[r * LDAp + tg + 4];        al[mi][2] = Alp[r * LDAp + tg + 4];
            ah[mi][3] = Ahp[(r + 8) * LDAp + tg + 4];  al[mi][3] = Alp[(r + 8) * LDAp + tg + 4];
        }
#pragma unroll
        for (int ni = 0; ni < 8; ni++) {
            int c = n0w1 + ni * 8 + g;
            uint32_t bh[2], bl[2];
            bh[0] = B1h[tg * LDB1 + c];        bl[0] = B1l[tg * LDB1 + c];
            bh[1] = B1h[(tg + 4) * LDB1 + c];  bl[1] = B1l[(tg + 4) * LDB1 + c];
#pragma unroll
            for (int mi = 0; mi < 2; mi++) {
                mma_bf16(acc1[mi][ni], al[mi], bh);
                mma_bf16(acc1[mi][ni], ah[mi], bl);
                mma_bf16(acc1[mi][ni], ah[mi], bh);
            }
        }
    }

    // ---- t = relu(T*ndst + b1), packed bf16 hi/lo into smem ----
    __syncthreads();
#pragma unroll
    for (int mi = 0; mi < 2; mi++) {
        int r0 = m0w + mi * 16 + g;
        int r1 = r0 + 8;
        int gr0 = blockRow + r0, gr1 = blockRow + r1;
        float nd0 = (gr0 < M) ? ndst[gr0] : 0.f;
        float nd1 = (gr1 < M) ? ndst[gr1] : 0.f;
#pragma unroll
        for (int ni = 0; ni < 8; ni++) {
            int col = n0w1 + ni * 8 + 2 * tg;
            int cp  = col >> 1;
            float t00 = fmaxf(fmaf(acc1[mi][ni][0], nd0, bsh[col]), 0.f);
            float t01 = fmaxf(fmaf(acc1[mi][ni][1], nd0, bsh[col + 1]), 0.f);
            float t10 = fmaxf(fmaf(acc1[mi][ni][2], nd1, bsh[col]), 0.f);
            float t11 = fmaxf(fmaf(acc1[mi][ni][3], nd1, bsh[col + 1]), 0.f);
            uint32_t h, l;
            split2(t00, t01, h, l);
            Th[r0 * LDT + cp] = h;  Tl[r0 * LDT + cp] = l;
            split2(t10, t11, h, l);
            Th[r1 * LDT + cp] = h;  Tl[r1 * LDT + cp] = l;
        }
    }

    // ================= stage 2: H2 = t @ W2 * nsrc =================
    float acc2[2][4][4];
#pragma unroll
    for (int mi = 0; mi < 2; mi++)
#pragma unroll
        for (int ni = 0; ni < 4; ni++)
#pragma unroll
            for (int j = 0; j < 4; j++) acc2[mi][ni][j] = 0.f;

    const int n0w2 = warp_n * 32;

    for (int ch = 0; ch < 8; ch++) {
        __syncthreads();
        if (tid < 128) {
            int jp = tid >> 4;
            int c4 = (tid & 15) * 4;
            *(uint4*)&B2h[jp * LDB2 + c4] =
                *(const uint4*)(W2h + (size_t)(ch * 8 + jp) * FOUT + c4);
        } else {
            int t2 = tid - 128;
            int jp = t2 >> 4;
            int c4 = (t2 & 15) * 4;
            *(uint4*)&B2l[jp * LDB2 + c4] =
                *(const uint4*)(W2l + (size_t)(ch * 8 + jp) * FOUT + c4);
        }
        __syncthreads();

        int cb = ch * 8;
        uint32_t ah[2][4], al[2][4];
#pragma unroll
        for (int mi = 0; mi < 2; mi++) {
            int r = m0w + mi * 16 + g;
            ah[mi][0] = Th[r * LDT + cb + tg];            al[mi][0] = Tl[r * LDT + cb + tg];
            ah[mi][1] = Th[(r + 8) * LDT + cb + tg];      al[mi][1] = Tl[(r + 8) * LDT + cb + tg];
            ah[mi][2] = Th[r * LDT + cb + tg + 4];        al[mi][2] = Tl[r * LDT + cb + tg + 4];
            ah[mi][3] = Th[(r + 8) * LDT + cb + tg + 4];  al[mi][3] = Tl[(r + 8) * LDT + cb + tg + 4];
        }
#pragma unroll
        for (int ni = 0; ni < 4; ni++) {
            int c = n0w2 + ni * 8 + g;
            uint32_t bh[2], bl[2];
            bh[0] = B2h[tg * LDB2 + c];        bl[0] = B2l[tg * LDB2 + c];
            bh[1] = B2h[(tg + 4) * LDB2 + c];  bl[1] = B2l[(tg + 4) * LDB2 + c];
#pragma unroll
            for (int mi = 0; mi < 2; mi++) {
                mma_bf16(acc2[mi][ni], al[mi], bh);
                mma_bf16(acc2[mi][ni], ah[mi], bl);
                mma_bf16(acc2[mi][ni], ah[mi], bh);
            }
        }
    }

    // ---- epilogue: H2 = fp16(acc2 * nsrc) ----
#pragma unroll
    for (int mi = 0; mi < 2; mi++) {
        int gr0 = blockRow + m0w + mi * 16 + g;
        int gr1 = gr0 + 8;
        float s0 = (gr0 < M) ? nsrc[gr0] : 0.f;
        float s1 = (gr1 < M) ? nsrc[gr1] : 0.f;
#pragma unroll
        for (int ni = 0; ni < 4; ni++) {
            int col = n0w2 + ni * 8 + 2 * tg;
            if (gr0 < M)
                *(half2*)(H2 + (size_t)gr0 * FOUT + col) =
                    __floats2half2_rn(acc2[mi][ni][0] * s0, acc2[mi][ni][1] * s0);
            if (gr1 < M)
                *(half2*)(H2 + (size_t)gr1 * FOUT + col) =
                    __floats2half2_rn(acc2[mi][ni][2] * s1, acc2[mi][ni][3] * s1);
        }
    }
}

// ---------------- launch 9: final gather SpMM (fp16 H2 rows, fp32 accumulate) ----------------
__global__ __launch_bounds__(256)
void spmm_out(const __half* __restrict__ H2base,
              const int* __restrict__ rowstartAll,
              const int* __restrict__ esrcAll,
              float* __restrict__ outBase,
              const float* __restrict__ ndstAll,
              const float* __restrict__ bias)
{
    constexpr int C = FOUT;          // 64 halves per row (128 bytes)
    const int gidx = blockIdx.y;
    const __half* H = H2base + (size_t)gidx * NNODES * C;
    const int* rowstart = rowstartAll + gidx * (NNODES + 1);
    const int* esrc = esrcAll + (size_t)gidx * NEDGES;
    float* out = outBase + (size_t)gidx * NNODES * C;

    int gt = blockIdx.x * blockDim.x + threadIdx.x;
    int w = gt >> 5;
    int lane = gt & 31;
    int sub = lane >> 4;             // 2 rows per warp
    int lc  = lane & 15;             // uint2 lane: 4 halves
    int row = w * 2 + sub;
    if (row >= NNODES) return;

    int beg = rowstart[row];
    int end = rowstart[row + 1];
    float4 acc = make_float4(0.f, 0.f, 0.f, 0.f);
    int e = beg;
    for (; e + 4 <= end; e += 4) {
        int s0 = __ldg(esrc + e + 0);
        int s1 = __ldg(esrc + e + 1);
        int s2 = __ldg(esrc + e + 2);
        int s3 = __ldg(esrc + e + 3);
        uint2 u0 = __ldg((const uint2*)(H + (size_t)s0 * C) + lc);
        uint2 u1 = __ldg((const uint2*)(H + (size_t)s1 * C) + lc);
        uint2 u2 = __ldg((const uint2*)(H + (size_t)s2 * C) + lc);
        uint2 u3 = __ldg((const uint2*)(H + (size_t)s3 * C) + lc);
#pragma unroll
        for (int j = 0; j < 4; j++) {
            uint2 u = (j == 0) ? u0 : (j == 1) ? u1 : (j == 2) ? u2 : u3;
            float2 fa = __half22float2(*(half2*)&u.x);
            float2 fb = __half22float2(*(half2*)&u.y);
            acc.x += fa.x; acc.y += fa.y; acc.z += fb.x; acc.w += fb.y;
        }
    }
    for (; e < end; e++) {
        int s = __ldg(esrc + e);
        uint2 u = __ldg((const uint2*)(H + (size_t)s * C) + lc);
        float2 fa = __half22float2(*(half2*)&u.x);
        float2 fb = __half22float2(*(half2*)&u.y);
        acc.x += fa.x; acc.y += fa.y; acc.z += fb.x; acc.w += fb.y;
    }
    float nd = ndstAll[gidx * NNODES + row];
    float4 b = ((const float4*)bias)[lc];
    acc.x = fmaf(acc.x, nd, b.x);
    acc.y = fmaf(acc.y, nd, b.y);
    acc.z = fmaf(acc.z, nd, b.z);
    acc.w = fmaf(acc.w, nd, b.w);
    *((float4*)(out + (size_t)row * C) + lc) = acc;
}

// ---------------- launch ----------------
extern "C" void kernel_launch(void* const* d_in, const int* in_sizes, int n_in,
                              void* d_out, int out_size)
{
    float *nsrc, *ndst;
    int *cnt, *outcnt, *rowstart, *esrc, *partial;
    uint32_t *xsh, *xsl, *w1h, *w1l, *w2h, *w2l;
    __half *h2;
    cudaGetSymbolAddress((void**)&xsh,      g_XSh);
    cudaGetSymbolAddress((void**)&xsl,      g_XSl);
    cudaGetSymbolAddress((void**)&h2,       g_H2);
    cudaGetSymbolAddress((void**)&cnt,      g_cnt);
    cudaGetSymbolAddress((void**)&outcnt,   g_outcnt);
    cudaGetSymbolAddress((void**)&rowstart, g_rowstart);
    cudaGetSymbolAddress((void**)&partial,  g_partial);
    cudaGetSymbolAddress((void**)&esrc,     g_esrc);
    cudaGetSymbolAddress((void**)&nsrc,     g_nsrc);
    cudaGetSymbolAddress((void**)&ndst,     g_ndst);
    cudaGetSymbolAddress((void**)&w1h,      g_W1h);
    cudaGetSymbolAddress((void**)&w1l,      g_W1l);
    cudaGetSymbolAddress((void**)&w2h,      g_W2h);
    cudaGetSymbolAddress((void**)&w2l,      g_W2l);

    F3 feats = {{ (const float*)d_in[0], (const float*)d_in[3], (const float*)d_in[6] }};
    I3 srcs  = {{ (const int*)d_in[1],   (const int*)d_in[4],   (const int*)d_in[7] }};
    I3 dsts  = {{ (const int*)d_in[2],   (const int*)d_in[5],   (const int*)d_in[8] }};
    const float* W1 = (const float*)d_in[9];
    const float* b1 = (const float*)d_in[10];
    const float* W2 = (const float*)d_in[11];
    const float* b2 = (const float*)d_in[12];

    static const size_t SMEM_BYTES = SMEM_WORDS * sizeof(uint32_t);
    cudaFuncSetAttribute(fused_gemm, cudaFuncAttributeMaxDynamicSharedMemorySize,
                         (int)SMEM_BYTES);

    dim3 gE4((NEDGES / 4 + 255) / 256, 3);       // 4 edges per thread (hist)
    dim3 gE8((NEDGES / 8 + 255) / 256, 3);       // 8 edges per thread (fill)
    dim3 gSc(SCAN_NB, 3);
    dim3 gG((NNODES + 127) / 128, 3);
    const int gS1 = (NNODES * 32 + 255) / 256;
    dim3 gS2((NNODES * 16 + 255) / 256, 3);

    zero_pack<<<(3 * NNODES + 255) / 256, 256>>>(cnt, outcnt, W1, W2, w1h, w1l, w2h, w2l);
    hist_all <<<gE4, 256>>>(srcs, dsts, cnt, outcnt);
    scanA    <<<gSc, 1024>>>(cnt, outcnt, rowstart, partial, nsrc, ndst);
    scanC    <<<gSc, 1024>>>(cnt, rowstart, partial);
    fill_all <<<gE8, 256>>>(srcs, dsts, cnt, esrc);

    // XS = gather(nsrc * feat), one graph per launch (L2-resident features)
    for (int g = 0; g < 3; g++)
        spmm_scaled<<<gS1, 256>>>(feats.p[g],
                                  rowstart + g * (NNODES + 1),
                                  esrc + (size_t)g * NEDGES,
                                  xsh + (size_t)g * NNODES * 64,
                                  xsl + (size_t)g * NNODES * 64,
                                  nsrc + g * NNODES);

    // H2 = fp16( relu((XS@W1)*ndst + b1) @ W2 * nsrc )
    fused_gemm<<<gG, 256, SMEM_BYTES>>>(xsh, xsl, w1h, w1l, w2h, w2l, b1, h2, nsrc, ndst);
    // out = gather(H2)*ndst + b2
    spmm_out<<<gS2, 256>>>(h2, rowstart, esrc, (float*)d_out, ndst, b2);
}

// round 15
// speedup vs baseline: 1.6151x; 1.0075x over previous
#include <cuda_runtime.h>
#include <cuda_bf16.h>
#include <cuda_fp16.h>
#include <cstdint>

#define NNODES 100000
#define NEDGES 1600000
#define FIN 128
#define FHID 128
#define FOUT 64
#define SCAN_NB 98   // ceil(NNODES / 1024)

// ---------------- scratch (static device globals; no allocation) ----------------
__device__ uint32_t g_XSh[(size_t)3 * NNODES * 64];    // XS bf16-hi plane (k-pairs packed)
__device__ uint32_t g_XSl[(size_t)3 * NNODES * 64];    // XS bf16-lo plane
__device__ __half   g_H2 [(size_t)3 * NNODES * FOUT];  // layer-2 transformed features (fp16)
__device__ int      g_cnt     [3 * NNODES];            // hist -> cursor
__device__ int      g_outcnt  [3 * NNODES];
__device__ int      g_rowstart[3 * (NNODES + 1)];
__device__ int      g_partial [3 * SCAN_NB];           // per-block scan totals
__device__ int      g_esrc    [3 * NEDGES];
__device__ float    g_nsrc    [3 * NNODES];
__device__ float    g_ndst    [3 * NNODES];
__device__ uint32_t g_W1h[64 * 128], g_W1l[64 * 128];  // W1 packed bf16 hi/lo (k-pairs)
__device__ uint32_t g_W2h[64 * 64],  g_W2l[64 * 64];   // W2 packed bf16 hi/lo

struct F3 { const float* p[3]; };
struct I3 { const int*   p[3]; };

// ---------------- bf16 split helpers ----------------
__device__ __forceinline__ void split2(float f0, float f1, uint32_t& uh, uint32_t& ul) {
    __nv_bfloat16 h0 = __float2bfloat16_rn(f0), h1 = __float2bfloat16_rn(f1);
    float r0 = f0 - __bfloat162float(h0);
    float r1 = f1 - __bfloat162float(h1);
    __nv_bfloat16 l0 = __float2bfloat16_rn(r0), l1 = __float2bfloat16_rn(r1);
    uh = ((uint32_t)(*(uint16_t*)&h1) << 16) | (uint32_t)(*(uint16_t*)&h0);
    ul = ((uint32_t)(*(uint16_t*)&l1) << 16) | (uint32_t)(*(uint16_t*)&l0);
}

__device__ __forceinline__ void mma_bf16(float* d, const uint32_t* a, const uint32_t* b) {
    asm volatile(
        "mma.sync.aligned.m16n8k16.row.col.f32.bf16.bf16.f32 "
        "{%0,%1,%2,%3},{%4,%5,%6,%7},{%8,%9},{%0,%1,%2,%3};"
        : "+f"(d[0]), "+f"(d[1]), "+f"(d[2]), "+f"(d[3])
        : "r"(a[0]), "r"(a[1]), "r"(a[2]), "r"(a[3]), "r"(b[0]), "r"(b[1]));
}

// ---------------- launch 0: zero histograms + pack weights ----------------
__global__ void zero_pack(int* cnt, int* outcnt,
                          const float* __restrict__ W1, const float* __restrict__ W2,
                          uint32_t* w1h, uint32_t* w1l, uint32_t* w2h, uint32_t* w2l) {
    int i = blockIdx.x * blockDim.x + threadIdx.x;
    if (i < 3 * NNODES) { cnt[i] = 0; outcnt[i] = 0; }
    if (i < 64 * 128) {
        int kp = i >> 7, c = i & 127;
        split2(W1[(2 * kp) * FHID + c], W1[(2 * kp + 1) * FHID + c], w1h[i], w1l[i]);
    }
    if (i < 64 * 64) {
        int kp = i >> 6, c = i & 63;
        split2(W2[(2 * kp) * FOUT + c], W2[(2 * kp + 1) * FOUT + c], w2h[i], w2l[i]);
    }
}

// ---------------- launch 1: degree histograms (8 edges/thread, 2x int4 loads) ----------------
__global__ __launch_bounds__(256)
void hist_all(I3 srcs, I3 dsts, int* cnt, int* outcnt) {
    int g = blockIdx.y;
    int i = blockIdx.x * blockDim.x + threadIdx.x;
    if (i < NEDGES / 8) {
        int4 d4a = __ldg((const int4*)dsts.p[g] + 2 * i + 0);
        int4 d4b = __ldg((const int4*)dsts.p[g] + 2 * i + 1);
        int4 s4a = __ldg((const int4*)srcs.p[g] + 2 * i + 0);
        int4 s4b = __ldg((const int4*)srcs.p[g] + 2 * i + 1);
        int* c = cnt + g * NNODES;
        int* o = outcnt + g * NNODES;
        atomicAdd(c + d4a.x, 1);
        atomicAdd(c + d4a.y, 1);
        atomicAdd(c + d4a.z, 1);
        atomicAdd(c + d4a.w, 1);
        atomicAdd(c + d4b.x, 1);
        atomicAdd(c + d4b.y, 1);
        atomicAdd(c + d4b.z, 1);
        atomicAdd(c + d4b.w, 1);
        atomicAdd(o + s4a.x, 1);
        atomicAdd(o + s4a.y, 1);
        atomicAdd(o + s4a.z, 1);
        atomicAdd(o + s4a.w, 1);
        atomicAdd(o + s4b.x, 1);
        atomicAdd(o + s4b.y, 1);
        atomicAdd(o + s4b.z, 1);
        atomicAdd(o + s4b.w, 1);
    }
}

// ---------------- launch 2: scanA — block-local exclusive scan + norms (shuffle) ----------------
// grid (SCAN_NB, 3) x 1024. rowstart gets LOCAL prefix; partial[g][b] = block total.
__global__ __launch_bounds__(1024)
void scanA(const int* __restrict__ cntAll, const int* __restrict__ outcntAll,
           int* __restrict__ rowstartAll, int* __restrict__ partial,
           float* __restrict__ nsrcAll, float* __restrict__ ndstAll) {
    __shared__ int wsum[32];
    const int g = blockIdx.y;
    const int b = blockIdx.x;
    const int t = threadIdx.x;
    const int lane = t & 31;
    const int wid  = t >> 5;
    const int i = b * 1024 + t;

    int c = 0;
    if (i < NNODES) {
        c = cntAll[g * NNODES + i];
        ndstAll[g * NNODES + i] = rsqrtf(fmaxf((float)c, 1.f));
        nsrcAll[g * NNODES + i] = rsqrtf(fmaxf((float)outcntAll[g * NNODES + i], 1.f));
    }
    // intra-warp inclusive scan
    int v = c;
#pragma unroll
    for (int off = 1; off < 32; off <<= 1) {
        int n = __shfl_up_sync(0xffffffffu, v, off);
        if (lane >= off) v += n;
    }
    if (lane == 31) wsum[wid] = v;
    __syncthreads();
    // warp 0 scans the 32 warp totals (inclusive)
    if (wid == 0) {
        int w = wsum[lane];
#pragma unroll
        for (int off = 1; off < 32; off <<= 1) {
            int n = __shfl_up_sync(0xffffffffu, w, off);
            if (lane >= off) w += n;
        }
        wsum[lane] = w;
    }
    __syncthreads();
    int base = (wid > 0) ? wsum[wid - 1] : 0;
    int incl = v + base;                       // block-inclusive prefix
    if (i < NNODES)
        rowstartAll[g * (NNODES + 1) + i] = incl - c;   // local exclusive prefix
    if (t == 1023)
        partial[g * SCAN_NB + b] = incl;                 // block total
}

// ---------------- launch 3: scanC — compute block offset (reduce partials) + apply ----------------
__global__ __launch_bounds__(1024)
void scanC(int* __restrict__ cntAll, int* __restrict__ rowstartAll,
           const int* __restrict__ partial) {
    __shared__ int red[128];
    const int g = blockIdx.y;
    const int b = blockIdx.x;
    const int t = threadIdx.x;
    const int i = b * 1024 + t;

    if (t < 128)
        red[t] = (t < b) ? partial[g * SCAN_NB + t] : 0;
    __syncthreads();
#pragma unroll
    for (int off = 64; off > 0; off >>= 1) {
        if (t < off) red[t] += red[t + off];
        __syncthreads();
    }
    int offset = red[0];

    if (i < NNODES) {
        int r = rowstartAll[g * (NNODES + 1) + i] + offset;
        rowstartAll[g * (NNODES + 1) + i] = r;
        cntAll[g * NNODES + i] = r;            // cursor = row start (absolute)
    }
    if (b == 0 && t == 0)
        rowstartAll[g * (NNODES + 1) + NNODES] = NEDGES;
}

// ---------------- launch 4: CSR fill (8 edges/thread; MLP=8 over ATOMG latency) ----------------
__global__ __launch_bounds__(256)
void fill_all(I3 srcs, I3 dsts, int* cnt, int* __restrict__ esrcAll) {
    int g = blockIdx.y;
    int i = blockIdx.x * blockDim.x + threadIdx.x;
    if (i < NEDGES / 8) {
        int4 d4a = __ldg((const int4*)dsts.p[g] + 2 * i + 0);
        int4 d4b = __ldg((const int4*)dsts.p[g] + 2 * i + 1);
        int4 s4a = __ldg((const int4*)srcs.p[g] + 2 * i + 0);
        int4 s4b = __ldg((const int4*)srcs.p[g] + 2 * i + 1);
        int* c = cnt + g * NNODES;
        int* esrc = esrcAll + (size_t)g * NEDGES;
        int p0 = atomicAdd(c + d4a.x, 1);
        int p1 = atomicAdd(c + d4a.y, 1);
        int p2 = atomicAdd(c + d4a.z, 1);
        int p3 = atomicAdd(c + d4a.w, 1);
        int p4 = atomicAdd(c + d4b.x, 1);
        int p5 = atomicAdd(c + d4b.y, 1);
        int p6 = atomicAdd(c + d4b.z, 1);
        int p7 = atomicAdd(c + d4b.w, 1);
        esrc[p0] = s4a.x;
        esrc[p1] = s4a.y;
        esrc[p2] = s4a.z;
        esrc[p3] = s4a.w;
        esrc[p4] = s4b.x;
        esrc[p5] = s4b.y;
        esrc[p6] = s4b.z;
        esrc[p7] = s4b.w;
    }
}

// ---------------- launches 5-7: scaled gather SpMM, ONE GRAPH per launch ----------------
// XS[i,:] = sum_{e in row i} nsrc[s]*feat[s,:]  -> packed bf16 hi/lo planes
__global__ __launch_bounds__(256)
void spmm_scaled(const float* __restrict__ X,
                 const int* __restrict__ rowstart,
                 const int* __restrict__ esrc,
                 uint32_t* __restrict__ XSh,
                 uint32_t* __restrict__ XSl,
                 const float* __restrict__ nsrc)
{
    int gt = blockIdx.x * blockDim.x + threadIdx.x;
    int row = gt >> 5;        // warp id == row
    int lc  = gt & 31;        // float4 lane (32 x 4 = 128 cols)
    if (row >= NNODES) return;

    int beg = rowstart[row];
    int end = rowstart[row + 1];
    float4 acc = make_float4(0.f, 0.f, 0.f, 0.f);
    int e = beg;
    for (; e + 4 <= end; e += 4) {
        int s0 = __ldg(esrc + e + 0);
        int s1 = __ldg(esrc + e + 1);
        int s2 = __ldg(esrc + e + 2);
        int s3 = __ldg(esrc + e + 3);
        float w0 = __ldg(nsrc + s0), w1 = __ldg(nsrc + s1);
        float w2 = __ldg(nsrc + s2), w3 = __ldg(nsrc + s3);
        float4 v0 = __ldg((const float4*)(X + (size_t)s0 * FIN) + lc);
        float4 v1 = __ldg((const float4*)(X + (size_t)s1 * FIN) + lc);
        float4 v2 = __ldg((const float4*)(X + (size_t)s2 * FIN) + lc);
        float4 v3 = __ldg((const float4*)(X + (size_t)s3 * FIN) + lc);
        acc.x = fmaf(w0, v0.x, fmaf(w1, v1.x, fmaf(w2, v2.x, fmaf(w3, v3.x, acc.x))));
        acc.y = fmaf(w0, v0.y, fmaf(w1, v1.y, fmaf(w2, v2.y, fmaf(w3, v3.y, acc.y))));
        acc.z = fmaf(w0, v0.z, fmaf(w1, v1.z, fmaf(w2, v2.z, fmaf(w3, v3.z, acc.z))));
        acc.w = fmaf(w0, v0.w, fmaf(w1, v1.w, fmaf(w2, v2.w, fmaf(w3, v3.w, acc.w))));
    }
    for (; e < end; e++) {
        int s = __ldg(esrc + e);
        float ws = __ldg(nsrc + s);
        float4 v = __ldg((const float4*)(X + (size_t)s * FIN) + lc);
        acc.x = fmaf(ws, v.x, acc.x);
        acc.y = fmaf(ws, v.y, acc.y);
        acc.z = fmaf(ws, v.z, acc.z);
        acc.w = fmaf(ws, v.w, acc.w);
    }
    uint32_t h0, l0, h1, l1;
    split2(acc.x, acc.y, h0, l0);
    split2(acc.z, acc.w, h1, l1);
    *((uint2*)(XSh + (size_t)row * 64) + lc) = make_uint2(h0, h1);
    *((uint2*)(XSl + (size_t)row * 64) + lc) = make_uint2(l0, l1);
}

// ---------------- launch 8: fused dense chain ----------------
// H2 = fp16( relu( (XS @ W1) * ndst + b1 ) @ W2 * nsrc )
#define LDAp 12
#define LDB1 136
#define LDT  68
#define LDB2 72
#define OFF_AH 0
#define OFF_AL (OFF_AH + 128 * LDAp)
#define OFF_B1H (OFF_AL + 128 * LDAp)
#define OFF_B1L (OFF_B1H + 8 * LDB1)
#define OFF_TH (OFF_B1L + 8 * LDB1)
#define OFF_TL (OFF_TH + 128 * LDT)
#define OFF_B2H (OFF_TL + 128 * LDT)
#define OFF_B2L (OFF_B2H + 8 * LDB2)
#define OFF_BSH (OFF_B2L + 8 * LDB2)
#define SMEM_WORDS (OFF_BSH + 128)

__global__ __launch_bounds__(256)
void fused_gemm(const uint32_t* __restrict__ XShBase,
                const uint32_t* __restrict__ XSlBase,
                const uint32_t* __restrict__ W1h, const uint32_t* __restrict__ W1l,
                const uint32_t* __restrict__ W2h, const uint32_t* __restrict__ W2l,
                const float* __restrict__ b1,
                __half* __restrict__ H2base,
                const float* __restrict__ nsrcAll,
                const float* __restrict__ ndstAll)
{
    extern __shared__ uint32_t sm[];
    uint32_t* Ahp = sm + OFF_AH;    // [128][LDAp]
    uint32_t* Alp = sm + OFF_AL;
    uint32_t* B1h = sm + OFF_B1H;   // [8][LDB1]
    uint32_t* B1l = sm + OFF_B1L;
    uint32_t* Th  = sm + OFF_TH;    // [128][LDT]
    uint32_t* Tl  = sm + OFF_TL;
    uint32_t* B2h = sm + OFF_B2H;   // [8][LDB2]
    uint32_t* B2l = sm + OFF_B2L;
    float*    bsh = (float*)(sm + OFF_BSH);

    const int gidx = blockIdx.y;
    const uint32_t* XSh = XShBase + (size_t)gidx * NNODES * 64;
    const uint32_t* XSl = XSlBase + (size_t)gidx * NNODES * 64;
    __half*      H2   = H2base + (size_t)gidx * NNODES * FOUT;
    const float* nsrc = nsrcAll + gidx * NNODES;
    const float* ndst = ndstAll + gidx * NNODES;

    const int tid  = threadIdx.x;
    const int warp = tid >> 5;
    const int lane = tid & 31;
    const int warp_m = warp & 3;
    const int warp_n = warp >> 2;
    const int m0w = warp_m * 32;
    const int g  = lane >> 2;
    const int tg = lane & 3;
    const int blockRow = blockIdx.x * 128;
    const int M = NNODES;

    if (tid < FHID) bsh[tid] = b1[tid];

    // ================= stage 1: T = XS @ W1 (3-term bf16) =================
    float acc1[2][8][4];
#pragma unroll
    for (int mi = 0; mi < 2; mi++)
#pragma unroll
        for (int ni = 0; ni < 8; ni++)
#pragma unroll
            for (int j = 0; j < 4; j++) acc1[mi][ni][j] = 0.f;

    const int n0w1 = warp_n * 64;
    const int arow = tid >> 1;          // 0..127
    const int aq   = (tid & 1) * 4;     // uint4 column within 8-wide chunk

    for (int kc = 0; kc < FIN; kc += 16) {
        __syncthreads();
        // A chunk: pre-packed planes, direct copy
        {
            int grow = blockRow + arow;
            uint4 vh = make_uint4(0u, 0u, 0u, 0u);
            uint4 vl = make_uint4(0u, 0u, 0u, 0u);
            if (grow < M) {
                vh = *(const uint4*)(XSh + (size_t)grow * 64 + kc / 2 + aq);
                vl = *(const uint4*)(XSl + (size_t)grow * 64 + kc / 2 + aq);
            }
            *(uint4*)&Ahp[arow * LDAp + aq] = vh;
            *(uint4*)&Alp[arow * LDAp + aq] = vl;
        }
        // B1 chunk (pre-packed)
        {
            int jp = tid >> 5;
            int c4 = (tid & 31) * 4;
            *(uint4*)&B1h[jp * LDB1 + c4] =
                *(const uint4*)(W1h + (size_t)(kc / 2 + jp) * FHID + c4);
            *(uint4*)&B1l[jp * LDB1 + c4] =
                *(const uint4*)(W1l + (size_t)(kc / 2 + jp) * FHID + c4);
        }
        __syncthreads();

        uint32_t ah[2][4], al[2][4];
#pragma unroll
        for (int mi = 0; mi < 2; mi++) {
            int r = m0w + mi * 16 + g;
            ah[mi][0] = Ahp[r * LDAp + tg];            al[mi][0] = Alp[r * LDAp + tg];
            ah[mi][1] = Ahp[(r + 8) * LDAp + tg];      al[mi][1] = Alp[(r + 8) * LDAp + tg];
            ah[mi][2] = Ahp[r * LDAp + tg + 4];        al[mi][2] = Alp[r * LDAp + tg + 4];
            ah[mi][3] = Ahp[(r + 8) * LDAp + tg + 4];  al[mi][3] = Alp[(r + 8) * LDAp + tg + 4];
        }
#pragma unroll
        for (int ni = 0; ni < 8; ni++) {
            int c = n0w1 + ni * 8 + g;
            uint32_t bh[2], bl[2];
            bh[0] = B1h[tg * LDB1 + c];        bl[0] = B1l[tg * LDB1 + c];
            bh[1] = B1h[(tg + 4) * LDB1 + c];  bl[1] = B1l[(tg + 4) * LDB1 + c];
#pragma unroll
            for (int mi = 0; mi < 2; mi++) {
                mma_bf16(acc1[mi][ni], al[mi], bh);
                mma_bf16(acc1[mi][ni], ah[mi], bl);
                mma_bf16(acc1[mi][ni], ah[mi], bh);
            }
        }
    }

    // ---- t = relu(T*ndst + b1), packed bf16 hi/lo into smem ----
    __syncthreads();
#pragma unroll
    for (int mi = 0; mi < 2; mi++) {
        int r0 = m0w + mi * 16 + g;
        int r1 = r0 + 8;
        int gr0 = blockRow + r0, gr1 = blockRow + r1;
        float nd0 = (gr0 < M) ? ndst[gr0] : 0.f;
        float nd1 = (gr1 < M) ? ndst[gr1] : 0.f;
#pragma unroll
        for (int ni = 0; ni < 8; ni++) {
            int col = n0w1 + ni * 8 + 2 * tg;
            int cp  = col >> 1;
            float t00 = fmaxf(fmaf(acc1[mi][ni][0], nd0, bsh[col]), 0.f);
            float t01 = fmaxf(fmaf(acc1[mi][ni][1], nd0, bsh[col + 1]), 0.f);
            float t10 = fmaxf(fmaf(acc1[mi][ni][2], nd1, bsh[col]), 0.f);
            float t11 = fmaxf(fmaf(acc1[mi][ni][3], nd1, bsh[col + 1]), 0.f);
            uint32_t h, l;
            split2(t00, t01, h, l);
            Th[r0 * LDT + cp] = h;  Tl[r0 * LDT + cp] = l;
            split2(t10, t11, h, l);
            Th[r1 * LDT + cp] = h;  Tl[r1 * LDT + cp] = l;
        }
    }

    // ================= stage 2: H2 = t @ W2 * nsrc =================
    float acc2[2][4][4];
#pragma unroll
    for (int mi = 0; mi < 2; mi++)
#pragma unroll
        for (int ni = 0; ni < 4; ni++)
#pragma unroll
            for (int j = 0; j < 4; j++) acc2[mi][ni][j] = 0.f;

    const int n0w2 = warp_n * 32;

    for (int ch = 0; ch < 8; ch++) {
        __syncthreads();
        if (tid < 128) {
            int jp = tid >> 4;
            int c4 = (tid & 15) * 4;
            *(uint4*)&B2h[jp * LDB2 + c4] =
                *(const uint4*)(W2h + (size_t)(ch * 8 + jp) * FOUT + c4);
        } else {
            int t2 = tid - 128;
            int jp = t2 >> 4;
            int c4 = (t2 & 15) * 4;
            *(uint4*)&B2l[jp * LDB2 + c4] =
                *(const uint4*)(W2l + (size_t)(ch * 8 + jp) * FOUT + c4);
        }
        __syncthreads();

        int cb = ch * 8;
        uint32_t ah[2][4], al[2][4];
#pragma unroll
        for (int mi = 0; mi < 2; mi++) {
            int r = m0w + mi * 16 + g;
            ah[mi][0] = Th[r * LDT + cb + tg];            al[mi][0] = Tl[r * LDT + cb + tg];
            ah[mi][1] = Th[(r + 8) * LDT + cb + tg];      al[mi][1] = Tl[(r + 8) * LDT + cb + tg];
            ah[mi][2] = Th[r * LDT + cb + tg + 4];        al[mi][2] = Tl[r * LDT + cb + tg + 4];
            ah[mi][3] = Th[(r + 8) * LDT + cb + tg + 4];  al[mi][3] = Tl[(r + 8) * LDT + cb + tg + 4];
        }
#pragma unroll
        for (int ni = 0; ni < 4; ni++) {
            int c = n0w2 + ni * 8 + g;
            uint32_t bh[2], bl[2];
            bh[0] = B2h[tg * LDB2 + c];        bl[0] = B2l[tg * LDB2 + c];
            bh[1] = B2h[(tg + 4) * LDB2 + c];  bl[1] = B2l[(tg + 4) * LDB2 + c];
#pragma unroll
            for (int mi = 0; mi < 2; mi++) {
                mma_bf16(acc2[mi][ni], al[mi], bh);
                mma_bf16(acc2[mi][ni], ah[mi], bl);
                mma_bf16(acc2[mi][ni], ah[mi], bh);
            }
        }
    }

    // ---- epilogue: H2 = fp16(acc2 * nsrc) ----
#pragma unroll
    for (int mi = 0; mi < 2; mi++) {
        int gr0 = blockRow + m0w + mi * 16 + g;
        int gr1 = gr0 + 8;
        float s0 = (gr0 < M) ? nsrc[gr0] : 0.f;
        float s1 = (gr1 < M) ? nsrc[gr1] : 0.f;
#pragma unroll
        for (int ni = 0; ni < 4; ni++) {
            int col = n0w2 + ni * 8 + 2 * tg;
            if (gr0 < M)
                *(half2*)(H2 + (size_t)gr0 * FOUT + col) =
                    __floats2half2_rn(acc2[mi][ni][0] * s0, acc2[mi][ni][1] * s0);
            if (gr1 < M)
                *(half2*)(H2 + (size_t)gr1 * FOUT + col) =
                    __floats2half2_rn(acc2[mi][ni][2] * s1, acc2[mi][ni][3] * s1);
        }
    }
}

// ---------------- launch 9: final gather SpMM (fp16 H2 rows, fp32 accumulate) ----------------
__global__ __launch_bounds__(256)
void spmm_out(const __half* __restrict__ H2base,
              const int* __restrict__ rowstartAll,
              const int* __restrict__ esrcAll,
              float* __restrict__ outBase,
              const float* __restrict__ ndstAll,
              const float* __restrict__ bias)
{
    constexpr int C = FOUT;          // 64 halves per row (128 bytes)
    const int gidx = blockIdx.y;
    const __half* H = H2base + (size_t)gidx * NNODES * C;
    const int* rowstart = rowstartAll + gidx * (NNODES + 1);
    const int* esrc = esrcAll + (size_t)gidx * NEDGES;
    float* out = outBase + (size_t)gidx * NNODES * C;

    int gt = blockIdx.x * blockDim.x + threadIdx.x;
    int w = gt >> 5;
    int lane = gt & 31;
    int sub = lane >> 4;             // 2 rows per warp
    int lc  = lane & 15;             // uint2 lane: 4 halves
    int row = w * 2 + sub;
    if (row >= NNODES) return;

    int beg = rowstart[row];
    int end = rowstart[row + 1];
    float4 acc = make_float4(0.f, 0.f, 0.f, 0.f);
    int e = beg;
    for (; e + 4 <= end; e += 4) {
        int s0 = __ldg(esrc + e + 0);
        int s1 = __ldg(esrc + e + 1);
        int s2 = __ldg(esrc + e + 2);
        int s3 = __ldg(esrc + e + 3);
        uint2 u0 = __ldg((const uint2*)(H + (size_t)s0 * C) + lc);
        uint2 u1 = __ldg((const uint2*)(H + (size_t)s1 * C) + lc);
        uint2 u2 = __ldg((const uint2*)(H + (size_t)s2 * C) + lc);
        uint2 u3 = __ldg((const uint2*)(H + (size_t)s3 * C) + lc);
#pragma unroll
        for (int j = 0; j < 4; j++) {
            uint2 u = (j == 0) ? u0 : (j == 1) ? u1 : (j == 2) ? u2 : u3;
            float2 fa = __half22float2(*(half2*)&u.x);
            float2 fb = __half22float2(*(half2*)&u.y);
            acc.x += fa.x; acc.y += fa.y; acc.z += fb.x; acc.w += fb.y;
        }
    }
    for (; e < end; e++) {
        int s = __ldg(esrc + e);
        uint2 u = __ldg((const uint2*)(H + (size_t)s * C) + lc);
        float2 fa = __half22float2(*(half2*)&u.x);
        float2 fb = __half22float2(*(half2*)&u.y);
        acc.x += fa.x; acc.y += fa.y; acc.z += fb.x; acc.w += fb.y;
    }
    float nd = ndstAll[gidx * NNODES + row];
    float4 b = ((const float4*)bias)[lc];
    acc.x = fmaf(acc.x, nd, b.x);
    acc.y = fmaf(acc.y, nd, b.y);
    acc.z = fmaf(acc.z, nd, b.z);
    acc.w = fmaf(acc.w, nd, b.w);
    *((float4*)(out + (size_t)row * C) + lc) = acc;
}

// ---------------- launch ----------------
extern "C" void kernel_launch(void* const* d_in, const int* in_sizes, int n_in,
                              void* d_out, int out_size)
{
    float *nsrc, *ndst;
    int *cnt, *outcnt, *rowstart, *esrc, *partial;
    uint32_t *xsh, *xsl, *w1h, *w1l, *w2h, *w2l;
    __half *h2;
    cudaGetSymbolAddress((void**)&xsh,      g_XSh);
    cudaGetSymbolAddress((void**)&xsl,      g_XSl);
    cudaGetSymbolAddress((void**)&h2,       g_H2);
    cudaGetSymbolAddress((void**)&cnt,      g_cnt);
    cudaGetSymbolAddress((void**)&outcnt,   g_outcnt);
    cudaGetSymbolAddress((void**)&rowstart, g_rowstart);
    cudaGetSymbolAddress((void**)&partial,  g_partial);
    cudaGetSymbolAddress((void**)&esrc,     g_esrc);
    cudaGetSymbolAddress((void**)&nsrc,     g_nsrc);
    cudaGetSymbolAddress((void**)&ndst,     g_ndst);
    cudaGetSymbolAddress((void**)&w1h,      g_W1h);
    cudaGetSymbolAddress((void**)&w1l,      g_W1l);
    cudaGetSymbolAddress((void**)&w2h,      g_W2h);
    cudaGetSymbolAddress((void**)&w2l,      g_W2l);

    F3 feats = {{ (const float*)d_in[0], (const float*)d_in[3], (const float*)d_in[6] }};
    I3 srcs  = {{ (const int*)d_in[1],   (const int*)d_in[4],   (const int*)d_in[7] }};
    I3 dsts  = {{ (const int*)d_in[2],   (const int*)d_in[5],   (const int*)d_in[8] }};
    const float* W1 = (const float*)d_in[9];
    const float* b1 = (const float*)d_in[10];
    const float* W2 = (const float*)d_in[11];
    const float* b2 = (const float*)d_in[12];

    static const size_t SMEM_BYTES = SMEM_WORDS * sizeof(uint32_t);
    cudaFuncSetAttribute(fused_gemm, cudaFuncAttributeMaxDynamicSharedMemorySize,
                         (int)SMEM_BYTES);

    dim3 gE8((NEDGES / 8 + 255) / 256, 3);       // 8 edges per thread (hist, fill)
    dim3 gSc(SCAN_NB, 3);
    dim3 gG((NNODES + 127) / 128, 3);
    const int gS1 = (NNODES * 32 + 255) / 256;
    dim3 gS2((NNODES * 16 + 255) / 256, 3);

    zero_pack<<<(3 * NNODES + 255) / 256, 256>>>(cnt, outcnt, W1, W2, w1h, w1l, w2h, w2l);
    hist_all <<<gE8, 256>>>(srcs, dsts, cnt, outcnt);
    scanA    <<<gSc, 1024>>>(cnt, outcnt, rowstart, partial, nsrc, ndst);
    scanC    <<<gSc, 1024>>>(cnt, rowstart, partial);
    fill_all <<<gE8, 256>>>(srcs, dsts, cnt, esrc);

    // XS = gather(nsrc * feat), one graph per launch (L2-resident features)
    for (int g = 0; g < 3; g++)
        spmm_scaled<<<gS1, 256>>>(feats.p[g],
                                  rowstart + g * (NNODES + 1),
                                  esrc + (size_t)g * NEDGES,
                                  xsh + (size_t)g * NNODES * 64,
                                  xsl + (size_t)g * NNODES * 64,
                                  nsrc + g * NNODES);

    // H2 = fp16( relu((XS@W1)*ndst + b1) @ W2 * nsrc )
    fused_gemm<<<gG, 256, SMEM_BYTES>>>(xsh, xsl, w1h, w1l, w2h, w2l, b1, h2, nsrc, ndst);
    // out = gather(H2)*ndst + b2
    spmm_out<<<gS2, 256>>>(h2, rowstart, esrc, (float*)d_out, ndst, b2);
}

// round 16
// speedup vs baseline: 1.6833x; 1.0422x over previous
#include <cuda_runtime.h>
#include <cuda_bf16.h>
#include <cuda_fp16.h>
#include <cstdint>

#define NNODES 100000
#define NEDGES 1600000
#define FIN 128
#define FHID 128
#define FOUT 64
#define SCAN_NB 98   // ceil(NNODES / 1024)

// ---------------- scratch (static device globals; no allocation) ----------------
__device__ __half   g_Xh [(size_t)3 * NNODES * FIN];   // fp16(nsrc * feat)
__device__ uint32_t g_XSh[(size_t)3 * NNODES * 64];    // XS bf16-hi plane (k-pairs packed)
__device__ uint32_t g_XSl[(size_t)3 * NNODES * 64];    // XS bf16-lo plane
__device__ __half   g_H2 [(size_t)3 * NNODES * FOUT];  // layer-2 transformed features (fp16)
__device__ int      g_cnt     [3 * NNODES];            // hist -> cursor
__device__ int      g_outcnt  [3 * NNODES];
__device__ int      g_rowstart[3 * (NNODES + 1)];
__device__ int      g_partial [3 * SCAN_NB];           // per-block scan totals
__device__ int      g_esrc    [3 * NEDGES];
__device__ float    g_nsrc    [3 * NNODES];
__device__ float    g_ndst    [3 * NNODES];
__device__ uint32_t g_W1h[64 * 128], g_W1l[64 * 128];  // W1 packed bf16 hi/lo (k-pairs)
__device__ uint32_t g_W2h[64 * 64],  g_W2l[64 * 64];   // W2 packed bf16 hi/lo

struct F3 { const float* p[3]; };
struct I3 { const int*   p[3]; };

// ---------------- bf16 split helpers ----------------
__device__ __forceinline__ void split2(float f0, float f1, uint32_t& uh, uint32_t& ul) {
    __nv_bfloat16 h0 = __float2bfloat16_rn(f0), h1 = __float2bfloat16_rn(f1);
    float r0 = f0 - __bfloat162float(h0);
    float r1 = f1 - __bfloat162float(h1);
    __nv_bfloat16 l0 = __float2bfloat16_rn(r0), l1 = __float2bfloat16_rn(r1);
    uh = ((uint32_t)(*(uint16_t*)&h1) << 16) | (uint32_t)(*(uint16_t*)&h0);
    ul = ((uint32_t)(*(uint16_t*)&l1) << 16) | (uint32_t)(*(uint16_t*)&l0);
}

__device__ __forceinline__ void mma_bf16(float* d, const uint32_t* a, const uint32_t* b) {
    asm volatile(
        "mma.sync.aligned.m16n8k16.row.col.f32.bf16.bf16.f32 "
        "{%0,%1,%2,%3},{%4,%5,%6,%7},{%8,%9},{%0,%1,%2,%3};"
        : "+f"(d[0]), "+f"(d[1]), "+f"(d[2]), "+f"(d[3])
        : "r"(a[0]), "r"(a[1]), "r"(a[2]), "r"(a[3]), "r"(b[0]), "r"(b[1]));
}

// ---------------- launch 0: zero histograms + pack weights ----------------
__global__ void zero_pack(int* cnt, int* outcnt,
                          const float* __restrict__ W1, const float* __restrict__ W2,
                          uint32_t* w1h, uint32_t* w1l, uint32_t* w2h, uint32_t* w2l) {
    int i = blockIdx.x * blockDim.x + threadIdx.x;
    if (i < 3 * NNODES) { cnt[i] = 0; outcnt[i] = 0; }
    if (i < 64 * 128) {
        int kp = i >> 7, c = i & 127;
        split2(W1[(2 * kp) * FHID + c], W1[(2 * kp + 1) * FHID + c], w1h[i], w1l[i]);
    }
    if (i < 64 * 64) {
        int kp = i >> 6, c = i & 63;
        split2(W2[(2 * kp) * FOUT + c], W2[(2 * kp + 1) * FOUT + c], w2h[i], w2l[i]);
    }
}

// ---------------- launch 1: degree histograms (8 edges/thread, 2x int4 loads) ----------------
__global__ __launch_bounds__(256)
void hist_all(I3 srcs, I3 dsts, int* cnt, int* outcnt) {
    int g = blockIdx.y;
    int i = blockIdx.x * blockDim.x + threadIdx.x;
    if (i < NEDGES / 8) {
        int4 d4a = __ldg((const int4*)dsts.p[g] + 2 * i + 0);
        int4 d4b = __ldg((const int4*)dsts.p[g] + 2 * i + 1);
        int4 s4a = __ldg((const int4*)srcs.p[g] + 2 * i + 0);
        int4 s4b = __ldg((const int4*)srcs.p[g] + 2 * i + 1);
        int* c = cnt + g * NNODES;
        int* o = outcnt + g * NNODES;
        atomicAdd(c + d4a.x, 1);
        atomicAdd(c + d4a.y, 1);
        atomicAdd(c + d4a.z, 1);
        atomicAdd(c + d4a.w, 1);
        atomicAdd(c + d4b.x, 1);
        atomicAdd(c + d4b.y, 1);
        atomicAdd(c + d4b.z, 1);
        atomicAdd(c + d4b.w, 1);
        atomicAdd(o + s4a.x, 1);
        atomicAdd(o + s4a.y, 1);
        atomicAdd(o + s4a.z, 1);
        atomicAdd(o + s4a.w, 1);
        atomicAdd(o + s4b.x, 1);
        atomicAdd(o + s4b.y, 1);
        atomicAdd(o + s4b.z, 1);
        atomicAdd(o + s4b.w, 1);
    }
}

// ---------------- launch 2: scanA — block-local exclusive scan + norms (shuffle) ----------------
__global__ __launch_bounds__(1024)
void scanA(const int* __restrict__ cntAll, const int* __restrict__ outcntAll,
           int* __restrict__ rowstartAll, int* __restrict__ partial,
           float* __restrict__ nsrcAll, float* __restrict__ ndstAll) {
    __shared__ int wsum[32];
    const int g = blockIdx.y;
    const int b = blockIdx.x;
    const int t = threadIdx.x;
    const int lane = t & 31;
    const int wid  = t >> 5;
    const int i = b * 1024 + t;

    int c = 0;
    if (i < NNODES) {
        c = cntAll[g * NNODES + i];
        ndstAll[g * NNODES + i] = rsqrtf(fmaxf((float)c, 1.f));
        nsrcAll[g * NNODES + i] = rsqrtf(fmaxf((float)outcntAll[g * NNODES + i], 1.f));
    }
    int v = c;
#pragma unroll
    for (int off = 1; off < 32; off <<= 1) {
        int n = __shfl_up_sync(0xffffffffu, v, off);
        if (lane >= off) v += n;
    }
    if (lane == 31) wsum[wid] = v;
    __syncthreads();
    if (wid == 0) {
        int w = wsum[lane];
#pragma unroll
        for (int off = 1; off < 32; off <<= 1) {
            int n = __shfl_up_sync(0xffffffffu, w, off);
            if (lane >= off) w += n;
        }
        wsum[lane] = w;
    }
    __syncthreads();
    int base = (wid > 0) ? wsum[wid - 1] : 0;
    int incl = v + base;
    if (i < NNODES)
        rowstartAll[g * (NNODES + 1) + i] = incl - c;
    if (t == 1023)
        partial[g * SCAN_NB + b] = incl;
}

// ---------------- launch 3: scanC — compute block offset + apply ----------------
__global__ __launch_bounds__(1024)
void scanC(int* __restrict__ cntAll, int* __restrict__ rowstartAll,
           const int* __restrict__ partial) {
    __shared__ int red[128];
    const int g = blockIdx.y;
    const int b = blockIdx.x;
    const int t = threadIdx.x;
    const int i = b * 1024 + t;

    if (t < 128)
        red[t] = (t < b) ? partial[g * SCAN_NB + t] : 0;
    __syncthreads();
#pragma unroll
    for (int off = 64; off > 0; off >>= 1) {
        if (t < off) red[t] += red[t + off];
        __syncthreads();
    }
    int offset = red[0];

    if (i < NNODES) {
        int r = rowstartAll[g * (NNODES + 1) + i] + offset;
        rowstartAll[g * (NNODES + 1) + i] = r;
        cntAll[g * NNODES + i] = r;
    }
    if (b == 0 && t == 0)
        rowstartAll[g * (NNODES + 1) + NNODES] = NEDGES;
}

// ---------------- launch 4: fp16 scaled feature copy ----------------
// Xh[g][node][c] = fp16(nsrc[node] * feat[node][c]); 8 elems/thread
__global__ __launch_bounds__(256)
void convert_feat(F3 feats, const float* __restrict__ nsrcAll,
                  __half* __restrict__ XhBase) {
    const int PER_G = NNODES * 16;        // 16 threads per node (8 elems each)
    int g = blockIdx.y;
    int i = blockIdx.x * blockDim.x + threadIdx.x;
    if (i >= PER_G) return;
    int node = i >> 4;
    int q    = i & 15;
    const float* src = feats.p[g] + (size_t)node * FIN + q * 8;
    float s = __ldg(nsrcAll + g * NNODES + node);
    float4 a = __ldg((const float4*)src);
    float4 b = __ldg((const float4*)src + 1);
    half2 h0 = __floats2half2_rn(a.x * s, a.y * s);
    half2 h1 = __floats2half2_rn(a.z * s, a.w * s);
    half2 h2 = __floats2half2_rn(b.x * s, b.y * s);
    half2 h3 = __floats2half2_rn(b.z * s, b.w * s);
    uint4 o;
    o.x = *(uint32_t*)&h0; o.y = *(uint32_t*)&h1;
    o.z = *(uint32_t*)&h2; o.w = *(uint32_t*)&h3;
    *((uint4*)(XhBase + (size_t)g * NNODES * FIN + (size_t)node * FIN + q * 8)) = o;
}

// ---------------- launch 5: CSR fill (8 edges/thread; MLP=8 over ATOMG latency) ----------------
__global__ __launch_bounds__(256)
void fill_all(I3 srcs, I3 dsts, int* cnt, int* __restrict__ esrcAll) {
    int g = blockIdx.y;
    int i = blockIdx.x * blockDim.x + threadIdx.x;
    if (i < NEDGES / 8) {
        int4 d4a = __ldg((const int4*)dsts.p[g] + 2 * i + 0);
        int4 d4b = __ldg((const int4*)dsts.p[g] + 2 * i + 1);
        int4 s4a = __ldg((const int4*)srcs.p[g] + 2 * i + 0);
        int4 s4b = __ldg((const int4*)srcs.p[g] + 2 * i + 1);
        int* c = cnt + g * NNODES;
        int* esrc = esrcAll + (size_t)g * NEDGES;
        int p0 = atomicAdd(c + d4a.x, 1);
        int p1 = atomicAdd(c + d4a.y, 1);
        int p2 = atomicAdd(c + d4a.z, 1);
        int p3 = atomicAdd(c + d4a.w, 1);
        int p4 = atomicAdd(c + d4b.x, 1);
        int p5 = atomicAdd(c + d4b.y, 1);
        int p6 = atomicAdd(c + d4b.z, 1);
        int p7 = atomicAdd(c + d4b.w, 1);
        esrc[p0] = s4a.x;
        esrc[p1] = s4a.y;
        esrc[p2] = s4a.z;
        esrc[p3] = s4a.w;
        esrc[p4] = s4b.x;
        esrc[p5] = s4b.y;
        esrc[p6] = s4b.z;
        esrc[p7] = s4b.w;
    }
}

// ---------------- launches 6-8: scaled gather SpMM (fp16 rows), ONE GRAPH per launch ----------------
// XS[i,:] = sum_{e in row i} Xh[esrc[e],:]   -> packed bf16 hi/lo planes
// 16 lanes per row (uint4 = 256B/row), 2 rows per warp, fp32 accumulate.
__global__ __launch_bounds__(256)
void spmm_scaled(const __half* __restrict__ X,
                 const int* __restrict__ rowstart,
                 const int* __restrict__ esrc,
                 uint32_t* __restrict__ XSh,
                 uint32_t* __restrict__ XSl)
{
    int gt = blockIdx.x * blockDim.x + threadIdx.x;
    int w = gt >> 5;
    int lane = gt & 31;
    int sub = lane >> 4;            // 2 rows per warp
    int lc  = lane & 15;            // uint4 lane: 8 halves (cols lc*8 .. lc*8+7)
    int row = w * 2 + sub;
    if (row >= NNODES) return;

    int beg = rowstart[row];
    int end = rowstart[row + 1];
    float a0 = 0.f, a1 = 0.f, a2 = 0.f, a3 = 0.f;
    float a4 = 0.f, a5 = 0.f, a6 = 0.f, a7 = 0.f;
    int e = beg;
    for (; e + 4 <= end; e += 4) {
        int s0 = __ldg(esrc + e + 0);
        int s1 = __ldg(esrc + e + 1);
        int s2 = __ldg(esrc + e + 2);
        int s3 = __ldg(esrc + e + 3);
        uint4 u0 = __ldg((const uint4*)(X + (size_t)s0 * FIN) + lc);
        uint4 u1 = __ldg((const uint4*)(X + (size_t)s1 * FIN) + lc);
        uint4 u2 = __ldg((const uint4*)(X + (size_t)s2 * FIN) + lc);
        uint4 u3 = __ldg((const uint4*)(X + (size_t)s3 * FIN) + lc);
        float2 f;
        f = __half22float2(*(half2*)&u0.x); a0 += f.x; a1 += f.y;
        f = __half22float2(*(half2*)&u0.y); a2 += f.x; a3 += f.y;
        f = __half22float2(*(half2*)&u0.z); a4 += f.x; a5 += f.y;
        f = __half22float2(*(half2*)&u0.w); a6 += f.x; a7 += f.y;
        f = __half22float2(*(half2*)&u1.x); a0 += f.x; a1 += f.y;
        f = __half22float2(*(half2*)&u1.y); a2 += f.x; a3 += f.y;
        f = __half22float2(*(half2*)&u1.z); a4 += f.x; a5 += f.y;
        f = __half22float2(*(half2*)&u1.w); a6 += f.x; a7 += f.y;
        f = __half22float2(*(half2*)&u2.x); a0 += f.x; a1 += f.y;
        f = __half22float2(*(half2*)&u2.y); a2 += f.x; a3 += f.y;
        f = __half22float2(*(half2*)&u2.z); a4 += f.x; a5 += f.y;
        f = __half22float2(*(half2*)&u2.w); a6 += f.x; a7 += f.y;
        f = __half22float2(*(half2*)&u3.x); a0 += f.x; a1 += f.y;
        f = __half22float2(*(half2*)&u3.y); a2 += f.x; a3 += f.y;
        f = __half22float2(*(half2*)&u3.z); a4 += f.x; a5 += f.y;
        f = __half22float2(*(half2*)&u3.w); a6 += f.x; a7 += f.y;
    }
    for (; e < end; e++) {
        int s = __ldg(esrc + e);
        uint4 u = __ldg((const uint4*)(X + (size_t)s * FIN) + lc);
        float2 f;
        f = __half22float2(*(half2*)&u.x); a0 += f.x; a1 += f.y;
        f = __half22float2(*(half2*)&u.y); a2 += f.x; a3 += f.y;
        f = __half22float2(*(half2*)&u.z); a4 += f.x; a5 += f.y;
        f = __half22float2(*(half2*)&u.w); a6 += f.x; a7 += f.y;
    }
    // pack 8 cols -> 4 k-pair words in each plane
    uint32_t h, l;
    uint4 oh, ol;
    split2(a0, a1, h, l); oh.x = h; ol.x = l;
    split2(a2, a3, h, l); oh.y = h; ol.y = l;
    split2(a4, a5, h, l); oh.z = h; ol.z = l;
    split2(a6, a7, h, l); oh.w = h; ol.w = l;
    *((uint4*)(XSh + (size_t)row * 64) + lc) = oh;
    *((uint4*)(XSl + (size_t)row * 64) + lc) = ol;
}

// ---------------- launch 9: fused dense chain ----------------
// H2 = fp16( relu( (XS @ W1) * ndst + b1 ) @ W2 * nsrc )
#define LDAp 12
#define LDB1 136
#define LDT  68
#define LDB2 72
#define OFF_AH 0
#define OFF_AL (OFF_AH + 128 * LDAp)
#define OFF_B1H (OFF_AL + 128 * LDAp)
#define OFF_B1L (OFF_B1H + 8 * LDB1)
#define OFF_TH (OFF_B1L + 8 * LDB1)
#define OFF_TL (OFF_TH + 128 * LDT)
#define OFF_B2H (OFF_TL + 128 * LDT)
#define OFF_B2L (OFF_B2H + 8 * LDB2)
#define OFF_BSH (OFF_B2L + 8 * LDB2)
#define SMEM_WORDS (OFF_BSH + 128)

__global__ __launch_bounds__(256)
void fused_gemm(const uint32_t* __restrict__ XShBase,
                const uint32_t* __restrict__ XSlBase,
                const uint32_t* __restrict__ W1h, const uint32_t* __restrict__ W1l,
                const uint32_t* __restrict__ W2h, const uint32_t* __restrict__ W2l,
                const float* __restrict__ b1,
                __half* __restrict__ H2base,
                const float* __restrict__ nsrcAll,
                const float* __restrict__ ndstAll)
{
    extern __shared__ uint32_t sm[];
    uint32_t* Ahp = sm + OFF_AH;    // [128][LDAp]
    uint32_t* Alp = sm + OFF_AL;
    uint32_t* B1h = sm + OFF_B1H;   // [8][LDB1]
    uint32_t* B1l = sm + OFF_B1L;
    uint32_t* Th  = sm + OFF_TH;    // [128][LDT]
    uint32_t* Tl  = sm + OFF_TL;
    uint32_t* B2h = sm + OFF_B2H;   // [8][LDB2]
    uint32_t* B2l = sm + OFF_B2L;
    float*    bsh = (float*)(sm + OFF_BSH);

    const int gidx = blockIdx.y;
    const uint32_t* XSh = XShBase + (size_t)gidx * NNODES * 64;
    const uint32_t* XSl = XSlBase + (size_t)gidx * NNODES * 64;
    __half*      H2   = H2base + (size_t)gidx * NNODES * FOUT;
    const float* nsrc = nsrcAll + gidx * NNODES;
    const float* ndst = ndstAll + gidx * NNODES;

    const int tid  = threadIdx.x;
    const int warp = tid >> 5;
    const int lane = tid & 31;
    const int warp_m = warp & 3;
    const int warp_n = warp >> 2;
    const int m0w = warp_m * 32;
    const int g  = lane >> 2;
    const int tg = lane & 3;
    const int blockRow = blockIdx.x * 128;
    const int M = NNODES;

    if (tid < FHID) bsh[tid] = b1[tid];

    // ================= stage 1: T = XS @ W1 (3-term bf16) =================
    float acc1[2][8][4];
#pragma unroll
    for (int mi = 0; mi < 2; mi++)
#pragma unroll
        for (int ni = 0; ni < 8; ni++)
#pragma unroll
            for (int j = 0; j < 4; j++) acc1[mi][ni][j] = 0.f;

    const int n0w1 = warp_n * 64;
    const int arow = tid >> 1;          // 0..127
    const int aq   = (tid & 1) * 4;     // uint4 column within 8-wide chunk

    for (int kc = 0; kc < FIN; kc += 16) {
        __syncthreads();
        {
            int grow = blockRow + arow;
            uint4 vh = make_uint4(0u, 0u, 0u, 0u);
            uint4 vl = make_uint4(0u, 0u, 0u, 0u);
            if (grow < M) {
                vh = *(const uint4*)(XSh + (size_t)grow * 64 + kc / 2 + aq);
                vl = *(const uint4*)(XSl + (size_t)grow * 64 + kc / 2 + aq);
            }
            *(uint4*)&Ahp[arow * LDAp + aq] = vh;
            *(uint4*)&Alp[arow * LDAp + aq] = vl;
        }
        {
            int jp = tid >> 5;
            int c4 = (tid & 31) * 4;
            *(uint4*)&B1h[jp * LDB1 + c4] =
                *(const uint4*)(W1h + (size_t)(kc / 2 + jp) * FHID + c4);
            *(uint4*)&B1l[jp * LDB1 + c4] =
                *(const uint4*)(W1l + (size_t)(kc / 2 + jp) * FHID + c4);
        }
        __syncthreads();

        uint32_t ah[2][4], al[2][4];
#pragma unroll
        for (int mi = 0; mi < 2; mi++) {
            int r = m0w + mi * 16 + g;
            ah[mi][0] = Ahp[r * LDAp + tg];            al[mi][0] = Alp[r * LDAp + tg];
            ah[mi][1] = Ahp[(r + 8) * LDAp + tg];      al[mi][1] = Alp[(r + 8) * LDAp + tg];
            ah[mi][2] = Ahp[r * LDAp + tg + 4];        al[mi][2] = Alp[r * LDAp + tg + 4];
            ah[mi][3] = Ahp[(r + 8) * LDAp + tg + 4];  al[mi][3] = Alp[(r + 8) * LDAp + tg + 4];
        }
#pragma unroll
        for (int ni = 0; ni < 8; ni++) {
            int c = n0w1 + ni * 8 + g;
            uint32_t bh[2], bl[2];
            bh[0] = B1h[tg * LDB1 + c];        bl[0] = B1l[tg * LDB1 + c];
            bh[1] = B1h[(tg + 4) * LDB1 + c];  bl[1] = B1l[(tg + 4) * LDB1 + c];
#pragma unroll
            for (int mi = 0; mi < 2; mi++) {
                mma_bf16(acc1[mi][ni], al[mi], bh);
                mma_bf16(acc1[mi][ni], ah[mi], bl);
                mma_bf16(acc1[mi][ni], ah[mi], bh);
            }
        }
    }

    // ---- t = relu(T*ndst + b1), packed bf16 hi/lo into smem ----
    __syncthreads();
#pragma unroll
    for (int mi = 0; mi < 2; mi++) {
        int r0 = m0w + mi * 16 + g;
        int r1 = r0 + 8;
        int gr0 = blockRow + r0, gr1 = blockRow + r1;
        float nd0 = (gr0 < M) ? ndst[gr0] : 0.f;
        float nd1 = (gr1 < M) ? ndst[gr1] : 0.f;
#pragma unroll
        for (int ni = 0; ni < 8; ni++) {
            int col = n0w1 + ni * 8 + 2 * tg;
            int cp  = col >> 1;
            float t00 = fmaxf(fmaf(acc1[mi][ni][0], nd0, bsh[col]), 0.f);
            float t01 = fmaxf(fmaf(acc1[mi][ni][1], nd0, bsh[col + 1]), 0.f);
            float t10 = fmaxf(fmaf(acc1[mi][ni][2], nd1, bsh[col]), 0.f);
            float t11 = fmaxf(fmaf(acc1[mi][ni][3], nd1, bsh[col + 1]), 0.f);
            uint32_t h, l;
            split2(t00, t01, h, l);
            Th[r0 * LDT + cp] = h;  Tl[r0 * LDT + cp] = l;
            split2(t10, t11, h, l);
            Th[r1 * LDT + cp] = h;  Tl[r1 * LDT + cp] = l;
        }
    }

    // ================= stage 2: H2 = t @ W2 * nsrc =================
    float acc2[2][4][4];
#pragma unroll
    for (int mi = 0; mi < 2; mi++)
#pragma unroll
        for (int ni = 0; ni < 4; ni++)
#pragma unroll
            for (int j = 0; j < 4; j++) acc2[mi][ni][j] = 0.f;

    const int n0w2 = warp_n * 32;

    for (int ch = 0; ch < 8; ch++) {
        __syncthreads();
        if (tid < 128) {
            int jp = tid >> 4;
            int c4 = (tid & 15) * 4;
            *(uint4*)&B2h[jp * LDB2 + c4] =
                *(const uint4*)(W2h + (size_t)(ch * 8 + jp) * FOUT + c4);
        } else {
            int t2 = tid - 128;
            int jp = t2 >> 4;
            int c4 = (t2 & 15) * 4;
            *(uint4*)&B2l[jp * LDB2 + c4] =
                *(const uint4*)(W2l + (size_t)(ch * 8 + jp) * FOUT + c4);
        }
        __syncthreads();

        int cb = ch * 8;
        uint32_t ah[2][4], al[2][4];
#pragma unroll
        for (int mi = 0; mi < 2; mi++) {
            int r = m0w + mi * 16 + g;
            ah[mi][0] = Th[r * LDT + cb + tg];            al[mi][0] = Tl[r * LDT + cb + tg];
            ah[mi][1] = Th[(r + 8) * LDT + cb + tg];      al[mi][1] = Tl[(r + 8) * LDT + cb + tg];
            ah[mi][2] = Th[r * LDT + cb + tg + 4];        al[mi][2] = Tl[r * LDT + cb + tg + 4];
            ah[mi][3] = Th[(r + 8) * LDT + cb + tg + 4];  al[mi][3] = Tl[(r + 8) * LDT + cb + tg + 4];
        }
#pragma unroll
        for (int ni = 0; ni < 4; ni++) {
            int c = n0w2 + ni * 8 + g;
            uint32_t bh[2], bl[2];
            bh[0] = B2h[tg * LDB2 + c];        bl[0] = B2l[tg * LDB2 + c];
            bh[1] = B2h[(tg + 4) * LDB2 + c];  bl[1] = B2l[(tg + 4) * LDB2 + c];
#pragma unroll
            for (int mi = 0; mi < 2; mi++) {
                mma_bf16(acc2[mi][ni], al[mi], bh);
                mma_bf16(acc2[mi][ni], ah[mi], bl);
                mma_bf16(acc2[mi][ni], ah[mi], bh);
            }
        }
    }

    // ---- epilogue: H2 = fp16(acc2 * nsrc) ----
#pragma unroll
    for (int mi = 0; mi < 2; mi++) {
        int gr0 = blockRow + m0w + mi * 16 + g;
        int gr1 = gr0 + 8;
        float s0 = (gr0 < M) ? nsrc[gr0] : 0.f;
        float s1 = (gr1 < M) ? nsrc[gr1] : 0.f;
#pragma unroll
        for (int ni = 0; ni < 4; ni++) {
            int col = n0w2 + ni * 8 + 2 * tg;
            if (gr0 < M)
                *(half2*)(H2 + (size_t)gr0 * FOUT + col) =
                    __floats2half2_rn(acc2[mi][ni][0] * s0, acc2[mi][ni][1] * s0);
            if (gr1 < M)
                *(half2*)(H2 + (size_t)gr1 * FOUT + col) =
                    __floats2half2_rn(acc2[mi][ni][2] * s1, acc2[mi][ni][3] * s1);
        }
    }
}

// ---------------- launch 10: final gather SpMM (fp16 H2 rows, fp32 accumulate) ----------------
__global__ __launch_bounds__(256)
void spmm_out(const __half* __restrict__ H2base,
              const int* __restrict__ rowstartAll,
              const int* __restrict__ esrcAll,
              float* __restrict__ outBase,
              const float* __restrict__ ndstAll,
              const float* __restrict__ bias)
{
    constexpr int C = FOUT;          // 64 halves per row (128 bytes)
    const int gidx = blockIdx.y;
    const __half* H = H2base + (size_t)gidx * NNODES * C;
    const int* rowstart = rowstartAll + gidx * (NNODES + 1);
    const int* esrc = esrcAll + (size_t)gidx * NEDGES;
    float* out = outBase + (size_t)gidx * NNODES * C;

    int gt = blockIdx.x * blockDim.x + threadIdx.x;
    int w = gt >> 5;
    int lane = gt & 31;
    int sub = lane >> 4;             // 2 rows per warp
    int lc  = lane & 15;             // uint2 lane: 4 halves
    int row = w * 2 + sub;
    if (row >= NNODES) return;

    int beg = rowstart[row];
    int end = rowstart[row + 1];
    float4 acc = make_float4(0.f, 0.f, 0.f, 0.f);
    int e = beg;
    for (; e + 4 <= end; e += 4) {
        int s0 = __ldg(esrc + e + 0);
        int s1 = __ldg(esrc + e + 1);
        int s2 = __ldg(esrc + e + 2);
        int s3 = __ldg(esrc + e + 3);
        uint2 u0 = __ldg((const uint2*)(H + (size_t)s0 * C) + lc);
        uint2 u1 = __ldg((const uint2*)(H + (size_t)s1 * C) + lc);
        uint2 u2 = __ldg((const uint2*)(H + (size_t)s2 * C) + lc);
        uint2 u3 = __ldg((const uint2*)(H + (size_t)s3 * C) + lc);
        float2 f;
        f = __half22float2(*(half2*)&u0.x); acc.x += f.x; acc.y += f.y;
        f = __half22float2(*(half2*)&u0.y); acc.z += f.x; acc.w += f.y;
        f = __half22float2(*(half2*)&u1.x); acc.x += f.x; acc.y += f.y;
        f = __half22float2(*(half2*)&u1.y); acc.z += f.x; acc.w += f.y;
        f = __half22float2(*(half2*)&u2.x); acc.x += f.x; acc.y += f.y;
        f = __half22float2(*(half2*)&u2.y); acc.z += f.x; acc.w += f.y;
        f = __half22float2(*(half2*)&u3.x); acc.x += f.x; acc.y += f.y;
        f = __half22float2(*(half2*)&u3.y); acc.z += f.x; acc.w += f.y;
    }
    for (; e < end; e++) {
        int s = __ldg(esrc + e);
        uint2 u = __ldg((const uint2*)(H + (size_t)s * C) + lc);
        float2 fa = __half22float2(*(half2*)&u.x);
        float2 fb = __half22float2(*(half2*)&u.y);
        acc.x += fa.x; acc.y += fa.y; acc.z += fb.x; acc.w += fb.y;
    }
    float nd = ndstAll[gidx * NNODES + row];
    float4 b = ((const float4*)bias)[lc];
    acc.x = fmaf(acc.x, nd, b.x);
    acc.y = fmaf(acc.y, nd, b.y);
    acc.z = fmaf(acc.z, nd, b.z);
    acc.w = fmaf(acc.w, nd, b.w);
    *((float4*)(out + (size_t)row * C) + lc) = acc;
}

// ---------------- launch ----------------
extern "C" void kernel_launch(void* const* d_in, const int* in_sizes, int n_in,
                              void* d_out, int out_size)
{
    float *nsrc, *ndst;
    int *cnt, *outcnt, *rowstart, *esrc, *partial;
    uint32_t *xsh, *xsl, *w1h, *w1l, *w2h, *w2l;
    __half *xh, *h2;
    cudaGetSymbolAddress((void**)&xh,       g_Xh);
    cudaGetSymbolAddress((void**)&xsh,      g_XSh);
    cudaGetSymbolAddress((void**)&xsl,      g_XSl);
    cudaGetSymbolAddress((void**)&h2,       g_H2);
    cudaGetSymbolAddress((void**)&cnt,      g_cnt);
    cudaGetSymbolAddress((void**)&outcnt,   g_outcnt);
    cudaGetSymbolAddress((void**)&rowstart, g_rowstart);
    cudaGetSymbolAddress((void**)&partial,  g_partial);
    cudaGetSymbolAddress((void**)&esrc,     g_esrc);
    cudaGetSymbolAddress((void**)&nsrc,     g_nsrc);
    cudaGetSymbolAddress((void**)&ndst,     g_ndst);
    cudaGetSymbolAddress((void**)&w1h,      g_W1h);
    cudaGetSymbolAddress((void**)&w1l,      g_W1l);
    cudaGetSymbolAddress((void**)&w2h,      g_W2h);
    cudaGetSymbolAddress((void**)&w2l,      g_W2l);

    F3 feats = {{ (const float*)d_in[0], (const float*)d_in[3], (const float*)d_in[6] }};
    I3 srcs  = {{ (const int*)d_in[1],   (const int*)d_in[4],   (const int*)d_in[7] }};
    I3 dsts  = {{ (const int*)d_in[2],   (const int*)d_in[5],   (const int*)d_in[8] }};
    const float* W1 = (const float*)d_in[9];
    const float* b1 = (const float*)d_in[10];
    const float* W2 = (const float*)d_in[11];
    const float* b2 = (const float*)d_in[12];

    static const size_t SMEM_BYTES = SMEM_WORDS * sizeof(uint32_t);
    cudaFuncSetAttribute(fused_gemm, cudaFuncAttributeMaxDynamicSharedMemorySize,
                         (int)SMEM_BYTES);

    dim3 gE8((NEDGES / 8 + 255) / 256, 3);       // 8 edges per thread (hist, fill)
    dim3 gSc(SCAN_NB, 3);
    dim3 gCv((NNODES * 16 + 255) / 256, 3);      // convert: 16 threads/node
    dim3 gG((NNODES + 127) / 128, 3);
    const int gS1 = (NNODES * 16 + 255) / 256;   // 2 rows/warp
    dim3 gS2((NNODES * 16 + 255) / 256, 3);

    zero_pack<<<(3 * NNODES + 255) / 256, 256>>>(cnt, outcnt, W1, W2, w1h, w1l, w2h, w2l);
    hist_all <<<gE8, 256>>>(srcs, dsts, cnt, outcnt);
    scanA    <<<gSc, 1024>>>(cnt, outcnt, rowstart, partial, nsrc, ndst);
    scanC    <<<gSc, 1024>>>(cnt, rowstart, partial);
    convert_feat<<<gCv, 256>>>(feats, nsrc, xh);
    fill_all <<<gE8, 256>>>(srcs, dsts, cnt, esrc);

    // XS = gather(Xh), one graph per launch (fp16 features: 77MB total, L2-resident)
    for (int g = 0; g < 3; g++)
        spmm_scaled<<<gS1, 256>>>(xh + (size_t)g * NNODES * FIN,
                                  rowstart + g * (NNODES + 1),
                                  esrc + (size_t)g * NEDGES,
                                  xsh + (size_t)g * NNODES * 64,
                                  xsl + (size_t)g * NNODES * 64);

    // H2 = fp16( relu((XS@W1)*ndst + b1) @ W2 * nsrc )
    fused_gemm<<<gG, 256, SMEM_BYTES>>>(xsh, xsl, w1h, w1l, w2h, w2l, b1, h2, nsrc, ndst);
    // out = gather(H2)*ndst + b2
    spmm_out<<<gS2, 256>>>(h2, rowstart, esrc, (float*)d_out, ndst, b2);
}

// round 17
// speedup vs baseline: 1.7027x; 1.0115x over previous
#include <cuda_runtime.h>
#include <cuda_bf16.h>
#include <cuda_fp16.h>
#include <cstdint>

#define NNODES 100000
#define NEDGES 1600000
#define FIN 128
#define FHID 128
#define FOUT 64
#define SCAN_NB 98   // ceil(NNODES / 1024)

// ---------------- scratch (static device globals; no allocation) ----------------
__device__ __half   g_Xh [(size_t)3 * NNODES * FIN];   // fp16(nsrc * feat)
__device__ uint32_t g_XSh[(size_t)3 * NNODES * 64];    // XS bf16-hi plane (k-pairs packed)
__device__ uint32_t g_XSl[(size_t)3 * NNODES * 64];    // XS bf16-lo plane
__device__ __half   g_H2 [(size_t)3 * NNODES * FOUT];  // layer-2 transformed features (fp16)
__device__ int      g_cnt     [3 * NNODES];            // in-deg hist -> cursor
__device__ int      g_outcnt  [3 * NNODES];            // out-deg hist (filled by fill_all)
__device__ int      g_rowstart[3 * (NNODES + 1)];
__device__ int      g_partial [3 * SCAN_NB];           // per-block scan totals
__device__ int      g_esrc    [3 * NEDGES];
__device__ float    g_nsrc    [3 * NNODES];
__device__ float    g_ndst    [3 * NNODES];
__device__ uint32_t g_W1h[64 * 128], g_W1l[64 * 128];  // W1 packed bf16 hi/lo (k-pairs)
__device__ uint32_t g_W2h[64 * 64],  g_W2l[64 * 64];   // W2 packed bf16 hi/lo

struct F3 { const float* p[3]; };
struct I3 { const int*   p[3]; };

// ---------------- bf16 split helpers ----------------
__device__ __forceinline__ void split2(float f0, float f1, uint32_t& uh, uint32_t& ul) {
    __nv_bfloat16 h0 = __float2bfloat16_rn(f0), h1 = __float2bfloat16_rn(f1);
    float r0 = f0 - __bfloat162float(h0);
    float r1 = f1 - __bfloat162float(h1);
    __nv_bfloat16 l0 = __float2bfloat16_rn(r0), l1 = __float2bfloat16_rn(r1);
    uh = ((uint32_t)(*(uint16_t*)&h1) << 16) | (uint32_t)(*(uint16_t*)&h0);
    ul = ((uint32_t)(*(uint16_t*)&l1) << 16) | (uint32_t)(*(uint16_t*)&l0);
}

__device__ __forceinline__ void mma_bf16(float* d, const uint32_t* a, const uint32_t* b) {
    asm volatile(
        "mma.sync.aligned.m16n8k16.row.col.f32.bf16.bf16.f32 "
        "{%0,%1,%2,%3},{%4,%5,%6,%7},{%8,%9},{%0,%1,%2,%3};"
        : "+f"(d[0]), "+f"(d[1]), "+f"(d[2]), "+f"(d[3])
        : "r"(a[0]), "r"(a[1]), "r"(a[2]), "r"(a[3]), "r"(b[0]), "r"(b[1]));
}

// ---------------- launch 0: zero histograms + pack weights ----------------
__global__ void zero_pack(int* cnt, int* outcnt,
                          const float* __restrict__ W1, const float* __restrict__ W2,
                          uint32_t* w1h, uint32_t* w1l, uint32_t* w2h, uint32_t* w2l) {
    int i = blockIdx.x * blockDim.x + threadIdx.x;
    if (i < 3 * NNODES) { cnt[i] = 0; outcnt[i] = 0; }
    if (i < 64 * 128) {
        int kp = i >> 7, c = i & 127;
        split2(W1[(2 * kp) * FHID + c], W1[(2 * kp + 1) * FHID + c], w1h[i], w1l[i]);
    }
    if (i < 64 * 64) {
        int kp = i >> 6, c = i & 63;
        split2(W2[(2 * kp) * FOUT + c], W2[(2 * kp + 1) * FOUT + c], w2h[i], w2l[i]);
    }
}

// ---------------- launch 1: in-degree histogram only (8 edges/thread) ----------------
__global__ __launch_bounds__(256)
void hist_all(I3 dsts, int* cnt) {
    int g = blockIdx.y;
    int i = blockIdx.x * blockDim.x + threadIdx.x;
    if (i < NEDGES / 8) {
        int4 d4a = __ldg((const int4*)dsts.p[g] + 2 * i + 0);
        int4 d4b = __ldg((const int4*)dsts.p[g] + 2 * i + 1);
        int* c = cnt + g * NNODES;
        atomicAdd(c + d4a.x, 1);
        atomicAdd(c + d4a.y, 1);
        atomicAdd(c + d4a.z, 1);
        atomicAdd(c + d4a.w, 1);
        atomicAdd(c + d4b.x, 1);
        atomicAdd(c + d4b.y, 1);
        atomicAdd(c + d4b.z, 1);
        atomicAdd(c + d4b.w, 1);
    }
}

// ---------------- launch 2: scanA — block-local exclusive scan + ndst (shuffle) ----------------
__global__ __launch_bounds__(1024)
void scanA(const int* __restrict__ cntAll,
           int* __restrict__ rowstartAll, int* __restrict__ partial,
           float* __restrict__ ndstAll) {
    __shared__ int wsum[32];
    const int g = blockIdx.y;
    const int b = blockIdx.x;
    const int t = threadIdx.x;
    const int lane = t & 31;
    const int wid  = t >> 5;
    const int i = b * 1024 + t;

    int c = 0;
    if (i < NNODES) {
        c = cntAll[g * NNODES + i];
        ndstAll[g * NNODES + i] = rsqrtf(fmaxf((float)c, 1.f));
    }
    int v = c;
#pragma unroll
    for (int off = 1; off < 32; off <<= 1) {
        int n = __shfl_up_sync(0xffffffffu, v, off);
        if (lane >= off) v += n;
    }
    if (lane == 31) wsum[wid] = v;
    __syncthreads();
    if (wid == 0) {
        int w = wsum[lane];
#pragma unroll
        for (int off = 1; off < 32; off <<= 1) {
            int n = __shfl_up_sync(0xffffffffu, w, off);
            if (lane >= off) w += n;
        }
        wsum[lane] = w;
    }
    __syncthreads();
    int base = (wid > 0) ? wsum[wid - 1] : 0;
    int incl = v + base;
    if (i < NNODES)
        rowstartAll[g * (NNODES + 1) + i] = incl - c;
    if (t == 1023)
        partial[g * SCAN_NB + b] = incl;
}

// ---------------- launch 3: scanC — compute block offset + apply ----------------
__global__ __launch_bounds__(1024)
void scanC(int* __restrict__ cntAll, int* __restrict__ rowstartAll,
           const int* __restrict__ partial) {
    __shared__ int red[128];
    const int g = blockIdx.y;
    const int b = blockIdx.x;
    const int t = threadIdx.x;
    const int i = b * 1024 + t;

    if (t < 128)
        red[t] = (t < b) ? partial[g * SCAN_NB + t] : 0;
    __syncthreads();
#pragma unroll
    for (int off = 64; off > 0; off >>= 1) {
        if (t < off) red[t] += red[t + off];
        __syncthreads();
    }
    int offset = red[0];

    if (i < NNODES) {
        int r = rowstartAll[g * (NNODES + 1) + i] + offset;
        rowstartAll[g * (NNODES + 1) + i] = r;
        cntAll[g * NNODES + i] = r;
    }
    if (b == 0 && t == 0)
        rowstartAll[g * (NNODES + 1) + NNODES] = NEDGES;
}

// ---------------- launch 4: CSR fill + out-degree histogram (8 edges/thread) ----------------
__global__ __launch_bounds__(256)
void fill_all(I3 srcs, I3 dsts, int* cnt, int* outcnt, int* __restrict__ esrcAll) {
    int g = blockIdx.y;
    int i = blockIdx.x * blockDim.x + threadIdx.x;
    if (i < NEDGES / 8) {
        int4 d4a = __ldg((const int4*)dsts.p[g] + 2 * i + 0);
        int4 d4b = __ldg((const int4*)dsts.p[g] + 2 * i + 1);
        int4 s4a = __ldg((const int4*)srcs.p[g] + 2 * i + 0);
        int4 s4b = __ldg((const int4*)srcs.p[g] + 2 * i + 1);
        int* c = cnt + g * NNODES;
        int* o = outcnt + g * NNODES;
        int* esrc = esrcAll + (size_t)g * NEDGES;
        // out-degree REDs (fire-and-forget; fill issue slots idle on ATOMG latency)
        atomicAdd(o + s4a.x, 1);
        atomicAdd(o + s4a.y, 1);
        atomicAdd(o + s4a.z, 1);
        atomicAdd(o + s4a.w, 1);
        atomicAdd(o + s4b.x, 1);
        atomicAdd(o + s4b.y, 1);
        atomicAdd(o + s4b.z, 1);
        atomicAdd(o + s4b.w, 1);
        int p0 = atomicAdd(c + d4a.x, 1);
        int p1 = atomicAdd(c + d4a.y, 1);
        int p2 = atomicAdd(c + d4a.z, 1);
        int p3 = atomicAdd(c + d4a.w, 1);
        int p4 = atomicAdd(c + d4b.x, 1);
        int p5 = atomicAdd(c + d4b.y, 1);
        int p6 = atomicAdd(c + d4b.z, 1);
        int p7 = atomicAdd(c + d4b.w, 1);
        esrc[p0] = s4a.x;
        esrc[p1] = s4a.y;
        esrc[p2] = s4a.z;
        esrc[p3] = s4a.w;
        esrc[p4] = s4b.x;
        esrc[p5] = s4b.y;
        esrc[p6] = s4b.z;
        esrc[p7] = s4b.w;
    }
}

// ---------------- launch 5: fp16 scaled feature copy (also writes nsrc) ----------------
// Xh[g][node][c] = fp16(rsqrt(max(outdeg,1)) * feat[node][c]); 8 elems/thread
__global__ __launch_bounds__(256)
void convert_feat(F3 feats, const int* __restrict__ outcntAll,
                  float* __restrict__ nsrcAll, __half* __restrict__ XhBase) {
    const int PER_G = NNODES * 16;        // 16 threads per node (8 elems each)
    int g = blockIdx.y;
    int i = blockIdx.x * blockDim.x + threadIdx.x;
    if (i >= PER_G) return;
    int node = i >> 4;
    int q    = i & 15;
    float s = rsqrtf(fmaxf((float)__ldg(outcntAll + g * NNODES + node), 1.f));
    if (q == 0) nsrcAll[g * NNODES + node] = s;   // for fused_gemm epilogue
    const float* src = feats.p[g] + (size_t)node * FIN + q * 8;
    float4 a = __ldg((const float4*)src);
    float4 b = __ldg((const float4*)src + 1);
    half2 h0 = __floats2half2_rn(a.x * s, a.y * s);
    half2 h1 = __floats2half2_rn(a.z * s, a.w * s);
    half2 h2 = __floats2half2_rn(b.x * s, b.y * s);
    half2 h3 = __floats2half2_rn(b.z * s, b.w * s);
    uint4 o;
    o.x = *(uint32_t*)&h0; o.y = *(uint32_t*)&h1;
    o.z = *(uint32_t*)&h2; o.w = *(uint32_t*)&h3;
    *((uint4*)(XhBase + (size_t)g * NNODES * FIN + (size_t)node * FIN + q * 8)) = o;
}

// ---------------- launches 6-8: scaled gather SpMM (fp16 rows), ONE GRAPH per launch ----------------
// XS[i,:] = sum_{e in row i} Xh[esrc[e],:]   -> packed bf16 hi/lo planes
__global__ __launch_bounds__(256)
void spmm_scaled(const __half* __restrict__ X,
                 const int* __restrict__ rowstart,
                 const int* __restrict__ esrc,
                 uint32_t* __restrict__ XSh,
                 uint32_t* __restrict__ XSl)
{
    int gt = blockIdx.x * blockDim.x + threadIdx.x;
    int w = gt >> 5;
    int lane = gt & 31;
    int sub = lane >> 4;            // 2 rows per warp
    int lc  = lane & 15;            // uint4 lane: 8 halves
    int row = w * 2 + sub;
    if (row >= NNODES) return;

    int beg = rowstart[row];
    int end = rowstart[row + 1];
    float a0 = 0.f, a1 = 0.f, a2 = 0.f, a3 = 0.f;
    float a4 = 0.f, a5 = 0.f, a6 = 0.f, a7 = 0.f;
    int e = beg;
    for (; e + 4 <= end; e += 4) {
        int s0 = __ldg(esrc + e + 0);
        int s1 = __ldg(esrc + e + 1);
        int s2 = __ldg(esrc + e + 2);
        int s3 = __ldg(esrc + e + 3);
        uint4 u0 = __ldg((const uint4*)(X + (size_t)s0 * FIN) + lc);
        uint4 u1 = __ldg((const uint4*)(X + (size_t)s1 * FIN) + lc);
        uint4 u2 = __ldg((const uint4*)(X + (size_t)s2 * FIN) + lc);
        uint4 u3 = __ldg((const uint4*)(X + (size_t)s3 * FIN) + lc);
        float2 f;
        f = __half22float2(*(half2*)&u0.x); a0 += f.x; a1 += f.y;
        f = __half22float2(*(half2*)&u0.y); a2 += f.x; a3 += f.y;
        f = __half22float2(*(half2*)&u0.z); a4 += f.x; a5 += f.y;
        f = __half22float2(*(half2*)&u0.w); a6 += f.x; a7 += f.y;
        f = __half22float2(*(half2*)&u1.x); a0 += f.x; a1 += f.y;
        f = __half22float2(*(half2*)&u1.y); a2 += f.x; a3 += f.y;
        f = __half22float2(*(half2*)&u1.z); a4 += f.x; a5 += f.y;
        f = __half22float2(*(half2*)&u1.w); a6 += f.x; a7 += f.y;
        f = __half22float2(*(half2*)&u2.x); a0 += f.x; a1 += f.y;
        f = __half22float2(*(half2*)&u2.y); a2 += f.x; a3 += f.y;
        f = __half22float2(*(half2*)&u2.z); a4 += f.x; a5 += f.y;
        f = __half22float2(*(half2*)&u2.w); a6 += f.x; a7 += f.y;
        f = __half22float2(*(half2*)&u3.x); a0 += f.x; a1 += f.y;
        f = __half22float2(*(half2*)&u3.y); a2 += f.x; a3 += f.y;
        f = __half22float2(*(half2*)&u3.z); a4 += f.x; a5 += f.y;
        f = __half22float2(*(half2*)&u3.w); a6 += f.x; a7 += f.y;
    }
    for (; e < end; e++) {
        int s = __ldg(esrc + e);
        uint4 u = __ldg((const uint4*)(X + (size_t)s * FIN) + lc);
        float2 f;
        f = __half22float2(*(half2*)&u.x); a0 += f.x; a1 += f.y;
        f = __half22float2(*(half2*)&u.y); a2 += f.x; a3 += f.y;
        f = __half22float2(*(half2*)&u.z); a4 += f.x; a5 += f.y;
        f = __half22float2(*(half2*)&u.w); a6 += f.x; a7 += f.y;
    }
    uint32_t h, l;
    uint4 oh, ol;
    split2(a0, a1, h, l); oh.x = h; ol.x = l;
    split2(a2, a3, h, l); oh.y = h; ol.y = l;
    split2(a4, a5, h, l); oh.z = h; ol.z = l;
    split2(a6, a7, h, l); oh.w = h; ol.w = l;
    *((uint4*)(XSh + (size_t)row * 64) + lc) = oh;
    *((uint4*)(XSl + (size_t)row * 64) + lc) = ol;
}

// ---------------- launch 9: fused dense chain ----------------
// H2 = fp16( relu( (XS @ W1) * ndst + b1 ) @ W2 * nsrc )
#define LDAp 12
#define LDB1 136
#define LDT  68
#define LDB2 72
#define OFF_AH 0
#define OFF_AL (OFF_AH + 128 * LDAp)
#define OFF_B1H (OFF_AL + 128 * LDAp)
#define OFF_B1L (OFF_B1H + 8 * LDB1)
#define OFF_TH (OFF_B1L + 8 * LDB1)
#define OFF_TL (OFF_TH + 128 * LDT)
#define OFF_B2H (OFF_TL + 128 * LDT)
#define OFF_B2L (OFF_B2H + 8 * LDB2)
#define OFF_BSH (OFF_B2L + 8 * LDB2)
#define SMEM_WORDS (OFF_BSH + 128)

__global__ __launch_bounds__(256)
void fused_gemm(const uint32_t* __restrict__ XShBase,
                const uint32_t* __restrict__ XSlBase,
                const uint32_t* __restrict__ W1h, const uint32_t* __restrict__ W1l,
                const uint32_t* __restrict__ W2h, const uint32_t* __restrict__ W2l,
                const float* __restrict__ b1,
                __half* __restrict__ H2base,
                const float* __restrict__ nsrcAll,
                const float* __restrict__ ndstAll)
{
    extern __shared__ uint32_t sm[];
    uint32_t* Ahp = sm + OFF_AH;    // [128][LDAp]
    uint32_t* Alp = sm + OFF_AL;
    uint32_t* B1h = sm + OFF_B1H;   // [8][LDB1]
    uint32_t* B1l = sm + OFF_B1L;
    uint32_t* Th  = sm + OFF_TH;    // [128][LDT]
    uint32_t* Tl  = sm + OFF_TL;
    uint32_t* B2h = sm + OFF_B2H;   // [8][LDB2]
    uint32_t* B2l = sm + OFF_B2L;
    float*    bsh = (float*)(sm + OFF_BSH);

    const int gidx = blockIdx.y;
    const uint32_t* XSh = XShBase + (size_t)gidx * NNODES * 64;
    const uint32_t* XSl = XSlBase + (size_t)gidx * NNODES * 64;
    __half*      H2   = H2base + (size_t)gidx * NNODES * FOUT;
    const float* nsrc = nsrcAll + gidx * NNODES;
    const float* ndst = ndstAll + gidx * NNODES;

    const int tid  = threadIdx.x;
    const int warp = tid >> 5;
    const int lane = tid & 31;
    const int warp_m = warp & 3;
    const int warp_n = warp >> 2;
    const int m0w = warp_m * 32;
    const int g  = lane >> 2;
    const int tg = lane & 3;
    const int blockRow = blockIdx.x * 128;
    const int M = NNODES;

    if (tid < FHID) bsh[tid] = b1[tid];

    // ================= stage 1: T = XS @ W1 (3-term bf16) =================
    float acc1[2][8][4];
#pragma unroll
    for (int mi = 0; mi < 2; mi++)
#pragma unroll
        for (int ni = 0; ni < 8; ni++)
#pragma unroll
            for (int j = 0; j < 4; j++) acc1[mi][ni][j] = 0.f;

    const int n0w1 = warp_n * 64;
    const int arow = tid >> 1;          // 0..127
    const int aq   = (tid & 1) * 4;     // uint4 column within 8-wide chunk

    for (int kc = 0; kc < FIN; kc += 16) {
        __syncthreads();
        {
            int grow = blockRow + arow;
            uint4 vh = make_uint4(0u, 0u, 0u, 0u);
            uint4 vl = make_uint4(0u, 0u, 0u, 0u);
            if (grow < M) {
                vh = *(const uint4*)(XSh + (size_t)grow * 64 + kc / 2 + aq);
                vl = *(const uint4*)(XSl + (size_t)grow * 64 + kc / 2 + aq);
            }
            *(uint4*)&Ahp[arow * LDAp + aq] = vh;
            *(uint4*)&Alp[arow * LDAp + aq] = vl;
        }
        {
            int jp = tid >> 5;
            int c4 = (tid & 31) * 4;
            *(uint4*)&B1h[jp * LDB1 + c4] =
                *(const uint4*)(W1h + (size_t)(kc / 2 + jp) * FHID + c4);
            *(uint4*)&B1l[jp * LDB1 + c4] =
                *(const uint4*)(W1l + (size_t)(kc / 2 + jp) * FHID + c4);
        }
        __syncthreads();

        uint32_t ah[2][4], al[2][4];
#pragma unroll
        for (int mi = 0; mi < 2; mi++) {
            int r = m0w + mi * 16 + g;
            ah[mi][0] = Ahp[r * LDAp + tg];            al[mi][0] = Alp[r * LDAp + tg];
            ah[mi][1] = Ahp[(r + 8) * LDAp + tg];      al[mi][1] = Alp[(r + 8) * LDAp + tg];
            ah[mi][2] = Ahp[r * LDAp + tg + 4];        al[mi][2] = Alp[r * LDAp + tg + 4];
            ah[mi][3] = Ahp[(r + 8) * LDAp + tg + 4];  al[mi][3] = Alp[(r + 8) * LDAp + tg + 4];
        }
#pragma unroll
        for (int ni = 0; ni < 8; ni++) {
            int c = n0w1 + ni * 8 + g;
            uint32_t bh[2], bl[2];
            bh[0] = B1h[tg * LDB1 + c];        bl[0] = B1l[tg * LDB1 + c];
            bh[1] = B1h[(tg + 4) * LDB1 + c];  bl[1] = B1l[(tg + 4) * LDB1 + c];
#pragma unroll
            for (int mi = 0; mi < 2; mi++) {
                mma_bf16(acc1[mi][ni], al[mi], bh);
                mma_bf16(acc1[mi][ni], ah[mi], bl);
                mma_bf16(acc1[mi][ni], ah[mi], bh);
            }
        }
    }

    // ---- t = relu(T*ndst + b1), packed bf16 hi/lo into smem ----
    __syncthreads();
#pragma unroll
    for (int mi = 0; mi < 2; mi++) {
        int r0 = m0w + mi * 16 + g;
        int r1 = r0 + 8;
        int gr0 = blockRow + r0, gr1 = blockRow + r1;
        float nd0 = (gr0 < M) ? ndst[gr0] : 0.f;
        float nd1 = (gr1 < M) ? ndst[gr1] : 0.f;
#pragma unroll
        for (int ni = 0; ni < 8; ni++) {
            int col = n0w1 + ni * 8 + 2 * tg;
            int cp  = col >> 1;
            float t00 = fmaxf(fmaf(acc1[mi][ni][0], nd0, bsh[col]), 0.f);
            float t01 = fmaxf(fmaf(acc1[mi][ni][1], nd0, bsh[col + 1]), 0.f);
            float t10 = fmaxf(fmaf(acc1[mi][ni][2], nd1, bsh[col]), 0.f);
            float t11 = fmaxf(fmaf(acc1[mi][ni][3], nd1, bsh[col + 1]), 0.f);
            uint32_t h, l;
            split2(t00, t01, h, l);
            Th[r0 * LDT + cp] = h;  Tl[r0 * LDT + cp] = l;
            split2(t10, t11, h, l);
            Th[r1 * LDT + cp] = h;  Tl[r1 * LDT + cp] = l;
        }
    }

    // ================= stage 2: H2 = t @ W2 * nsrc =================
    float acc2[2][4][4];
#pragma unroll
    for (int mi = 0; mi < 2; mi++)
#pragma unroll
        for (int ni = 0; ni < 4; ni++)
#pragma unroll
            for (int j = 0; j < 4; j++) acc2[mi][ni][j] = 0.f;

    const int n0w2 = warp_n * 32;

    for (int ch = 0; ch < 8; ch++) {
        __syncthreads();
        if (tid < 128) {
            int jp = tid >> 4;
            int c4 = (tid & 15) * 4;
            *(uint4*)&B2h[jp * LDB2 + c4] =
                *(const uint4*)(W2h + (size_t)(ch * 8 + jp) * FOUT + c4);
        } else {
            int t2 = tid - 128;
            int jp = t2 >> 4;
            int c4 = (t2 & 15) * 4;
            *(uint4*)&B2l[jp * LDB2 + c4] =
                *(const uint4*)(W2l + (size_t)(ch * 8 + jp) * FOUT + c4);
        }
        __syncthreads();

        int cb = ch * 8;
        uint32_t ah[2][4], al[2][4];
#pragma unroll
        for (int mi = 0; mi < 2; mi++) {
            int r = m0w + mi * 16 + g;
            ah[mi][0] = Th[r * LDT + cb + tg];            al[mi][0] = Tl[r * LDT + cb + tg];
            ah[mi][1] = Th[(r + 8) * LDT + cb + tg];      al[mi][1] = Tl[(r + 8) * LDT + cb + tg];
            ah[mi][2] = Th[r * LDT + cb + tg + 4];        al[mi][2] = Tl[r * LDT + cb + tg + 4];
            ah[mi][3] = Th[(r + 8) * LDT + cb + tg + 4];  al[mi][3] = Tl[(r + 8) * LDT + cb + tg + 4];
        }
#pragma unroll
        for (int ni = 0; ni < 4; ni++) {
            int c = n0w2 + ni * 8 + g;
            uint32_t bh[2], bl[2];
            bh[0] = B2h[tg * LDB2 + c];        bl[0] = B2l[tg * LDB2 + c];
            bh[1] = B2h[(tg + 4) * LDB2 + c];  bl[1] = B2l[(tg + 4) * LDB2 + c];
#pragma unroll
            for (int mi = 0; mi < 2; mi++) {
                mma_bf16(acc2[mi][ni], al[mi], bh);
                mma_bf16(acc2[mi][ni], ah[mi], bl);
                mma_bf16(acc2[mi][ni], ah[mi], bh);
            }
        }
    }

    // ---- epilogue: H2 = fp16(acc2 * nsrc) ----
#pragma unroll
    for (int mi = 0; mi < 2; mi++) {
        int gr0 = blockRow + m0w + mi * 16 + g;
        int gr1 = gr0 + 8;
        float s0 = (gr0 < M) ? nsrc[gr0] : 0.f;
        float s1 = (gr1 < M) ? nsrc[gr1] : 0.f;
#pragma unroll
        for (int ni = 0; ni < 4; ni++) {
            int col = n0w2 + ni * 8 + 2 * tg;
            if (gr0 < M)
                *(half2*)(H2 + (size_t)gr0 * FOUT + col) =
                    __floats2half2_rn(acc2[mi][ni][0] * s0, acc2[mi][ni][1] * s0);
            if (gr1 < M)
                *(half2*)(H2 + (size_t)gr1 * FOUT + col) =
                    __floats2half2_rn(acc2[mi][ni][2] * s1, acc2[mi][ni][3] * s1);
        }
    }
}

// ---------------- launch 10: final gather SpMM (fp16 H2 rows, fp32 accumulate) ----------------
__global__ __launch_bounds__(256)
void spmm_out(const __half* __restrict__ H2base,
              const int* __restrict__ rowstartAll,
              const int* __restrict__ esrcAll,
              float* __restrict__ outBase,
              const float* __restrict__ ndstAll,
              const float* __restrict__ bias)
{
    constexpr int C = FOUT;          // 64 halves per row (128 bytes)
    const int gidx = blockIdx.y;
    const __half* H = H2base + (size_t)gidx * NNODES * C;
    const int* rowstart = rowstartAll + gidx * (NNODES + 1);
    const int* esrc = esrcAll + (size_t)gidx * NEDGES;
    float* out = outBase + (size_t)gidx * NNODES * C;

    int gt = blockIdx.x * blockDim.x + threadIdx.x;
    int w = gt >> 5;
    int lane = gt & 31;
    int sub = lane >> 4;             // 2 rows per warp
    int lc  = lane & 15;             // uint2 lane: 4 halves
    int row = w * 2 + sub;
    if (row >= NNODES) return;

    int beg = rowstart[row];
    int end = rowstart[row + 1];
    float4 acc = make_float4(0.f, 0.f, 0.f, 0.f);
    int e = beg;
    for (; e + 4 <= end; e += 4) {
        int s0 = __ldg(esrc + e + 0);
        int s1 = __ldg(esrc + e + 1);
        int s2 = __ldg(esrc + e + 2);
        int s3 = __ldg(esrc + e + 3);
        uint2 u0 = __ldg((const uint2*)(H + (size_t)s0 * C) + lc);
        uint2 u1 = __ldg((const uint2*)(H + (size_t)s1 * C) + lc);
        uint2 u2 = __ldg((const uint2*)(H + (size_t)s2 * C) + lc);
        uint2 u3 = __ldg((const uint2*)(H + (size_t)s3 * C) + lc);
        float2 f;
        f = __half22float2(*(half2*)&u0.x); acc.x += f.x; acc.y += f.y;
        f = __half22float2(*(half2*)&u0.y); acc.z += f.x; acc.w += f.y;
        f = __half22float2(*(half2*)&u1.x); acc.x += f.x; acc.y += f.y;
        f = __half22float2(*(half2*)&u1.y); acc.z += f.x; acc.w += f.y;
        f = __half22float2(*(half2*)&u2.x); acc.x += f.x; acc.y += f.y;
        f = __half22float2(*(half2*)&u2.y); acc.z += f.x; acc.w += f.y;
        f = __half22float2(*(half2*)&u3.x); acc.x += f.x; acc.y += f.y;
        f = __half22float2(*(half2*)&u3.y); acc.z += f.x; acc.w += f.y;
    }
    for (; e < end; e++) {
        int s = __ldg(esrc + e);
        uint2 u = __ldg((const uint2*)(H + (size_t)s * C) + lc);
        float2 fa = __half22float2(*(half2*)&u.x);
        float2 fb = __half22float2(*(half2*)&u.y);
        acc.x += fa.x; acc.y += fa.y; acc.z += fb.x; acc.w += fb.y;
    }
    float nd = ndstAll[gidx * NNODES + row];
    float4 b = ((const float4*)bias)[lc];
    acc.x = fmaf(acc.x, nd, b.x);
    acc.y = fmaf(acc.y, nd, b.y);
    acc.z = fmaf(acc.z, nd, b.z);
    acc.w = fmaf(acc.w, nd, b.w);
    *((float4*)(out + (size_t)row * C) + lc) = acc;
}

// ---------------- launch ----------------
extern "C" void kernel_launch(void* const* d_in, const int* in_sizes, int n_in,
                              void* d_out, int out_size)
{
    float *nsrc, *ndst;
    int *cnt, *outcnt, *rowstart, *esrc, *partial;
    uint32_t *xsh, *xsl, *w1h, *w1l, *w2h, *w2l;
    __half *xh, *h2;
    cudaGetSymbolAddress((void**)&xh,       g_Xh);
    cudaGetSymbolAddress((void**)&xsh,      g_XSh);
    cudaGetSymbolAddress((void**)&xsl,      g_XSl);
    cudaGetSymbolAddress((void**)&h2,       g_H2);
    cudaGetSymbolAddress((void**)&cnt,      g_cnt);
    cudaGetSymbolAddress((void**)&outcnt,   g_outcnt);
    cudaGetSymbolAddress((void**)&rowstart, g_rowstart);
    cudaGetSymbolAddress((void**)&partial,  g_partial);
    cudaGetSymbolAddress((void**)&esrc,     g_esrc);
    cudaGetSymbolAddress((void**)&nsrc,     g_nsrc);
    cudaGetSymbolAddress((void**)&ndst,     g_ndst);
    cudaGetSymbolAddress((void**)&w1h,      g_W1h);
    cudaGetSymbolAddress((void**)&w1l,      g_W1l);
    cudaGetSymbolAddress((void**)&w2h,      g_W2h);
    cudaGetSymbolAddress((void**)&w2l,      g_W2l);

    F3 feats = {{ (const float*)d_in[0], (const float*)d_in[3], (const float*)d_in[6] }};
    I3 srcs  = {{ (const int*)d_in[1],   (const int*)d_in[4],   (const int*)d_in[7] }};
    I3 dsts  = {{ (const int*)d_in[2],   (const int*)d_in[5],   (const int*)d_in[8] }};
    const float* W1 = (const float*)d_in[9];
    const float* b1 = (const float*)d_in[10];
    const float* W2 = (const float*)d_in[11];
    const float* b2 = (const float*)d_in[12];

    static const size_t SMEM_BYTES = SMEM_WORDS * sizeof(uint32_t);
    cudaFuncSetAttribute(fused_gemm, cudaFuncAttributeMaxDynamicSharedMemorySize,
                         (int)SMEM_BYTES);

    dim3 gE8((NEDGES / 8 + 255) / 256, 3);       // 8 edges per thread (hist, fill)
    dim3 gSc(SCAN_NB, 3);
    dim3 gCv((NNODES * 16 + 255) / 256, 3);      // convert: 16 threads/node
    dim3 gG((NNODES + 127) / 128, 3);
    const int gS1 = (NNODES * 16 + 255) / 256;   // 2 rows/warp
    dim3 gS2((NNODES * 16 + 255) / 256, 3);

    zero_pack<<<(3 * NNODES + 255) / 256, 256>>>(cnt, outcnt, W1, W2, w1h, w1l, w2h, w2l);
    hist_all <<<gE8, 256>>>(dsts, cnt);
    scanA    <<<gSc, 1024>>>(cnt, rowstart, partial, ndst);
    scanC    <<<gSc, 1024>>>(cnt, rowstart, partial);
    fill_all <<<gE8, 256>>>(srcs, dsts, cnt, outcnt, esrc);
    convert_feat<<<gCv, 256>>>(feats, outcnt, nsrc, xh);

    // XS = gather(Xh), one graph per launch (fp16 features: 77MB total, L2-resident)
    for (int g = 0; g < 3; g++)
        spmm_scaled<<<gS1, 256>>>(xh + (size_t)g * NNODES * FIN,
                                  rowstart + g * (NNODES + 1),
                                  esrc + (size_t)g * NEDGES,
                                  xsh + (size_t)g * NNODES * 64,
                                  xsl + (size_t)g * NNODES * 64);

    // H2 = fp16( relu((XS@W1)*ndst + b1) @ W2 * nsrc )
    fused_gemm<<<gG, 256, SMEM_BYTES>>>(xsh, xsl, w1h, w1l, w2h, w2l, b1, h2, nsrc, ndst);
    // out = gather(H2)*ndst + b2
    spmm_out<<<gS2, 256>>>(h2, rowstart, esrc, (float*)d_out, ndst, b2);
}